// round 1
// baseline (speedup 1.0000x reference)
#include <cuda_runtime.h>
#include <cuda_bf16.h>
#include <math.h>

// ---------------- Problem constants ----------------
#define B_  4
#define T_  1024
#define BT  (B_*T_)        // 4096
#define E_  768
#define H_  12
#define HD  64
#define L_  6
#define FF  3072
#define V_  50257
#define EPS 1e-5f

// ---------------- Device scratch (no allocs allowed) ----------------
__device__ float g_x  [BT * E_];
__device__ float g_xn [BT * E_];
__device__ float g_q  [BT * E_];
__device__ float g_k  [BT * E_];
__device__ float g_v  [BT * E_];
__device__ float g_att[BT * E_];
__device__ float g_ff [BT * FF];

// ---------------- Embedding: x = tok_emb[idx] + pos_emb[t] ----------------
__global__ void embed_kernel(const int* __restrict__ idx,
                             const float* __restrict__ tok,
                             const float* __restrict__ pos,
                             float* __restrict__ x) {
    int row = blockIdx.x;              // b*T + t
    int t   = row & (T_ - 1);
    int token = idx[row];
    const float* tp = tok + (size_t)token * E_;
    const float* pp = pos + (size_t)t * E_;
    float* xp = x + (size_t)row * E_;
    for (int e = threadIdx.x; e < E_; e += blockDim.x)
        xp[e] = tp[e] + pp[e];
}

// ---------------- LayerNorm (one block per row, 256 threads, E=768) ----------------
__global__ void ln_kernel(const float* __restrict__ x,
                          const float* __restrict__ g,
                          const float* __restrict__ b,
                          float* __restrict__ y) {
    int row = blockIdx.x;
    int tid = threadIdx.x;             // 256 threads, 3 elems each
    const float* xr = x + (size_t)row * E_;
    float v0 = xr[tid], v1 = xr[tid + 256], v2 = xr[tid + 512];
    float s  = v0 + v1 + v2;
    float ss = v0*v0 + v1*v1 + v2*v2;
    #pragma unroll
    for (int off = 16; off > 0; off >>= 1) {
        s  += __shfl_down_sync(0xffffffffu, s,  off);
        ss += __shfl_down_sync(0xffffffffu, ss, off);
    }
    __shared__ float sh_s[8], sh_ss[8];
    int wid = tid >> 5, lane = tid & 31;
    if (lane == 0) { sh_s[wid] = s; sh_ss[wid] = ss; }
    __syncthreads();
    float tot = 0.f, tots = 0.f;
    #pragma unroll
    for (int i = 0; i < 8; i++) { tot += sh_s[i]; tots += sh_ss[i]; }
    float mean = tot * (1.0f / E_);
    float var  = tots * (1.0f / E_) - mean * mean;
    float rstd = rsqrtf(var + EPS);
    float* yr = y + (size_t)row * E_;
    yr[tid      ] = (v0 - mean) * rstd * g[tid      ] + b[tid      ];
    yr[tid + 256] = (v1 - mean) * rstd * g[tid + 256] + b[tid + 256];
    yr[tid + 512] = (v2 - mean) * rstd * g[tid + 512] + b[tid + 512];
}

// ---------------- SGEMM: C[M,N] = A[M,K] @ Bw + epilogue ----------------
// BMODE 0: Bw row-major (K,N).  BMODE 1: head-blocked Bw[h][e][d] (h=c>>6, d=c&63), K=E.
// EPI 0: +bias. EPI 1: relu(+bias). EPI 2: res + (+bias).  bias may be nullptr.
template<int BMODE, int EPI>
__global__ void sgemm_kernel(const float* __restrict__ A,
                             const float* __restrict__ Bw,
                             const float* __restrict__ bias,
                             const float* __restrict__ res,
                             float* __restrict__ C,
                             int M, int N, int K) {
    __shared__ float As[8][128];
    __shared__ float Bs[8][128];

    const int tid = threadIdx.x;          // 256
    const int tx  = tid & 15;
    const int ty  = tid >> 4;
    const int m0  = blockIdx.y * 128;
    const int n0  = blockIdx.x * 128;

    float acc[8][8];
    #pragma unroll
    for (int i = 0; i < 8; i++)
        #pragma unroll
        for (int j = 0; j < 8; j++) acc[i][j] = 0.f;

    for (int k0 = 0; k0 < K; k0 += 8) {
        // load A tile (128 x 8), transposed into As[k][m]
        #pragma unroll
        for (int i = 0; i < 4; i++) {
            int idx = tid + i * 256;
            int r = idx >> 3, c = idx & 7;
            As[c][r] = A[(size_t)(m0 + r) * K + k0 + c];
        }
        // load B tile (8 x 128)
        #pragma unroll
        for (int i = 0; i < 4; i++) {
            int idx = tid + i * 256;
            int r = idx >> 7, c = idx & 127;
            int n = n0 + c;
            float val = 0.f;
            if (n < N) {
                if (BMODE == 0) val = Bw[(size_t)(k0 + r) * N + n];
                else            val = Bw[(size_t)(n >> 6) * (K * 64) + (size_t)(k0 + r) * 64 + (n & 63)];
            }
            Bs[r][c] = val;
        }
        __syncthreads();

        #pragma unroll
        for (int kk = 0; kk < 8; kk++) {
            float a[8], b[8];
            *(float4*)&a[0] = *(const float4*)&As[kk][ty * 4];
            *(float4*)&a[4] = *(const float4*)&As[kk][ty * 4 + 64];
            *(float4*)&b[0] = *(const float4*)&Bs[kk][tx * 4];
            *(float4*)&b[4] = *(const float4*)&Bs[kk][tx * 4 + 64];
            #pragma unroll
            for (int i = 0; i < 8; i++)
                #pragma unroll
                for (int j = 0; j < 8; j++)
                    acc[i][j] += a[i] * b[j];
        }
        __syncthreads();
    }

    #pragma unroll
    for (int i = 0; i < 8; i++) {
        int r = m0 + ty * 4 + (i & 3) + ((i >= 4) ? 64 : 0);
        #pragma unroll
        for (int j = 0; j < 8; j++) {
            int n = n0 + tx * 4 + (j & 3) + ((j >= 4) ? 64 : 0);
            if (n < N) {
                float v = acc[i][j];
                if (bias) v += bias[n];
                if (EPI == 1) v = fmaxf(v, 0.f);
                if (EPI == 2) v += res[(size_t)r * N + n];
                C[(size_t)r * N + n] = v;
            }
        }
    }
}

// ---------------- Attention (causal, online softmax) ----------------
// q,k,v,o in (b,t,h,d) layout. One thread per query, 128 queries/block, 64-key tiles.
__global__ void attn_kernel(const float* __restrict__ q,
                            const float* __restrict__ k,
                            const float* __restrict__ v,
                            float* __restrict__ o) {
    __shared__ float Ks[64][68];
    __shared__ float Vs[64][68];

    const int bh = blockIdx.y;                 // 0..B*H-1
    const int b  = bh / H_, h = bh % H_;
    const int tq = blockIdx.x * 128 + threadIdx.x;
    const float scale = rsqrtf((float)E_);     // model scales by EMBED_DIM

    float qr[64], oacc[64];
    const float* qp = q + ((size_t)(b * T_ + tq) * H_ + h) * HD;
    #pragma unroll
    for (int d = 0; d < 64; d += 4) {
        float4 t4 = *(const float4*)(qp + d);
        qr[d] = t4.x * scale; qr[d+1] = t4.y * scale; qr[d+2] = t4.z * scale; qr[d+3] = t4.w * scale;
    }
    #pragma unroll
    for (int d = 0; d < 64; d++) oacc[d] = 0.f;

    float m = -1e30f, lsum = 0.f;
    const int kt_end = blockIdx.x * 128 + 127;   // last query in this block

    for (int st0 = 0; st0 <= kt_end; st0 += 64) {
        // cooperative load of K/V tile: 128 threads, each loads half of one key row
        int s    = threadIdx.x >> 1;
        int half = (threadIdx.x & 1) * 32;
        const float* kp = k + ((size_t)(b * T_ + st0 + s) * H_ + h) * HD + half;
        const float* vp = v + ((size_t)(b * T_ + st0 + s) * H_ + h) * HD + half;
        #pragma unroll
        for (int d = 0; d < 32; d += 4) {
            *(float4*)&Ks[s][half + d] = *(const float4*)(kp + d);
            *(float4*)&Vs[s][half + d] = *(const float4*)(vp + d);
        }
        __syncthreads();

        #pragma unroll 4
        for (int s2 = 0; s2 < 64; s2++) {
            float sc = 0.f;
            #pragma unroll
            for (int d = 0; d < 64; d += 4) {
                float4 kv = *(const float4*)&Ks[s2][d];
                sc += qr[d] * kv.x + qr[d+1] * kv.y + qr[d+2] * kv.z + qr[d+3] * kv.w;
            }
            if (st0 + s2 <= tq) {
                float newm = fmaxf(m, sc);
                float corr = __expf(m - newm);
                float p    = __expf(sc - newm);
                lsum = lsum * corr + p;
                #pragma unroll
                for (int d = 0; d < 64; d += 4) {
                    float4 vv = *(const float4*)&Vs[s2][d];
                    oacc[d]   = oacc[d]   * corr + p * vv.x;
                    oacc[d+1] = oacc[d+1] * corr + p * vv.y;
                    oacc[d+2] = oacc[d+2] * corr + p * vv.z;
                    oacc[d+3] = oacc[d+3] * corr + p * vv.w;
                }
                m = newm;
            }
        }
        __syncthreads();
    }

    float inv = 1.0f / lsum;
    float* op = o + ((size_t)(b * T_ + tq) * H_ + h) * HD;
    #pragma unroll
    for (int d = 0; d < 64; d += 4) {
        float4 r4;
        r4.x = oacc[d] * inv; r4.y = oacc[d+1] * inv;
        r4.z = oacc[d+2] * inv; r4.w = oacc[d+3] * inv;
        *(float4*)(op + d) = r4;
    }
}

// ---------------- Host launch ----------------
extern "C" void kernel_launch(void* const* d_in, const int* in_sizes, int n_in,
                              void* d_out, int out_size) {
    const int*   idx     = (const int*)  d_in[0];
    const float* tok_emb = (const float*)d_in[1];
    const float* pos_emb = (const float*)d_in[2];
    const float* Wq      = (const float*)d_in[3];
    const float* Wk      = (const float*)d_in[4];
    const float* Wv      = (const float*)d_in[5];
    const float* Wo      = (const float*)d_in[6];
    const float* bo      = (const float*)d_in[7];
    const float* ln1_g   = (const float*)d_in[8];
    const float* ln1_b   = (const float*)d_in[9];
    const float* ln2_g   = (const float*)d_in[10];
    const float* ln2_b   = (const float*)d_in[11];
    const float* W1      = (const float*)d_in[12];
    const float* b1      = (const float*)d_in[13];
    const float* W2      = (const float*)d_in[14];
    const float* b2      = (const float*)d_in[15];
    const float* lnf_g   = (const float*)d_in[16];
    const float* lnf_b   = (const float*)d_in[17];
    const float* Wh      = (const float*)d_in[18];
    const float* bh      = (const float*)d_in[19];
    float* out = (float*)d_out;

    float *x, *xn, *q, *k, *v, *att, *ff;
    cudaGetSymbolAddress((void**)&x,   g_x);
    cudaGetSymbolAddress((void**)&xn,  g_xn);
    cudaGetSymbolAddress((void**)&q,   g_q);
    cudaGetSymbolAddress((void**)&k,   g_k);
    cudaGetSymbolAddress((void**)&v,   g_v);
    cudaGetSymbolAddress((void**)&att, g_att);
    cudaGetSymbolAddress((void**)&ff,  g_ff);

    embed_kernel<<<BT, 256>>>(idx, tok_emb, pos_emb, x);

    dim3 gE((E_ + 127) / 128, BT / 128);     // (6, 32)
    dim3 gFF((FF + 127) / 128, BT / 128);    // (24, 32)
    dim3 gV((V_ + 127) / 128, BT / 128);     // (393, 32)
    dim3 gAttn(T_ / 128, B_ * H_);           // (8, 48)

    for (int l = 0; l < L_; l++) {
        ln_kernel<<<BT, 256>>>(x, ln1_g + (size_t)l * E_, ln1_b + (size_t)l * E_, xn);

        const float* wq = Wq + (size_t)l * H_ * E_ * HD;
        const float* wk = Wk + (size_t)l * H_ * E_ * HD;
        const float* wv = Wv + (size_t)l * H_ * E_ * HD;
        sgemm_kernel<1,0><<<gE, 256>>>(xn, wq, nullptr, nullptr, q, BT, E_, E_);
        sgemm_kernel<1,0><<<gE, 256>>>(xn, wk, nullptr, nullptr, k, BT, E_, E_);
        sgemm_kernel<1,0><<<gE, 256>>>(xn, wv, nullptr, nullptr, v, BT, E_, E_);

        attn_kernel<<<gAttn, 128>>>(q, k, v, att);

        // x = x + att @ Wo + bo
        sgemm_kernel<0,2><<<gE, 256>>>(att, Wo + (size_t)l * E_ * E_,
                                       bo + (size_t)l * E_, x, x, BT, E_, E_);

        ln_kernel<<<BT, 256>>>(x, ln2_g + (size_t)l * E_, ln2_b + (size_t)l * E_, xn);

        // ff = relu(xn @ W1 + b1)
        sgemm_kernel<0,1><<<gFF, 256>>>(xn, W1 + (size_t)l * E_ * FF,
                                        b1 + (size_t)l * FF, nullptr, ff, BT, FF, E_);
        // x = x + ff @ W2 + b2
        sgemm_kernel<0,2><<<gE, 256>>>(ff, W2 + (size_t)l * FF * E_,
                                       b2 + (size_t)l * E_, x, x, BT, E_, FF);
    }

    ln_kernel<<<BT, 256>>>(x, lnf_g, lnf_b, xn);

    // logits = xn @ Wh + bh
    sgemm_kernel<0,0><<<gV, 256>>>(xn, Wh, bh, nullptr, out, BT, V_, E_);

    (void)in_sizes; (void)n_in; (void)out_size;
}

// round 4
// speedup vs baseline: 1.5509x; 1.5509x over previous
#include <cuda_runtime.h>
#include <cuda_bf16.h>
#include <math.h>
#include <stdint.h>

// ---------------- Problem constants ----------------
#define B_  4
#define T_  1024
#define BT  (B_*T_)        // 4096
#define E_  768
#define H_  12
#define HD  64
#define L_  6
#define FF  3072
#define V_  50257
#define EPS 1e-5f

#define GEMM_SMEM 68096
#define STAGE_LD  132

// ---------------- Device scratch (no allocs allowed) ----------------
__device__ float g_x  [BT * E_];
__device__ float g_xn [BT * E_];
__device__ float g_q  [BT * E_];
__device__ float g_k  [BT * E_];
__device__ float g_v  [BT * E_];
__device__ float g_att[BT * E_];
__device__ float g_ff [BT * FF];

struct GemmPtrs {
    const float* w[3];
    float*       c[3];
};

// ---------------- helpers ----------------
__device__ __forceinline__ uint32_t smem_u32(const void* p) {
    uint32_t a;
    asm("{ .reg .u64 t; cvta.to.shared.u64 t, %1; cvt.u32.u64 %0, t; }" : "=r"(a) : "l"(p));
    return a;
}
__device__ __forceinline__ uint32_t pack_bf(float a, float b) {
    __nv_bfloat162 h = __floats2bfloat162_rn(a, b);
    return *(uint32_t*)&h;
}
// smem byte offset for element (r, k) in a [R][32] bf16 tile, 64B rows,
// 16B chunks XOR-swizzled by (r & 3)
__device__ __forceinline__ uint32_t aoff(uint32_t r, uint32_t k) {
    return r * 64u + (((((k) >> 3) & 3u) ^ (r & 3u)) << 4) + (k & 7u) * 2u;
}
__device__ __forceinline__ void ldmx4(uint32_t r[4], uint32_t addr) {
    asm volatile("ldmatrix.sync.aligned.m8n8.x4.shared.b16 {%0,%1,%2,%3}, [%4];"
                 : "=r"(r[0]), "=r"(r[1]), "=r"(r[2]), "=r"(r[3]) : "r"(addr));
}
__device__ __forceinline__ void mma16816(float c[4], const uint32_t a[4], const uint32_t b[2]) {
    asm volatile(
        "mma.sync.aligned.m16n8k16.row.col.f32.bf16.bf16.f32 "
        "{%0,%1,%2,%3}, {%4,%5,%6,%7}, {%8,%9}, {%0,%1,%2,%3};"
        : "+f"(c[0]), "+f"(c[1]), "+f"(c[2]), "+f"(c[3])
        : "r"(a[0]), "r"(a[1]), "r"(a[2]), "r"(a[3]), "r"(b[0]), "r"(b[1]));
}

// ---------------- mma.sync GEMM: C[M,N] = A[M,K] @ W + epilogue ----------------
// BMODE 0: W row-major (K,N). BMODE 1: head-blocked W[h][e][d], n=(h*64+d), K=E.
// EPI 0: +bias (bias may be null). EPI 1: relu(+bias). EPI 2: res + (+bias).
// QKV 1: blockIdx.z selects P.w[z] / P.c[z].
// fp32 via bf16 hi/lo split: C = Ah*Bh + Ah*Bl + Al*Bh  (fp32 accum).
template<int BMODE, int EPI, int QKV>
__global__ void __launch_bounds__(256, 1)
gemm_mma(const float* __restrict__ A, GemmPtrs P,
         const float* __restrict__ bias, const float* __restrict__ res,
         int N, int K) {
    extern __shared__ char smraw[];
    uint32_t raw = smem_u32(smraw);
    uint32_t sb  = (raw + 255u) & ~255u;
    char* smp    = smraw + (sb - raw);

    const float* Bw = QKV ? P.w[blockIdx.z] : P.w[0];
    float*       C  = QKV ? P.c[blockIdx.z] : P.c[0];

    const int tid  = threadIdx.x;
    const int lane = tid & 31;
    const int wid  = tid >> 5;
    const int wm   = wid >> 2;          // 0..1
    const int wn   = wid & 3;           // 0..3
    const int m0   = blockIdx.x * 128;
    const int n0   = blockIdx.y * 128;
    const bool n_vec = ((N & 3) == 0);  // float4-safe B/N addressing

    // gmem load mappings
    const int ar  = tid >> 1;               // A row 0..127
    const int akh = (tid & 1) * 16;         // A k-half
    const int nb  = (tid & 31) * 4;         // B n group (0..124)
    const int kq  = (tid >> 5) * 4;         // B k group (0..28)

    float acc[4][4][4];
    #pragma unroll
    for (int i = 0; i < 4; i++)
        #pragma unroll
        for (int j = 0; j < 4; j++)
            #pragma unroll
            for (int q = 0; q < 4; q++) acc[i][j][q] = 0.f;

    float ra[16];
    float rb[4][4];
    const int NC = K >> 5;

    // ---- gmem loads into regs for chunk c ----
    auto LDG = [&](int c) {
        const int k0c = c << 5;
        const float* ap = A + (size_t)(m0 + ar) * K + k0c + akh;
        #pragma unroll
        for (int i = 0; i < 4; i++)
            *(float4*)&ra[i * 4] = *(const float4*)(ap + i * 4);
        if (BMODE == 0) {
            const int ng = n0 + nb;
            if (n_vec) {
                #pragma unroll
                for (int i = 0; i < 4; i++) {
                    const float* bp = Bw + (size_t)(k0c + kq + i) * N + ng;
                    float4 v = *(const float4*)bp;   // N%4==0: tiles always full & aligned
                    rb[i][0] = v.x; rb[i][1] = v.y; rb[i][2] = v.z; rb[i][3] = v.w;
                }
            } else {
                #pragma unroll
                for (int i = 0; i < 4; i++) {
                    const float* bp = Bw + (size_t)(k0c + kq + i) * N + ng;
                    #pragma unroll
                    for (int j = 0; j < 4; j++)
                        rb[i][j] = (ng + j < N) ? bp[j] : 0.f;   // scalar: odd-N safe
                }
            }
        } else {
            const int ng = n0 + nb;
            const float* bp = Bw + ((size_t)(ng >> 6) * K + (k0c + kq)) * 64 + (ng & 63);
            #pragma unroll
            for (int i = 0; i < 4; i++) {
                float4 v = *(const float4*)(bp + (size_t)i * 64);
                rb[i][0] = v.x; rb[i][1] = v.y; rb[i][2] = v.z; rb[i][3] = v.w;
            }
        }
    };

    // ---- convert + STS regs into buffer b ----
    auto STS = [&](int b) {
        char* buf = smp + b * 32768;
        char* Ah = buf;          char* Al = buf + 8192;
        char* Bh = buf + 16384;  char* Bl = buf + 24576;
        #pragma unroll
        for (int h = 0; h < 2; h++) {
            uint4 hi, lo;
            float f[8];
            #pragma unroll
            for (int q = 0; q < 8; q++) f[q] = ra[h * 8 + q];
            float fh[8], fl[8];
            #pragma unroll
            for (int q = 0; q < 8; q++) {
                __nv_bfloat16 hb = __float2bfloat16_rn(f[q]);
                fh[q] = __bfloat162float(hb);
                fl[q] = f[q] - fh[q];
            }
            hi.x = pack_bf(fh[0], fh[1]); hi.y = pack_bf(fh[2], fh[3]);
            hi.z = pack_bf(fh[4], fh[5]); hi.w = pack_bf(fh[6], fh[7]);
            lo.x = pack_bf(fl[0], fl[1]); lo.y = pack_bf(fl[2], fl[3]);
            lo.z = pack_bf(fl[4], fl[5]); lo.w = pack_bf(fl[6], fl[7]);
            uint32_t off = aoff(ar, akh + h * 8);
            *(uint4*)(Ah + off) = hi;
            *(uint4*)(Al + off) = lo;
        }
        #pragma unroll
        for (int j = 0; j < 4; j++) {
            float w0 = rb[0][j], w1 = rb[1][j], w2 = rb[2][j], w3 = rb[3][j];
            float h0 = __bfloat162float(__float2bfloat16_rn(w0));
            float h1 = __bfloat162float(__float2bfloat16_rn(w1));
            float h2 = __bfloat162float(__float2bfloat16_rn(w2));
            float h3 = __bfloat162float(__float2bfloat16_rn(w3));
            uint2 hi, lo;
            hi.x = pack_bf(h0, h1); hi.y = pack_bf(h2, h3);
            lo.x = pack_bf(w0 - h0, w1 - h1); lo.y = pack_bf(w2 - h2, w3 - h3);
            uint32_t off = aoff(nb + j, kq);
            *(uint2*)(Bh + off) = hi;
            *(uint2*)(Bl + off) = lo;
        }
    };

    // ---- mma over buffer b ----
    auto MMA = [&](int b) {
        uint32_t base = sb + b * 32768;
        const uint32_t arow = wm * 64 + (lane & 15);
        const uint32_t koffA = (lane & 16) ? 8u : 0u;
        const uint32_t nrow = wn * 32 + (lane & 7) + ((lane & 16) ? 8 : 0);
        const uint32_t koffB = (lane & 8) ? 8u : 0u;
        #pragma unroll
        for (int ks = 0; ks < 2; ks++) {
            uint32_t ah[4][4], al[4][4], bh[4][2], bl[4][2];
            #pragma unroll
            for (int mt = 0; mt < 4; mt++) {
                uint32_t off = aoff(arow + mt * 16, ks * 16 + koffA);
                ldmx4(ah[mt], base + off);
                ldmx4(al[mt], base + 8192 + off);
            }
            #pragma unroll
            for (int g = 0; g < 2; g++) {
                uint32_t off = aoff(nrow + g * 16, ks * 16 + koffB);
                uint32_t t[4];
                ldmx4(t, base + 16384 + off);
                bh[2*g][0] = t[0]; bh[2*g][1] = t[1];
                bh[2*g+1][0] = t[2]; bh[2*g+1][1] = t[3];
                ldmx4(t, base + 24576 + off);
                bl[2*g][0] = t[0]; bl[2*g][1] = t[1];
                bl[2*g+1][0] = t[2]; bl[2*g+1][1] = t[3];
            }
            #pragma unroll
            for (int mt = 0; mt < 4; mt++)
                #pragma unroll
                for (int nt = 0; nt < 4; nt++) {
                    mma16816(acc[mt][nt], ah[mt], bh[nt]);
                    mma16816(acc[mt][nt], ah[mt], bl[nt]);
                    mma16816(acc[mt][nt], al[mt], bh[nt]);
                }
        }
    };

    LDG(0);
    STS(0);
    __syncthreads();
    for (int c = 0; c < NC; c++) {
        if (c + 1 < NC) LDG(c + 1);
        MMA(c & 1);
        if (c + 1 < NC) STS((c + 1) & 1);
        __syncthreads();
    }

    // ---- epilogue: regs -> smem stage -> coalesced gmem ----
    float* stage = (float*)smp;
    {
        const int r0 = wm * 64 + (lane >> 2);
        const int c0 = wn * 32 + (lane & 3) * 2;
        #pragma unroll
        for (int mt = 0; mt < 4; mt++)
            #pragma unroll
            for (int nt = 0; nt < 4; nt++) {
                int r = r0 + mt * 16, cc = c0 + nt * 8;
                float2 p0; p0.x = acc[mt][nt][0]; p0.y = acc[mt][nt][1];
                float2 p1; p1.x = acc[mt][nt][2]; p1.y = acc[mt][nt][3];
                *(float2*)&stage[r * STAGE_LD + cc]       = p0;
                *(float2*)&stage[(r + 8) * STAGE_LD + cc] = p1;
            }
    }
    __syncthreads();

    if (n_vec) {
        #pragma unroll 4
        for (int j = 0; j < 16; j++) {
            int lin = j * 256 + tid;
            int rr = lin >> 5;
            int cg = (lin & 31) * 4;
            int n  = n0 + cg;
            float4 v = *(float4*)&stage[rr * STAGE_LD + cg];
            size_t base = (size_t)(m0 + rr) * N + n;
            if (bias) {
                float4 bb = *(const float4*)(bias + n);
                v.x += bb.x; v.y += bb.y; v.z += bb.z; v.w += bb.w;
            }
            if (EPI == 1) {
                v.x = fmaxf(v.x, 0.f); v.y = fmaxf(v.y, 0.f);
                v.z = fmaxf(v.z, 0.f); v.w = fmaxf(v.w, 0.f);
            }
            if (EPI == 2) {
                float4 rr4 = *(const float4*)(res + base);
                v.x += rr4.x; v.y += rr4.y; v.z += rr4.z; v.w += rr4.w;
            }
            *(float4*)(C + base) = v;
        }
    } else {
        #pragma unroll 4
        for (int j = 0; j < 16; j++) {
            int lin = j * 256 + tid;
            int rr = lin >> 5;
            int cg = (lin & 31) * 4;
            #pragma unroll
            for (int q = 0; q < 4; q++) {
                int n = n0 + cg + q;
                if (n < N) {
                    float v = stage[rr * STAGE_LD + cg + q];
                    if (bias) v += bias[n];
                    if (EPI == 1) v = fmaxf(v, 0.f);
                    size_t base = (size_t)(m0 + rr) * N + n;
                    if (EPI == 2) v += res[base];
                    C[base] = v;
                }
            }
        }
    }
}

// ---------------- Embedding ----------------
__global__ void embed_kernel(const int* __restrict__ idx,
                             const float* __restrict__ tok,
                             const float* __restrict__ pos,
                             float* __restrict__ x) {
    int row = blockIdx.x;
    int t   = row & (T_ - 1);
    int token = idx[row];
    const float* tp = tok + (size_t)token * E_;
    const float* pp = pos + (size_t)t * E_;
    float* xp = x + (size_t)row * E_;
    for (int e = threadIdx.x; e < E_; e += blockDim.x)
        xp[e] = tp[e] + pp[e];
}

// ---------------- LayerNorm ----------------
__global__ void ln_kernel(const float* __restrict__ x,
                          const float* __restrict__ g,
                          const float* __restrict__ b,
                          float* __restrict__ y) {
    int row = blockIdx.x;
    int tid = threadIdx.x;
    const float* xr = x + (size_t)row * E_;
    float v0 = xr[tid], v1 = xr[tid + 256], v2 = xr[tid + 512];
    float s  = v0 + v1 + v2;
    float ss = v0*v0 + v1*v1 + v2*v2;
    #pragma unroll
    for (int off = 16; off > 0; off >>= 1) {
        s  += __shfl_down_sync(0xffffffffu, s,  off);
        ss += __shfl_down_sync(0xffffffffu, ss, off);
    }
    __shared__ float sh_s[8], sh_ss[8];
    int wid = tid >> 5, lane = tid & 31;
    if (lane == 0) { sh_s[wid] = s; sh_ss[wid] = ss; }
    __syncthreads();
    float tot = 0.f, tots = 0.f;
    #pragma unroll
    for (int i = 0; i < 8; i++) { tot += sh_s[i]; tots += sh_ss[i]; }
    float mean = tot * (1.0f / E_);
    float var  = tots * (1.0f / E_) - mean * mean;
    float rstd = rsqrtf(var + EPS);
    float* yr = y + (size_t)row * E_;
    yr[tid      ] = (v0 - mean) * rstd * g[tid      ] + b[tid      ];
    yr[tid + 256] = (v1 - mean) * rstd * g[tid + 256] + b[tid + 256];
    yr[tid + 512] = (v2 - mean) * rstd * g[tid + 512] + b[tid + 512];
}

// ---------------- Attention (causal, online softmax, fp32) ----------------
__global__ void attn_kernel(const float* __restrict__ q,
                            const float* __restrict__ k,
                            const float* __restrict__ v,
                            float* __restrict__ o) {
    __shared__ float Ks[64][68];
    __shared__ float Vs[64][68];

    const int bh = blockIdx.y;
    const int b  = bh / H_, h = bh % H_;
    const int tq = blockIdx.x * 128 + threadIdx.x;
    const float scale = rsqrtf((float)E_);

    float qr[64], oacc[64];
    const float* qp = q + ((size_t)(b * T_ + tq) * H_ + h) * HD;
    #pragma unroll
    for (int d = 0; d < 64; d += 4) {
        float4 t4 = *(const float4*)(qp + d);
        qr[d] = t4.x * scale; qr[d+1] = t4.y * scale; qr[d+2] = t4.z * scale; qr[d+3] = t4.w * scale;
    }
    #pragma unroll
    for (int d = 0; d < 64; d++) oacc[d] = 0.f;

    float m = -1e30f, lsum = 0.f;
    const int kt_end = blockIdx.x * 128 + 127;

    for (int st0 = 0; st0 <= kt_end; st0 += 64) {
        int s    = threadIdx.x >> 1;
        int half = (threadIdx.x & 1) * 32;
        const float* kp = k + ((size_t)(b * T_ + st0 + s) * H_ + h) * HD + half;
        const float* vp = v + ((size_t)(b * T_ + st0 + s) * H_ + h) * HD + half;
        #pragma unroll
        for (int d = 0; d < 32; d += 4) {
            *(float4*)&Ks[s][half + d] = *(const float4*)(kp + d);
            *(float4*)&Vs[s][half + d] = *(const float4*)(vp + d);
        }
        __syncthreads();

        #pragma unroll 4
        for (int s2 = 0; s2 < 64; s2++) {
            float sc = 0.f;
            #pragma unroll
            for (int d = 0; d < 64; d += 4) {
                float4 kv = *(const float4*)&Ks[s2][d];
                sc += qr[d] * kv.x + qr[d+1] * kv.y + qr[d+2] * kv.z + qr[d+3] * kv.w;
            }
            if (st0 + s2 <= tq) {
                float newm = fmaxf(m, sc);
                float corr = __expf(m - newm);
                float p    = __expf(sc - newm);
                lsum = lsum * corr + p;
                #pragma unroll
                for (int d = 0; d < 64; d += 4) {
                    float4 vv = *(const float4*)&Vs[s2][d];
                    oacc[d]   = oacc[d]   * corr + p * vv.x;
                    oacc[d+1] = oacc[d+1] * corr + p * vv.y;
                    oacc[d+2] = oacc[d+2] * corr + p * vv.z;
                    oacc[d+3] = oacc[d+3] * corr + p * vv.w;
                }
                m = newm;
            }
        }
        __syncthreads();
    }

    float inv = 1.0f / lsum;
    float* op = o + ((size_t)(b * T_ + tq) * H_ + h) * HD;
    #pragma unroll
    for (int d = 0; d < 64; d += 4) {
        float4 r4;
        r4.x = oacc[d] * inv; r4.y = oacc[d+1] * inv;
        r4.z = oacc[d+2] * inv; r4.w = oacc[d+3] * inv;
        *(float4*)(op + d) = r4;
    }
}

// ---------------- Host launch ----------------
extern "C" void kernel_launch(void* const* d_in, const int* in_sizes, int n_in,
                              void* d_out, int out_size) {
    const int*   idx     = (const int*)  d_in[0];
    const float* tok_emb = (const float*)d_in[1];
    const float* pos_emb = (const float*)d_in[2];
    const float* Wq      = (const float*)d_in[3];
    const float* Wk      = (const float*)d_in[4];
    const float* Wv      = (const float*)d_in[5];
    const float* Wo      = (const float*)d_in[6];
    const float* bo      = (const float*)d_in[7];
    const float* ln1_g   = (const float*)d_in[8];
    const float* ln1_b   = (const float*)d_in[9];
    const float* ln2_g   = (const float*)d_in[10];
    const float* ln2_b   = (const float*)d_in[11];
    const float* W1      = (const float*)d_in[12];
    const float* b1      = (const float*)d_in[13];
    const float* W2      = (const float*)d_in[14];
    const float* b2      = (const float*)d_in[15];
    const float* lnf_g   = (const float*)d_in[16];
    const float* lnf_b   = (const float*)d_in[17];
    const float* Wh      = (const float*)d_in[18];
    const float* bh      = (const float*)d_in[19];
    float* out = (float*)d_out;

    float *x, *xn, *q, *k, *v, *att, *ff;
    cudaGetSymbolAddress((void**)&x,   g_x);
    cudaGetSymbolAddress((void**)&xn,  g_xn);
    cudaGetSymbolAddress((void**)&q,   g_q);
    cudaGetSymbolAddress((void**)&k,   g_k);
    cudaGetSymbolAddress((void**)&v,   g_v);
    cudaGetSymbolAddress((void**)&att, g_att);
    cudaGetSymbolAddress((void**)&ff,  g_ff);

    cudaFuncSetAttribute(gemm_mma<1,0,1>, cudaFuncAttributeMaxDynamicSharedMemorySize, GEMM_SMEM);
    cudaFuncSetAttribute(gemm_mma<0,0,0>, cudaFuncAttributeMaxDynamicSharedMemorySize, GEMM_SMEM);
    cudaFuncSetAttribute(gemm_mma<0,1,0>, cudaFuncAttributeMaxDynamicSharedMemorySize, GEMM_SMEM);
    cudaFuncSetAttribute(gemm_mma<0,2,0>, cudaFuncAttributeMaxDynamicSharedMemorySize, GEMM_SMEM);

    embed_kernel<<<BT, 256>>>(idx, tok_emb, pos_emb, x);

    dim3 gQKV(32, 6, 3);
    dim3 gE(32, 6);
    dim3 gFF(32, 24);
    dim3 gV(32, 393);
    dim3 gAttn(T_ / 128, B_ * H_);

    for (int l = 0; l < L_; l++) {
        ln_kernel<<<BT, 256>>>(x, ln1_g + (size_t)l * E_, ln1_b + (size_t)l * E_, xn);

        GemmPtrs pq;
        pq.w[0] = Wq + (size_t)l * H_ * E_ * HD;
        pq.w[1] = Wk + (size_t)l * H_ * E_ * HD;
        pq.w[2] = Wv + (size_t)l * H_ * E_ * HD;
        pq.c[0] = q; pq.c[1] = k; pq.c[2] = v;
        gemm_mma<1,0,1><<<gQKV, 256, GEMM_SMEM>>>(xn, pq, nullptr, nullptr, E_, E_);

        attn_kernel<<<gAttn, 128>>>(q, k, v, att);

        GemmPtrs pp; pp.w[0] = Wo + (size_t)l * E_ * E_; pp.w[1] = pp.w[2] = nullptr;
        pp.c[0] = x; pp.c[1] = pp.c[2] = nullptr;
        gemm_mma<0,2,0><<<gE, 256, GEMM_SMEM>>>(att, pp, bo + (size_t)l * E_, x, E_, E_);

        ln_kernel<<<BT, 256>>>(x, ln2_g + (size_t)l * E_, ln2_b + (size_t)l * E_, xn);

        GemmPtrs p1; p1.w[0] = W1 + (size_t)l * E_ * FF; p1.w[1] = p1.w[2] = nullptr;
        p1.c[0] = ff; p1.c[1] = p1.c[2] = nullptr;
        gemm_mma<0,1,0><<<gFF, 256, GEMM_SMEM>>>(xn, p1, b1 + (size_t)l * FF, nullptr, FF, E_);

        GemmPtrs p2; p2.w[0] = W2 + (size_t)l * FF * E_; p2.w[1] = p2.w[2] = nullptr;
        p2.c[0] = x; p2.c[1] = p2.c[2] = nullptr;
        gemm_mma<0,2,0><<<gE, 256, GEMM_SMEM>>>(ff, p2, b2 + (size_t)l * E_, x, E_, FF);
    }

    ln_kernel<<<BT, 256>>>(x, lnf_g, lnf_b, xn);

    GemmPtrs ph; ph.w[0] = Wh; ph.w[1] = ph.w[2] = nullptr;
    ph.c[0] = out; ph.c[1] = ph.c[2] = nullptr;
    gemm_mma<0,0,0><<<gV, 256, GEMM_SMEM>>>(xn, ph, bh, nullptr, V_, E_);

    (void)in_sizes; (void)n_in; (void)out_size;
}

// round 5
// speedup vs baseline: 1.8816x; 1.2132x over previous
#include <cuda_runtime.h>
#include <cuda_bf16.h>
#include <math.h>
#include <stdint.h>

// ---------------- Problem constants ----------------
#define B_  4
#define T_  1024
#define BT  (B_*T_)        // 4096
#define E_  768
#define H_  12
#define HD  64
#define L_  6
#define FF  3072
#define V_  50257
#define EPS 1e-5f

#define GEMM_SMEM 68096
#define STAGE_LD  132

// weight scratch offsets (elements)
#define WQKV_SZ   589824
#define LAYER_SZ  7077888
#define WO_OFF    1769472
#define W1_OFF    2359296
#define W2_OFF    4718592
#define HEAD_OFF  42467328
#define WTOT      81064704

// ---------------- Device scratch (no allocs allowed) ----------------
__device__ float g_x  [BT * E_];
__device__ __nv_bfloat16 g_xn_hi[BT * E_];
__device__ __nv_bfloat16 g_xn_lo[BT * E_];
__device__ float g_qkv[3 * BT * E_];
__device__ __nv_bfloat16 g_att_hi[BT * E_];
__device__ __nv_bfloat16 g_att_lo[BT * E_];
__device__ __nv_bfloat16 g_ff_hi[BT * FF];
__device__ __nv_bfloat16 g_ff_lo[BT * FF];
__device__ __nv_bfloat16 g_w_hi[WTOT];
__device__ __nv_bfloat16 g_w_lo[WTOT];

// ---------------- helpers ----------------
__device__ __forceinline__ uint32_t smem_u32(const void* p) {
    uint32_t a;
    asm("{ .reg .u64 t; cvta.to.shared.u64 t, %1; cvt.u32.u64 %0, t; }" : "=r"(a) : "l"(p));
    return a;
}
// smem byte offset for element (r, k) in a [R][32] bf16 tile, 64B rows,
// 16B chunks XOR-swizzled by (r & 3)
__device__ __forceinline__ uint32_t aoff(uint32_t r, uint32_t k) {
    return r * 64u + (((((k) >> 3) & 3u) ^ (r & 3u)) << 4) + (k & 7u) * 2u;
}
__device__ __forceinline__ void ldmx4(uint32_t r[4], uint32_t addr) {
    asm volatile("ldmatrix.sync.aligned.m8n8.x4.shared.b16 {%0,%1,%2,%3}, [%4];"
                 : "=r"(r[0]), "=r"(r[1]), "=r"(r[2]), "=r"(r[3]) : "r"(addr));
}
__device__ __forceinline__ void mma16816(float c[4], const uint32_t a[4], const uint32_t b[2]) {
    asm volatile(
        "mma.sync.aligned.m16n8k16.row.col.f32.bf16.bf16.f32 "
        "{%0,%1,%2,%3}, {%4,%5,%6,%7}, {%8,%9}, {%0,%1,%2,%3};"
        : "+f"(c[0]), "+f"(c[1]), "+f"(c[2]), "+f"(c[3])
        : "r"(a[0]), "r"(a[1]), "r"(a[2]), "r"(a[3]), "r"(b[0]), "r"(b[1]));
}

// ---------------- Weight transpose + bf16 hi/lo split ----------------
// BMODE 0: W row-major (K,N). BMODE 1: W[h][e][d], n = h*64+d, k = e.
// out[n][k] bf16 (row length K).
template<int BMODE>
__global__ void wsplit_kernel(const float* __restrict__ W,
                              __nv_bfloat16* __restrict__ oh,
                              __nv_bfloat16* __restrict__ ol,
                              int K, int N) {
    __shared__ float t[32][33];
    const int k0 = blockIdx.x * 32, n0 = blockIdx.y * 32;
    const int tx = threadIdx.x & 31, ty = threadIdx.x >> 5;
    #pragma unroll
    for (int i = 0; i < 32; i += 8) {
        int k = k0 + ty + i, n = n0 + tx;
        float v = 0.f;
        if (n < N)
            v = (BMODE == 0) ? W[(size_t)k * N + n]
                             : W[((size_t)(n >> 6) * K + k) * 64 + (n & 63)];
        t[ty + i][tx] = v;
    }
    __syncthreads();
    #pragma unroll
    for (int i = 0; i < 32; i += 8) {
        int n = n0 + ty + i, k = k0 + tx;
        if (n < N) {
            float v = t[tx][ty + i];
            __nv_bfloat16 h = __float2bfloat16_rn(v);
            oh[(size_t)n * K + k] = h;
            ol[(size_t)n * K + k] = __float2bfloat16_rn(v - __bfloat162float(h));
        }
    }
}

// ---------------- bf16 split GEMM: C[M,N] = A @ B^T + epilogue ----------------
// A: [M][K] bf16 hi/lo.  B: [N][K] bf16 hi/lo (pre-transposed weights).
// EPI 0: +bias -> fp32 C (bias may be null; N may be odd).
// EPI 1: relu(+bias) -> bf16 hi/lo (Ch, Cl).
// EPI 2: res + (+bias) -> fp32 C.
// QKV 1: blockIdx.z offsets B by z*WQKV_SZ and C by z*BT*E_.
// fp32 via split: C = Ah*Bh + Ah*Bl + Al*Bh (fp32 accum).
template<int EPI, int QKV>
__global__ void __launch_bounds__(256, 1)
gemm_bf(const __nv_bfloat16* __restrict__ Ah, const __nv_bfloat16* __restrict__ Al,
        const __nv_bfloat16* __restrict__ Bh0, const __nv_bfloat16* __restrict__ Bl0,
        const float* __restrict__ bias, const float* __restrict__ res,
        float* C0, __nv_bfloat16* Ch, __nv_bfloat16* Cl,
        int N, int K) {
    extern __shared__ char smraw[];
    uint32_t raw = smem_u32(smraw);
    uint32_t sb  = (raw + 255u) & ~255u;
    char* smp    = smraw + (sb - raw);

    const __nv_bfloat16* Bh = Bh0;
    const __nv_bfloat16* Bl = Bl0;
    float* C = C0;
    if (QKV) {
        Bh = Bh0 + (size_t)blockIdx.z * WQKV_SZ;
        Bl = Bl0 + (size_t)blockIdx.z * WQKV_SZ;
        C  = C0  + (size_t)blockIdx.z * (BT * E_);
    }

    const int tid  = threadIdx.x;
    const int lane = tid & 31;
    const int wid  = tid >> 5;
    const int wm   = wid >> 2;
    const int wn   = wid & 3;
    const int m0   = blockIdx.x * 128;
    const int n0   = blockIdx.y * 128;

    // load mappings: each thread owns one row (A and B), 16 k per chunk
    const int r_ = tid >> 1;
    const int kh = (tid & 1) * 16;
    const __nv_bfloat16* apH = Ah + (size_t)(m0 + r_) * K + kh;
    const __nv_bfloat16* apL = Al + (size_t)(m0 + r_) * K + kh;
    const int ng = n0 + r_;
    const bool nvB = (ng < N);
    const __nv_bfloat16* bpH = Bh + (size_t)ng * K + kh;
    const __nv_bfloat16* bpL = Bl + (size_t)ng * K + kh;

    float acc[4][4][4];
    #pragma unroll
    for (int i = 0; i < 4; i++)
        #pragma unroll
        for (int j = 0; j < 4; j++)
            #pragma unroll
            for (int q = 0; q < 4; q++) acc[i][j][q] = 0.f;

    uint4 rAh0, rAh1, rAl0, rAl1, rBh0, rBh1, rBl0, rBl1;
    const int NC = K >> 5;

    auto LDG = [&](int c) {
        const int ko = c << 5;
        rAh0 = *(const uint4*)(apH + ko); rAh1 = *(const uint4*)(apH + ko + 8);
        rAl0 = *(const uint4*)(apL + ko); rAl1 = *(const uint4*)(apL + ko + 8);
        if (nvB) {
            rBh0 = *(const uint4*)(bpH + ko); rBh1 = *(const uint4*)(bpH + ko + 8);
            rBl0 = *(const uint4*)(bpL + ko); rBl1 = *(const uint4*)(bpL + ko + 8);
        } else {
            rBh0 = rBh1 = rBl0 = rBl1 = make_uint4(0u, 0u, 0u, 0u);
        }
    };
    auto STS = [&](int b) {
        char* buf = smp + b * 32768;
        uint32_t o0 = aoff(r_, kh), o1 = aoff(r_, kh + 8);
        *(uint4*)(buf + o0) = rAh0;          *(uint4*)(buf + o1) = rAh1;
        *(uint4*)(buf + 8192 + o0) = rAl0;   *(uint4*)(buf + 8192 + o1) = rAl1;
        *(uint4*)(buf + 16384 + o0) = rBh0;  *(uint4*)(buf + 16384 + o1) = rBh1;
        *(uint4*)(buf + 24576 + o0) = rBl0;  *(uint4*)(buf + 24576 + o1) = rBl1;
    };
    auto MMA = [&](int b) {
        uint32_t base = sb + b * 32768;
        const uint32_t arow = wm * 64 + (lane & 15);
        const uint32_t koffA = (lane & 16) ? 8u : 0u;
        const uint32_t nrow = wn * 32 + (lane & 7) + ((lane & 16) ? 8 : 0);
        const uint32_t koffB = (lane & 8) ? 8u : 0u;
        #pragma unroll
        for (int ks = 0; ks < 2; ks++) {
            uint32_t ah[4][4], al[4][4], bh[4][2], bl[4][2];
            #pragma unroll
            for (int mt = 0; mt < 4; mt++) {
                uint32_t off = aoff(arow + mt * 16, ks * 16 + koffA);
                ldmx4(ah[mt], base + off);
                ldmx4(al[mt], base + 8192 + off);
            }
            #pragma unroll
            for (int g = 0; g < 2; g++) {
                uint32_t off = aoff(nrow + g * 16, ks * 16 + koffB);
                uint32_t t[4];
                ldmx4(t, base + 16384 + off);
                bh[2*g][0] = t[0]; bh[2*g][1] = t[1];
                bh[2*g+1][0] = t[2]; bh[2*g+1][1] = t[3];
                ldmx4(t, base + 24576 + off);
                bl[2*g][0] = t[0]; bl[2*g][1] = t[1];
                bl[2*g+1][0] = t[2]; bl[2*g+1][1] = t[3];
            }
            #pragma unroll
            for (int mt = 0; mt < 4; mt++)
                #pragma unroll
                for (int nt = 0; nt < 4; nt++) {
                    mma16816(acc[mt][nt], ah[mt], bh[nt]);
                    mma16816(acc[mt][nt], ah[mt], bl[nt]);
                    mma16816(acc[mt][nt], al[mt], bh[nt]);
                }
        }
    };

    LDG(0);
    STS(0);
    __syncthreads();
    for (int c = 0; c < NC; c++) {
        if (c + 1 < NC) LDG(c + 1);
        MMA(c & 1);
        if (c + 1 < NC) STS((c + 1) & 1);
        __syncthreads();
    }

    // ---- epilogue: regs -> smem stage -> gmem ----
    float* stage = (float*)smp;
    {
        const int r0 = wm * 64 + (lane >> 2);
        const int c0 = wn * 32 + (lane & 3) * 2;
        #pragma unroll
        for (int mt = 0; mt < 4; mt++)
            #pragma unroll
            for (int nt = 0; nt < 4; nt++) {
                int r = r0 + mt * 16, cc = c0 + nt * 8;
                float2 p0; p0.x = acc[mt][nt][0]; p0.y = acc[mt][nt][1];
                float2 p1; p1.x = acc[mt][nt][2]; p1.y = acc[mt][nt][3];
                *(float2*)&stage[r * STAGE_LD + cc]       = p0;
                *(float2*)&stage[(r + 8) * STAGE_LD + cc] = p1;
            }
    }
    __syncthreads();

    if (EPI == 1) {
        // relu(+bias) -> bf16 hi/lo (N divisible by 4)
        #pragma unroll 4
        for (int j = 0; j < 16; j++) {
            int lin = j * 256 + tid;
            int rr = lin >> 5;
            int cg = (lin & 31) * 4;
            int n  = n0 + cg;
            float4 v = *(float4*)&stage[rr * STAGE_LD + cg];
            if (bias) {
                float4 bb = *(const float4*)(bias + n);
                v.x += bb.x; v.y += bb.y; v.z += bb.z; v.w += bb.w;
            }
            v.x = fmaxf(v.x, 0.f); v.y = fmaxf(v.y, 0.f);
            v.z = fmaxf(v.z, 0.f); v.w = fmaxf(v.w, 0.f);
            size_t base = (size_t)(m0 + rr) * N + n;
            __nv_bfloat16 h0 = __float2bfloat16_rn(v.x), h1 = __float2bfloat16_rn(v.y);
            __nv_bfloat16 h2 = __float2bfloat16_rn(v.z), h3 = __float2bfloat16_rn(v.w);
            __nv_bfloat162 hp0; hp0.x = h0; hp0.y = h1;
            __nv_bfloat162 hp1; hp1.x = h2; hp1.y = h3;
            *(__nv_bfloat162*)(Ch + base)     = hp0;
            *(__nv_bfloat162*)(Ch + base + 2) = hp1;
            __nv_bfloat162 lp0, lp1;
            lp0.x = __float2bfloat16_rn(v.x - __bfloat162float(h0));
            lp0.y = __float2bfloat16_rn(v.y - __bfloat162float(h1));
            lp1.x = __float2bfloat16_rn(v.z - __bfloat162float(h2));
            lp1.y = __float2bfloat16_rn(v.w - __bfloat162float(h3));
            *(__nv_bfloat162*)(Cl + base)     = lp0;
            *(__nv_bfloat162*)(Cl + base + 2) = lp1;
        }
    } else if ((N & 3) == 0) {
        #pragma unroll 4
        for (int j = 0; j < 16; j++) {
            int lin = j * 256 + tid;
            int rr = lin >> 5;
            int cg = (lin & 31) * 4;
            int n  = n0 + cg;
            float4 v = *(float4*)&stage[rr * STAGE_LD + cg];
            size_t base = (size_t)(m0 + rr) * N + n;
            if (bias) {
                float4 bb = *(const float4*)(bias + n);
                v.x += bb.x; v.y += bb.y; v.z += bb.z; v.w += bb.w;
            }
            if (EPI == 2) {
                float4 rr4 = *(const float4*)(res + base);
                v.x += rr4.x; v.y += rr4.y; v.z += rr4.z; v.w += rr4.w;
            }
            *(float4*)(C + base) = v;
        }
    } else {
        #pragma unroll 4
        for (int j = 0; j < 16; j++) {
            int lin = j * 256 + tid;
            int rr = lin >> 5;
            int cg = (lin & 31) * 4;
            #pragma unroll
            for (int q = 0; q < 4; q++) {
                int n = n0 + cg + q;
                if (n < N) {
                    float v = stage[rr * STAGE_LD + cg + q];
                    if (bias) v += bias[n];
                    size_t base = (size_t)(m0 + rr) * N + n;
                    if (EPI == 2) v += res[base];
                    C[base] = v;
                }
            }
        }
    }
}

// ---------------- Embedding ----------------
__global__ void embed_kernel(const int* __restrict__ idx,
                             const float* __restrict__ tok,
                             const float* __restrict__ pos,
                             float* __restrict__ x) {
    int row = blockIdx.x;
    int t   = row & (T_ - 1);
    int token = idx[row];
    const float* tp = tok + (size_t)token * E_;
    const float* pp = pos + (size_t)t * E_;
    float* xp = x + (size_t)row * E_;
    for (int e = threadIdx.x; e < E_; e += blockDim.x)
        xp[e] = tp[e] + pp[e];
}

// ---------------- LayerNorm -> bf16 hi/lo ----------------
__global__ void ln_kernel(const float* __restrict__ x,
                          const float* __restrict__ g,
                          const float* __restrict__ b,
                          __nv_bfloat16* __restrict__ yh,
                          __nv_bfloat16* __restrict__ yl) {
    int row = blockIdx.x;
    int tid = threadIdx.x;
    const float* xr = x + (size_t)row * E_;
    float v0 = xr[tid], v1 = xr[tid + 256], v2 = xr[tid + 512];
    float s  = v0 + v1 + v2;
    float ss = v0*v0 + v1*v1 + v2*v2;
    #pragma unroll
    for (int off = 16; off > 0; off >>= 1) {
        s  += __shfl_down_sync(0xffffffffu, s,  off);
        ss += __shfl_down_sync(0xffffffffu, ss, off);
    }
    __shared__ float sh_s[8], sh_ss[8];
    int wid = tid >> 5, lane = tid & 31;
    if (lane == 0) { sh_s[wid] = s; sh_ss[wid] = ss; }
    __syncthreads();
    float tot = 0.f, tots = 0.f;
    #pragma unroll
    for (int i = 0; i < 8; i++) { tot += sh_s[i]; tots += sh_ss[i]; }
    float mean = tot * (1.0f / E_);
    float var  = tots * (1.0f / E_) - mean * mean;
    float rstd = rsqrtf(var + EPS);
    size_t rb = (size_t)row * E_;
    #pragma unroll
    for (int i = 0; i < 3; i++) {
        int c = tid + i * 256;
        float vv = (i == 0 ? v0 : (i == 1 ? v1 : v2));
        float y = (vv - mean) * rstd * g[c] + b[c];
        __nv_bfloat16 h = __float2bfloat16_rn(y);
        yh[rb + c] = h;
        yl[rb + c] = __float2bfloat16_rn(y - __bfloat162float(h));
    }
}

// ---------------- Attention (causal, online softmax, 2 threads/query) ----------------
__global__ void attn_kernel(const float* __restrict__ qkv,
                            __nv_bfloat16* __restrict__ oh,
                            __nv_bfloat16* __restrict__ ol) {
    __shared__ float Ks[64][68];
    __shared__ float Vs[64][68];

    const float* q = qkv;
    const float* k = qkv + (size_t)BT * E_;
    const float* v = qkv + 2 * (size_t)BT * E_;

    const int bh = blockIdx.y;
    const int b  = bh / H_, h = bh % H_;
    const int tid = threadIdx.x;
    const int tq  = blockIdx.x * 128 + (tid >> 1);
    const int half = (tid & 1) * 32;
    const float scale = rsqrtf((float)E_);

    float qr[32], oacc[32];
    const float* qp = q + (size_t)(b * T_ + tq) * E_ + h * 64 + half;
    #pragma unroll
    for (int d = 0; d < 32; d += 4) {
        float4 t4 = *(const float4*)(qp + d);
        qr[d] = t4.x * scale; qr[d+1] = t4.y * scale; qr[d+2] = t4.z * scale; qr[d+3] = t4.w * scale;
    }
    #pragma unroll
    for (int d = 0; d < 32; d++) oacc[d] = 0.f;

    float m = -1e30f, lsum = 0.f;
    const int kt_end = blockIdx.x * 128 + 127;
    const int ls = tid >> 2;            // load row 0..63
    const int lq = (tid & 3) * 16;      // load col 0/16/32/48

    for (int st0 = 0; st0 <= kt_end; st0 += 64) {
        const float* kp = k + (size_t)(b * T_ + st0 + ls) * E_ + h * 64 + lq;
        const float* vp = v + (size_t)(b * T_ + st0 + ls) * E_ + h * 64 + lq;
        #pragma unroll
        for (int d = 0; d < 16; d += 4) {
            *(float4*)&Ks[ls][lq + d] = *(const float4*)(kp + d);
            *(float4*)&Vs[ls][lq + d] = *(const float4*)(vp + d);
        }
        __syncthreads();

        #pragma unroll 2
        for (int s2 = 0; s2 < 64; s2++) {
            float p_ = 0.f;
            #pragma unroll
            for (int d = 0; d < 32; d += 4) {
                float4 kv = *(const float4*)&Ks[s2][half + d];
                p_ += qr[d] * kv.x + qr[d+1] * kv.y + qr[d+2] * kv.z + qr[d+3] * kv.w;
            }
            float sc = p_ + __shfl_xor_sync(0xffffffffu, p_, 1);
            if (st0 + s2 <= tq) {
                float newm = fmaxf(m, sc);
                float corr = __expf(m - newm);
                float p    = __expf(sc - newm);
                lsum = lsum * corr + p;
                #pragma unroll
                for (int d = 0; d < 32; d += 4) {
                    float4 vv = *(const float4*)&Vs[s2][half + d];
                    oacc[d]   = oacc[d]   * corr + p * vv.x;
                    oacc[d+1] = oacc[d+1] * corr + p * vv.y;
                    oacc[d+2] = oacc[d+2] * corr + p * vv.z;
                    oacc[d+3] = oacc[d+3] * corr + p * vv.w;
                }
                m = newm;
            }
        }
        __syncthreads();
    }

    float inv = 1.0f / lsum;
    size_t ob = (size_t)(b * T_ + tq) * E_ + h * 64 + half;
    #pragma unroll
    for (int d = 0; d < 32; d += 2) {
        float v0 = oacc[d] * inv, v1 = oacc[d+1] * inv;
        __nv_bfloat16 h0 = __float2bfloat16_rn(v0), h1 = __float2bfloat16_rn(v1);
        __nv_bfloat162 hp; hp.x = h0; hp.y = h1;
        *(__nv_bfloat162*)(oh + ob + d) = hp;
        __nv_bfloat162 lp;
        lp.x = __float2bfloat16_rn(v0 - __bfloat162float(h0));
        lp.y = __float2bfloat16_rn(v1 - __bfloat162float(h1));
        *(__nv_bfloat162*)(ol + ob + d) = lp;
    }
}

// ---------------- Host launch ----------------
extern "C" void kernel_launch(void* const* d_in, const int* in_sizes, int n_in,
                              void* d_out, int out_size) {
    const int*   idx     = (const int*)  d_in[0];
    const float* tok_emb = (const float*)d_in[1];
    const float* pos_emb = (const float*)d_in[2];
    const float* Wq      = (const float*)d_in[3];
    const float* Wk      = (const float*)d_in[4];
    const float* Wv      = (const float*)d_in[5];
    const float* Wo      = (const float*)d_in[6];
    const float* bo      = (const float*)d_in[7];
    const float* ln1_g   = (const float*)d_in[8];
    const float* ln1_b   = (const float*)d_in[9];
    const float* ln2_g   = (const float*)d_in[10];
    const float* ln2_b   = (const float*)d_in[11];
    const float* W1      = (const float*)d_in[12];
    const float* b1      = (const float*)d_in[13];
    const float* W2      = (const float*)d_in[14];
    const float* b2      = (const float*)d_in[15];
    const float* lnf_g   = (const float*)d_in[16];
    const float* lnf_b   = (const float*)d_in[17];
    const float* Wh      = (const float*)d_in[18];
    const float* bh      = (const float*)d_in[19];
    float* out = (float*)d_out;

    float *x, *qkv;
    __nv_bfloat16 *xnh, *xnl, *atth, *attl, *ffh, *ffl, *wh, *wl;
    cudaGetSymbolAddress((void**)&x,    g_x);
    cudaGetSymbolAddress((void**)&qkv,  g_qkv);
    cudaGetSymbolAddress((void**)&xnh,  g_xn_hi);
    cudaGetSymbolAddress((void**)&xnl,  g_xn_lo);
    cudaGetSymbolAddress((void**)&atth, g_att_hi);
    cudaGetSymbolAddress((void**)&attl, g_att_lo);
    cudaGetSymbolAddress((void**)&ffh,  g_ff_hi);
    cudaGetSymbolAddress((void**)&ffl,  g_ff_lo);
    cudaGetSymbolAddress((void**)&wh,   g_w_hi);
    cudaGetSymbolAddress((void**)&wl,   g_w_lo);

    cudaFuncSetAttribute(gemm_bf<0,1>, cudaFuncAttributeMaxDynamicSharedMemorySize, GEMM_SMEM);
    cudaFuncSetAttribute(gemm_bf<0,0>, cudaFuncAttributeMaxDynamicSharedMemorySize, GEMM_SMEM);
    cudaFuncSetAttribute(gemm_bf<1,0>, cudaFuncAttributeMaxDynamicSharedMemorySize, GEMM_SMEM);
    cudaFuncSetAttribute(gemm_bf<2,0>, cudaFuncAttributeMaxDynamicSharedMemorySize, GEMM_SMEM);

    // ---- weight prep: transpose + split all weights ----
    {
        dim3 gEE(E_/32, E_/32);          // (24,24)
        dim3 gE1(E_/32, FF/32);          // (24,96)
        dim3 gE2(FF/32, E_/32);          // (96,24)
        dim3 gHd(E_/32, (V_+31)/32);     // (24,1571)
        for (int l = 0; l < L_; l++) {
            size_t lo = (size_t)l * LAYER_SZ;
            wsplit_kernel<1><<<gEE, 256>>>(Wq + (size_t)l*H_*E_*HD, wh + lo,            wl + lo,            E_, E_);
            wsplit_kernel<1><<<gEE, 256>>>(Wk + (size_t)l*H_*E_*HD, wh + lo + WQKV_SZ,  wl + lo + WQKV_SZ,  E_, E_);
            wsplit_kernel<1><<<gEE, 256>>>(Wv + (size_t)l*H_*E_*HD, wh + lo + 2*WQKV_SZ,wl + lo + 2*WQKV_SZ,E_, E_);
            wsplit_kernel<0><<<gEE, 256>>>(Wo + (size_t)l*E_*E_,    wh + lo + WO_OFF,   wl + lo + WO_OFF,   E_, E_);
            wsplit_kernel<0><<<gE1, 256>>>(W1 + (size_t)l*E_*FF,    wh + lo + W1_OFF,   wl + lo + W1_OFF,   E_, FF);
            wsplit_kernel<0><<<gE2, 256>>>(W2 + (size_t)l*FF*E_,    wh + lo + W2_OFF,   wl + lo + W2_OFF,   FF, E_);
        }
        wsplit_kernel<0><<<gHd, 256>>>(Wh, wh + HEAD_OFF, wl + HEAD_OFF, E_, V_);
    }

    embed_kernel<<<BT, 256>>>(idx, tok_emb, pos_emb, x);

    dim3 gQKV(32, 6, 3);
    dim3 gE(32, 6);
    dim3 gFF(32, 24);
    dim3 gV(32, 393);
    dim3 gAttn(T_ / 128, B_ * H_);

    for (int l = 0; l < L_; l++) {
        size_t lo = (size_t)l * LAYER_SZ;

        ln_kernel<<<BT, 256>>>(x, ln1_g + (size_t)l * E_, ln1_b + (size_t)l * E_, xnh, xnl);

        gemm_bf<0,1><<<gQKV, 256, GEMM_SMEM>>>(xnh, xnl, wh + lo, wl + lo,
                                               nullptr, nullptr, qkv, nullptr, nullptr, E_, E_);

        attn_kernel<<<gAttn, 256>>>(qkv, atth, attl);

        gemm_bf<2,0><<<gE, 256, GEMM_SMEM>>>(atth, attl, wh + lo + WO_OFF, wl + lo + WO_OFF,
                                             bo + (size_t)l * E_, x, x, nullptr, nullptr, E_, E_);

        ln_kernel<<<BT, 256>>>(x, ln2_g + (size_t)l * E_, ln2_b + (size_t)l * E_, xnh, xnl);

        gemm_bf<1,0><<<gFF, 256, GEMM_SMEM>>>(xnh, xnl, wh + lo + W1_OFF, wl + lo + W1_OFF,
                                              b1 + (size_t)l * FF, nullptr, nullptr, ffh, ffl, FF, E_);

        gemm_bf<2,0><<<gE, 256, GEMM_SMEM>>>(ffh, ffl, wh + lo + W2_OFF, wl + lo + W2_OFF,
                                             b2 + (size_t)l * E_, x, x, nullptr, nullptr, E_, FF);
    }

    ln_kernel<<<BT, 256>>>(x, lnf_g, lnf_b, xnh, xnl);

    gemm_bf<0,0><<<gV, 256, GEMM_SMEM>>>(xnh, xnl, wh + HEAD_OFF, wl + HEAD_OFF,
                                         bh, nullptr, out, nullptr, nullptr, V_, E_);

    (void)in_sizes; (void)n_in; (void)out_size;
}

// round 6
// speedup vs baseline: 2.0267x; 1.0771x over previous
#include <cuda_runtime.h>
#include <cuda_bf16.h>
#include <math.h>
#include <stdint.h>

// ---------------- Problem constants ----------------
#define B_  4
#define T_  1024
#define BT  (B_*T_)        // 4096
#define E_  768
#define H_  12
#define HD  64
#define L_  6
#define FF  3072
#define V_  50257
#define EPS 1e-5f

#define GEMM_SMEM 132096
#define STAGE_LD  132

// weight scratch offsets (elements)
#define WQKV_SZ   589824
#define LAYER_SZ  7077888
#define WO_OFF    1769472
#define W1_OFF    2359296
#define W2_OFF    4718592
#define HEAD_OFF  42467328
#define WTOT      81064704

// ---------------- Device scratch (no allocs allowed) ----------------
__device__ float g_x  [BT * E_];
__device__ __nv_bfloat16 g_xn_hi[BT * E_];
__device__ __nv_bfloat16 g_xn_lo[BT * E_];
__device__ float g_qkv[3 * BT * E_];
__device__ __nv_bfloat16 g_att_hi[BT * E_];
__device__ __nv_bfloat16 g_att_lo[BT * E_];
__device__ __nv_bfloat16 g_ff_hi[BT * FF];
__device__ __nv_bfloat16 g_ff_lo[BT * FF];
__device__ __nv_bfloat16 g_w_hi[WTOT];
__device__ __nv_bfloat16 g_w_lo[WTOT];

// ---------------- helpers ----------------
__device__ __forceinline__ uint32_t smem_u32(const void* p) {
    uint32_t a;
    asm("{ .reg .u64 t; cvta.to.shared.u64 t, %1; cvt.u32.u64 %0, t; }" : "=r"(a) : "l"(p));
    return a;
}
// smem byte offset for element (r, k) in a [R][32] bf16 tile, 64B rows,
// 16B chunks XOR-swizzled by (r & 3)
__device__ __forceinline__ uint32_t aoff(uint32_t r, uint32_t k) {
    return r * 64u + (((((k) >> 3) & 3u) ^ (r & 3u)) << 4) + (k & 7u) * 2u;
}
__device__ __forceinline__ void ldmx4(uint32_t r[4], uint32_t addr) {
    asm volatile("ldmatrix.sync.aligned.m8n8.x4.shared.b16 {%0,%1,%2,%3}, [%4];"
                 : "=r"(r[0]), "=r"(r[1]), "=r"(r[2]), "=r"(r[3]) : "r"(addr));
}
__device__ __forceinline__ void mma16816(float c[4], const uint32_t a[4], const uint32_t b[2]) {
    asm volatile(
        "mma.sync.aligned.m16n8k16.row.col.f32.bf16.bf16.f32 "
        "{%0,%1,%2,%3}, {%4,%5,%6,%7}, {%8,%9}, {%0,%1,%2,%3};"
        : "+f"(c[0]), "+f"(c[1]), "+f"(c[2]), "+f"(c[3])
        : "r"(a[0]), "r"(a[1]), "r"(a[2]), "r"(a[3]), "r"(b[0]), "r"(b[1]));
}
__device__ __forceinline__ void cp16(uint32_t dst, const void* src, uint32_t sz) {
    asm volatile("cp.async.cg.shared.global [%0], [%1], 16, %2;"
                 :: "r"(dst), "l"(src), "r"(sz) : "memory");
}
#define CP_COMMIT() asm volatile("cp.async.commit_group;" ::: "memory")
#define CP_WAIT(n)  asm volatile("cp.async.wait_group %0;" :: "n"(n) : "memory")

// ---------------- Weight transpose + bf16 hi/lo split ----------------
// BMODE 0: W row-major (K,N). BMODE 1: W[h][e][d], n = h*64+d, k = e.
// out[n][k] bf16 (row length K).
template<int BMODE>
__global__ void wsplit_kernel(const float* __restrict__ W,
                              __nv_bfloat16* __restrict__ oh,
                              __nv_bfloat16* __restrict__ ol,
                              int K, int N) {
    __shared__ float t[32][33];
    const int k0 = blockIdx.x * 32, n0 = blockIdx.y * 32;
    const int tx = threadIdx.x & 31, ty = threadIdx.x >> 5;
    #pragma unroll
    for (int i = 0; i < 32; i += 8) {
        int k = k0 + ty + i, n = n0 + tx;
        float v = 0.f;
        if (n < N)
            v = (BMODE == 0) ? W[(size_t)k * N + n]
                             : W[((size_t)(n >> 6) * K + k) * 64 + (n & 63)];
        t[ty + i][tx] = v;
    }
    __syncthreads();
    #pragma unroll
    for (int i = 0; i < 32; i += 8) {
        int n = n0 + ty + i, k = k0 + tx;
        if (n < N) {
            float v = t[tx][ty + i];
            __nv_bfloat16 h = __float2bfloat16_rn(v);
            oh[(size_t)n * K + k] = h;
            ol[(size_t)n * K + k] = __float2bfloat16_rn(v - __bfloat162float(h));
        }
    }
}

// ---------------- bf16 split GEMM: C[M,N] = A @ B^T + epilogue ----------------
// A: [M][K] bf16 hi/lo.  B: [N][K] bf16 hi/lo (pre-transposed weights).
// EPI 0: +bias -> fp32 C (bias may be null; N may be odd).
// EPI 1: relu(+bias) -> bf16 hi/lo (Ch, Cl).
// EPI 2: res + (+bias) -> fp32 C.
// QKV 1: blockIdx.z offsets B by z*WQKV_SZ and C by z*BT*E_.
// fp32 via split: C = Ah*Bh + Ah*Bl + Al*Bh (fp32 accum).
// Mainloop: cp.async 4-stage ring, loads issued 3 chunks ahead.
template<int EPI, int QKV>
__global__ void __launch_bounds__(256)
gemm_bf(const __nv_bfloat16* __restrict__ Ah, const __nv_bfloat16* __restrict__ Al,
        const __nv_bfloat16* __restrict__ Bh0, const __nv_bfloat16* __restrict__ Bl0,
        const float* __restrict__ bias, const float* __restrict__ res,
        float* C0, __nv_bfloat16* Ch, __nv_bfloat16* Cl,
        int N, int K) {
    extern __shared__ char smraw[];
    uint32_t raw = smem_u32(smraw);
    uint32_t sb  = (raw + 255u) & ~255u;
    char* smp    = smraw + (sb - raw);

    const __nv_bfloat16* Bh = Bh0;
    const __nv_bfloat16* Bl = Bl0;
    float* C = C0;
    if (QKV) {
        Bh = Bh0 + (size_t)blockIdx.z * WQKV_SZ;
        Bl = Bl0 + (size_t)blockIdx.z * WQKV_SZ;
        C  = C0  + (size_t)blockIdx.z * (BT * E_);
    }

    const int tid  = threadIdx.x;
    const int lane = tid & 31;
    const int wid  = tid >> 5;
    const int wm   = wid >> 2;
    const int wn   = wid & 3;
    const int m0   = blockIdx.x * 128;
    const int n0   = blockIdx.y * 128;

    // load mappings: each thread owns one row (A and B), 16 k per chunk
    const int r_ = tid >> 1;
    const int kh = (tid & 1) * 16;
    const __nv_bfloat16* apH = Ah + (size_t)(m0 + r_) * K + kh;
    const __nv_bfloat16* apL = Al + (size_t)(m0 + r_) * K + kh;
    const int ng = n0 + r_;
    const bool nvB = (ng < N);
    const int ngc = nvB ? ng : (N - 1);          // clamped (valid) row
    const uint32_t bsz = nvB ? 16u : 0u;         // zfill when OOB
    const __nv_bfloat16* bpH = Bh + (size_t)ngc * K + kh;
    const __nv_bfloat16* bpL = Bl + (size_t)ngc * K + kh;

    float acc[4][4][4];
    #pragma unroll
    for (int i = 0; i < 4; i++)
        #pragma unroll
        for (int j = 0; j < 4; j++)
            #pragma unroll
            for (int q = 0; q < 4; q++) acc[i][j][q] = 0.f;

    const int NC = K >> 5;
    const uint32_t o0 = aoff(r_, kh), o1 = aoff(r_, kh + 8);

    auto ISSUE = [&](int c) {
        uint32_t b0 = sb + (c & 3) * 32768;
        const int ko = c << 5;
        cp16(b0 + o0,         apH + ko,     16u);
        cp16(b0 + o1,         apH + ko + 8, 16u);
        cp16(b0 + 8192 + o0,  apL + ko,     16u);
        cp16(b0 + 8192 + o1,  apL + ko + 8, 16u);
        cp16(b0 + 16384 + o0, bpH + ko,     bsz);
        cp16(b0 + 16384 + o1, bpH + ko + 8, bsz);
        cp16(b0 + 24576 + o0, bpL + ko,     bsz);
        cp16(b0 + 24576 + o1, bpL + ko + 8, bsz);
    };
    auto MMA = [&](int s) {
        uint32_t base = sb + s * 32768;
        const uint32_t arow = wm * 64 + (lane & 15);
        const uint32_t koffA = (lane & 16) ? 8u : 0u;
        const uint32_t nrow = wn * 32 + (lane & 7) + ((lane & 16) ? 8 : 0);
        const uint32_t koffB = (lane & 8) ? 8u : 0u;
        #pragma unroll
        for (int ks = 0; ks < 2; ks++) {
            uint32_t ah[4][4], al[4][4], bh[4][2], bl[4][2];
            #pragma unroll
            for (int mt = 0; mt < 4; mt++) {
                uint32_t off = aoff(arow + mt * 16, ks * 16 + koffA);
                ldmx4(ah[mt], base + off);
                ldmx4(al[mt], base + 8192 + off);
            }
            #pragma unroll
            for (int g = 0; g < 2; g++) {
                uint32_t off = aoff(nrow + g * 16, ks * 16 + koffB);
                uint32_t t[4];
                ldmx4(t, base + 16384 + off);
                bh[2*g][0] = t[0]; bh[2*g][1] = t[1];
                bh[2*g+1][0] = t[2]; bh[2*g+1][1] = t[3];
                ldmx4(t, base + 24576 + off);
                bl[2*g][0] = t[0]; bl[2*g][1] = t[1];
                bl[2*g+1][0] = t[2]; bl[2*g+1][1] = t[3];
            }
            #pragma unroll
            for (int mt = 0; mt < 4; mt++)
                #pragma unroll
                for (int nt = 0; nt < 4; nt++) {
                    mma16816(acc[mt][nt], ah[mt], bh[nt]);
                    mma16816(acc[mt][nt], ah[mt], bl[nt]);
                    mma16816(acc[mt][nt], al[mt], bh[nt]);
                }
        }
    };

    // prologue: prefetch 3 stages
    ISSUE(0); CP_COMMIT();
    if (NC > 1) { ISSUE(1); CP_COMMIT(); }
    if (NC > 2) { ISSUE(2); CP_COMMIT(); }

    for (int c = 0; c < NC; c++) {
        const int rem = NC - 1 - c;
        if (rem >= 2)      CP_WAIT(2);
        else if (rem == 1) CP_WAIT(1);
        else               CP_WAIT(0);
        __syncthreads();                    // stage c visible; stage (c+3)&3 free
        if (c + 3 < NC) { ISSUE(c + 3); CP_COMMIT(); }
        MMA(c & 3);
    }
    __syncthreads();                        // all reads done before stage reuse

    // ---- epilogue: regs -> smem stage -> gmem ----
    float* stage = (float*)smp;
    {
        const int r0 = wm * 64 + (lane >> 2);
        const int c0 = wn * 32 + (lane & 3) * 2;
        #pragma unroll
        for (int mt = 0; mt < 4; mt++)
            #pragma unroll
            for (int nt = 0; nt < 4; nt++) {
                int r = r0 + mt * 16, cc = c0 + nt * 8;
                float2 p0; p0.x = acc[mt][nt][0]; p0.y = acc[mt][nt][1];
                float2 p1; p1.x = acc[mt][nt][2]; p1.y = acc[mt][nt][3];
                *(float2*)&stage[r * STAGE_LD + cc]       = p0;
                *(float2*)&stage[(r + 8) * STAGE_LD + cc] = p1;
            }
    }
    __syncthreads();

    if (EPI == 1) {
        // relu(+bias) -> bf16 hi/lo (N divisible by 4)
        #pragma unroll 4
        for (int j = 0; j < 16; j++) {
            int lin = j * 256 + tid;
            int rr = lin >> 5;
            int cg = (lin & 31) * 4;
            int n  = n0 + cg;
            float4 v = *(float4*)&stage[rr * STAGE_LD + cg];
            if (bias) {
                float4 bb = *(const float4*)(bias + n);
                v.x += bb.x; v.y += bb.y; v.z += bb.z; v.w += bb.w;
            }
            v.x = fmaxf(v.x, 0.f); v.y = fmaxf(v.y, 0.f);
            v.z = fmaxf(v.z, 0.f); v.w = fmaxf(v.w, 0.f);
            size_t base = (size_t)(m0 + rr) * N + n;
            __nv_bfloat16 h0 = __float2bfloat16_rn(v.x), h1 = __float2bfloat16_rn(v.y);
            __nv_bfloat16 h2 = __float2bfloat16_rn(v.z), h3 = __float2bfloat16_rn(v.w);
            __nv_bfloat162 hp0; hp0.x = h0; hp0.y = h1;
            __nv_bfloat162 hp1; hp1.x = h2; hp1.y = h3;
            *(__nv_bfloat162*)(Ch + base)     = hp0;
            *(__nv_bfloat162*)(Ch + base + 2) = hp1;
            __nv_bfloat162 lp0, lp1;
            lp0.x = __float2bfloat16_rn(v.x - __bfloat162float(h0));
            lp0.y = __float2bfloat16_rn(v.y - __bfloat162float(h1));
            lp1.x = __float2bfloat16_rn(v.z - __bfloat162float(h2));
            lp1.y = __float2bfloat16_rn(v.w - __bfloat162float(h3));
            *(__nv_bfloat162*)(Cl + base)     = lp0;
            *(__nv_bfloat162*)(Cl + base + 2) = lp1;
        }
    } else if ((N & 3) == 0) {
        #pragma unroll 4
        for (int j = 0; j < 16; j++) {
            int lin = j * 256 + tid;
            int rr = lin >> 5;
            int cg = (lin & 31) * 4;
            int n  = n0 + cg;
            float4 v = *(float4*)&stage[rr * STAGE_LD + cg];
            size_t base = (size_t)(m0 + rr) * N + n;
            if (bias) {
                float4 bb = *(const float4*)(bias + n);
                v.x += bb.x; v.y += bb.y; v.z += bb.z; v.w += bb.w;
            }
            if (EPI == 2) {
                float4 rr4 = *(const float4*)(res + base);
                v.x += rr4.x; v.y += rr4.y; v.z += rr4.z; v.w += rr4.w;
            }
            *(float4*)(C + base) = v;
        }
    } else {
        #pragma unroll 4
        for (int j = 0; j < 16; j++) {
            int lin = j * 256 + tid;
            int rr = lin >> 5;
            int cg = (lin & 31) * 4;
            #pragma unroll
            for (int q = 0; q < 4; q++) {
                int n = n0 + cg + q;
                if (n < N) {
                    float v = stage[rr * STAGE_LD + cg + q];
                    if (bias) v += bias[n];
                    size_t base = (size_t)(m0 + rr) * N + n;
                    if (EPI == 2) v += res[base];
                    C[base] = v;
                }
            }
        }
    }
}

// ---------------- Embedding ----------------
__global__ void embed_kernel(const int* __restrict__ idx,
                             const float* __restrict__ tok,
                             const float* __restrict__ pos,
                             float* __restrict__ x) {
    int row = blockIdx.x;
    int t   = row & (T_ - 1);
    int token = idx[row];
    const float* tp = tok + (size_t)token * E_;
    const float* pp = pos + (size_t)t * E_;
    float* xp = x + (size_t)row * E_;
    for (int e = threadIdx.x; e < E_; e += blockDim.x)
        xp[e] = tp[e] + pp[e];
}

// ---------------- LayerNorm -> bf16 hi/lo ----------------
__global__ void ln_kernel(const float* __restrict__ x,
                          const float* __restrict__ g,
                          const float* __restrict__ b,
                          __nv_bfloat16* __restrict__ yh,
                          __nv_bfloat16* __restrict__ yl) {
    int row = blockIdx.x;
    int tid = threadIdx.x;
    const float* xr = x + (size_t)row * E_;
    float v0 = xr[tid], v1 = xr[tid + 256], v2 = xr[tid + 512];
    float s  = v0 + v1 + v2;
    float ss = v0*v0 + v1*v1 + v2*v2;
    #pragma unroll
    for (int off = 16; off > 0; off >>= 1) {
        s  += __shfl_down_sync(0xffffffffu, s,  off);
        ss += __shfl_down_sync(0xffffffffu, ss, off);
    }
    __shared__ float sh_s[8], sh_ss[8];
    int wid = tid >> 5, lane = tid & 31;
    if (lane == 0) { sh_s[wid] = s; sh_ss[wid] = ss; }
    __syncthreads();
    float tot = 0.f, tots = 0.f;
    #pragma unroll
    for (int i = 0; i < 8; i++) { tot += sh_s[i]; tots += sh_ss[i]; }
    float mean = tot * (1.0f / E_);
    float var  = tots * (1.0f / E_) - mean * mean;
    float rstd = rsqrtf(var + EPS);
    size_t rb = (size_t)row * E_;
    #pragma unroll
    for (int i = 0; i < 3; i++) {
        int c = tid + i * 256;
        float vv = (i == 0 ? v0 : (i == 1 ? v1 : v2));
        float y = (vv - mean) * rstd * g[c] + b[c];
        __nv_bfloat16 h = __float2bfloat16_rn(y);
        yh[rb + c] = h;
        yl[rb + c] = __float2bfloat16_rn(y - __bfloat162float(h));
    }
}

// ---------------- Attention (causal, online softmax, 2 threads/query) ----------------
__global__ void attn_kernel(const float* __restrict__ qkv,
                            __nv_bfloat16* __restrict__ oh,
                            __nv_bfloat16* __restrict__ ol) {
    __shared__ float Ks[64][68];
    __shared__ float Vs[64][68];

    const float* q = qkv;
    const float* k = qkv + (size_t)BT * E_;
    const float* v = qkv + 2 * (size_t)BT * E_;

    const int bh = blockIdx.y;
    const int b  = bh / H_, h = bh % H_;
    const int tid = threadIdx.x;
    const int tq  = blockIdx.x * 128 + (tid >> 1);
    const int half = (tid & 1) * 32;
    const float scale = rsqrtf((float)E_);

    float qr[32], oacc[32];
    const float* qp = q + (size_t)(b * T_ + tq) * E_ + h * 64 + half;
    #pragma unroll
    for (int d = 0; d < 32; d += 4) {
        float4 t4 = *(const float4*)(qp + d);
        qr[d] = t4.x * scale; qr[d+1] = t4.y * scale; qr[d+2] = t4.z * scale; qr[d+3] = t4.w * scale;
    }
    #pragma unroll
    for (int d = 0; d < 32; d++) oacc[d] = 0.f;

    float m = -1e30f, lsum = 0.f;
    const int kt_end = blockIdx.x * 128 + 127;
    const int ls = tid >> 2;            // load row 0..63
    const int lq = (tid & 3) * 16;      // load col 0/16/32/48

    for (int st0 = 0; st0 <= kt_end; st0 += 64) {
        const float* kp = k + (size_t)(b * T_ + st0 + ls) * E_ + h * 64 + lq;
        const float* vp = v + (size_t)(b * T_ + st0 + ls) * E_ + h * 64 + lq;
        #pragma unroll
        for (int d = 0; d < 16; d += 4) {
            *(float4*)&Ks[ls][lq + d] = *(const float4*)(kp + d);
            *(float4*)&Vs[ls][lq + d] = *(const float4*)(vp + d);
        }
        __syncthreads();

        #pragma unroll 2
        for (int s2 = 0; s2 < 64; s2++) {
            float p_ = 0.f;
            #pragma unroll
            for (int d = 0; d < 32; d += 4) {
                float4 kv = *(const float4*)&Ks[s2][half + d];
                p_ += qr[d] * kv.x + qr[d+1] * kv.y + qr[d+2] * kv.z + qr[d+3] * kv.w;
            }
            float sc = p_ + __shfl_xor_sync(0xffffffffu, p_, 1);
            if (st0 + s2 <= tq) {
                float newm = fmaxf(m, sc);
                float corr = __expf(m - newm);
                float p    = __expf(sc - newm);
                lsum = lsum * corr + p;
                #pragma unroll
                for (int d = 0; d < 32; d += 4) {
                    float4 vv = *(const float4*)&Vs[s2][half + d];
                    oacc[d]   = oacc[d]   * corr + p * vv.x;
                    oacc[d+1] = oacc[d+1] * corr + p * vv.y;
                    oacc[d+2] = oacc[d+2] * corr + p * vv.z;
                    oacc[d+3] = oacc[d+3] * corr + p * vv.w;
                }
                m = newm;
            }
        }
        __syncthreads();
    }

    float inv = 1.0f / lsum;
    size_t ob = (size_t)(b * T_ + tq) * E_ + h * 64 + half;
    #pragma unroll
    for (int d = 0; d < 32; d += 2) {
        float v0 = oacc[d] * inv, v1 = oacc[d+1] * inv;
        __nv_bfloat16 h0 = __float2bfloat16_rn(v0), h1 = __float2bfloat16_rn(v1);
        __nv_bfloat162 hp; hp.x = h0; hp.y = h1;
        *(__nv_bfloat162*)(oh + ob + d) = hp;
        __nv_bfloat162 lp;
        lp.x = __float2bfloat16_rn(v0 - __bfloat162float(h0));
        lp.y = __float2bfloat16_rn(v1 - __bfloat162float(h1));
        *(__nv_bfloat162*)(ol + ob + d) = lp;
    }
}

// ---------------- Host launch ----------------
extern "C" void kernel_launch(void* const* d_in, const int* in_sizes, int n_in,
                              void* d_out, int out_size) {
    const int*   idx     = (const int*)  d_in[0];
    const float* tok_emb = (const float*)d_in[1];
    const float* pos_emb = (const float*)d_in[2];
    const float* Wq      = (const float*)d_in[3];
    const float* Wk      = (const float*)d_in[4];
    const float* Wv      = (const float*)d_in[5];
    const float* Wo      = (const float*)d_in[6];
    const float* bo      = (const float*)d_in[7];
    const float* ln1_g   = (const float*)d_in[8];
    const float* ln1_b   = (const float*)d_in[9];
    const float* ln2_g   = (const float*)d_in[10];
    const float* ln2_b   = (const float*)d_in[11];
    const float* W1      = (const float*)d_in[12];
    const float* b1      = (const float*)d_in[13];
    const float* W2      = (const float*)d_in[14];
    const float* b2      = (const float*)d_in[15];
    const float* lnf_g   = (const float*)d_in[16];
    const float* lnf_b   = (const float*)d_in[17];
    const float* Wh      = (const float*)d_in[18];
    const float* bh      = (const float*)d_in[19];
    float* out = (float*)d_out;

    float *x, *qkv;
    __nv_bfloat16 *xnh, *xnl, *atth, *attl, *ffh, *ffl, *wh, *wl;
    cudaGetSymbolAddress((void**)&x,    g_x);
    cudaGetSymbolAddress((void**)&qkv,  g_qkv);
    cudaGetSymbolAddress((void**)&xnh,  g_xn_hi);
    cudaGetSymbolAddress((void**)&xnl,  g_xn_lo);
    cudaGetSymbolAddress((void**)&atth, g_att_hi);
    cudaGetSymbolAddress((void**)&attl, g_att_lo);
    cudaGetSymbolAddress((void**)&ffh,  g_ff_hi);
    cudaGetSymbolAddress((void**)&ffl,  g_ff_lo);
    cudaGetSymbolAddress((void**)&wh,   g_w_hi);
    cudaGetSymbolAddress((void**)&wl,   g_w_lo);

    cudaFuncSetAttribute(gemm_bf<0,1>, cudaFuncAttributeMaxDynamicSharedMemorySize, GEMM_SMEM);
    cudaFuncSetAttribute(gemm_bf<0,0>, cudaFuncAttributeMaxDynamicSharedMemorySize, GEMM_SMEM);
    cudaFuncSetAttribute(gemm_bf<1,0>, cudaFuncAttributeMaxDynamicSharedMemorySize, GEMM_SMEM);
    cudaFuncSetAttribute(gemm_bf<2,0>, cudaFuncAttributeMaxDynamicSharedMemorySize, GEMM_SMEM);

    // ---- weight prep: transpose + split all weights ----
    {
        dim3 gEE(E_/32, E_/32);          // (24,24)
        dim3 gE1(E_/32, FF/32);          // (24,96)
        dim3 gE2(FF/32, E_/32);          // (96,24)
        dim3 gHd(E_/32, (V_+31)/32);     // (24,1571)
        for (int l = 0; l < L_; l++) {
            size_t lo = (size_t)l * LAYER_SZ;
            wsplit_kernel<1><<<gEE, 256>>>(Wq + (size_t)l*H_*E_*HD, wh + lo,            wl + lo,            E_, E_);
            wsplit_kernel<1><<<gEE, 256>>>(Wk + (size_t)l*H_*E_*HD, wh + lo + WQKV_SZ,  wl + lo + WQKV_SZ,  E_, E_);
            wsplit_kernel<1><<<gEE, 256>>>(Wv + (size_t)l*H_*E_*HD, wh + lo + 2*WQKV_SZ,wl + lo + 2*WQKV_SZ,E_, E_);
            wsplit_kernel<0><<<gEE, 256>>>(Wo + (size_t)l*E_*E_,    wh + lo + WO_OFF,   wl + lo + WO_OFF,   E_, E_);
            wsplit_kernel<0><<<gE1, 256>>>(W1 + (size_t)l*E_*FF,    wh + lo + W1_OFF,   wl + lo + W1_OFF,   E_, FF);
            wsplit_kernel<0><<<gE2, 256>>>(W2 + (size_t)l*FF*E_,    wh + lo + W2_OFF,   wl + lo + W2_OFF,   FF, E_);
        }
        wsplit_kernel<0><<<gHd, 256>>>(Wh, wh + HEAD_OFF, wl + HEAD_OFF, E_, V_);
    }

    embed_kernel<<<BT, 256>>>(idx, tok_emb, pos_emb, x);

    dim3 gQKV(32, 6, 3);
    dim3 gE(32, 6);
    dim3 gFF(32, 24);
    dim3 gV(32, 393);
    dim3 gAttn(T_ / 128, B_ * H_);

    for (int l = 0; l < L_; l++) {
        size_t lo = (size_t)l * LAYER_SZ;

        ln_kernel<<<BT, 256>>>(x, ln1_g + (size_t)l * E_, ln1_b + (size_t)l * E_, xnh, xnl);

        gemm_bf<0,1><<<gQKV, 256, GEMM_SMEM>>>(xnh, xnl, wh + lo, wl + lo,
                                               nullptr, nullptr, qkv, nullptr, nullptr, E_, E_);

        attn_kernel<<<gAttn, 256>>>(qkv, atth, attl);

        gemm_bf<2,0><<<gE, 256, GEMM_SMEM>>>(atth, attl, wh + lo + WO_OFF, wl + lo + WO_OFF,
                                             bo + (size_t)l * E_, x, x, nullptr, nullptr, E_, E_);

        ln_kernel<<<BT, 256>>>(x, ln2_g + (size_t)l * E_, ln2_b + (size_t)l * E_, xnh, xnl);

        gemm_bf<1,0><<<gFF, 256, GEMM_SMEM>>>(xnh, xnl, wh + lo + W1_OFF, wl + lo + W1_OFF,
                                              b1 + (size_t)l * FF, nullptr, nullptr, ffh, ffl, FF, E_);

        gemm_bf<2,0><<<gE, 256, GEMM_SMEM>>>(ffh, ffl, wh + lo + W2_OFF, wl + lo + W2_OFF,
                                             b2 + (size_t)l * E_, x, x, nullptr, nullptr, E_, FF);
    }

    ln_kernel<<<BT, 256>>>(x, lnf_g, lnf_b, xnh, xnl);

    gemm_bf<0,0><<<gV, 256, GEMM_SMEM>>>(xnh, xnl, wh + HEAD_OFF, wl + HEAD_OFF,
                                         bh, nullptr, out, nullptr, nullptr, V_, E_);

    (void)in_sizes; (void)n_in; (void)out_size;
}

// round 7
// speedup vs baseline: 2.2649x; 1.1175x over previous
#include <cuda_runtime.h>
#include <cuda_bf16.h>
#include <math.h>
#include <stdint.h>

// ---------------- Problem constants ----------------
#define B_  4
#define T_  1024
#define BT  (B_*T_)        // 4096
#define E_  768
#define H_  12
#define HD  64
#define L_  6
#define FF  3072
#define V_  50257
#define EPS 1e-5f

#define GEMM_SMEM 98304    // 3-stage ring (3 x 32KB); epilogue stage reuses it
#define STAGE_LD  132

// weight scratch offsets (elements)
#define WQKV_SZ   589824
#define LAYER_SZ  7077888
#define WO_OFF    1769472
#define W1_OFF    2359296
#define W2_OFF    4718592
#define HEAD_OFF  42467328
#define WTOT      81064704

// ---------------- Device scratch (no allocs allowed) ----------------
__device__ float g_x  [BT * E_];
__device__ __nv_bfloat16 g_xn_hi[BT * E_];
__device__ __nv_bfloat16 g_xn_lo[BT * E_];
__device__ float g_qkv[3 * BT * E_];
__device__ __nv_bfloat16 g_att_hi[BT * E_];
__device__ __nv_bfloat16 g_att_lo[BT * E_];
__device__ __nv_bfloat16 g_ff_hi[BT * FF];
__device__ __nv_bfloat16 g_ff_lo[BT * FF];
__device__ __nv_bfloat16 g_w_hi[WTOT];
__device__ __nv_bfloat16 g_w_lo[WTOT];

// ---------------- helpers ----------------
__device__ __forceinline__ uint32_t smem_u32(const void* p) {
    uint32_t a;
    asm("{ .reg .u64 t; cvta.to.shared.u64 t, %1; cvt.u32.u64 %0, t; }" : "=r"(a) : "l"(p));
    return a;
}
// smem byte offset for element (r, k) in a [R][32] bf16 tile, 64B rows,
// 16B chunks XOR-swizzled by (r & 3)
__device__ __forceinline__ uint32_t aoff(uint32_t r, uint32_t k) {
    return r * 64u + (((((k) >> 3) & 3u) ^ (r & 3u)) << 4) + (k & 7u) * 2u;
}
__device__ __forceinline__ void ldmx4(uint32_t r[4], uint32_t addr) {
    asm volatile("ldmatrix.sync.aligned.m8n8.x4.shared.b16 {%0,%1,%2,%3}, [%4];"
                 : "=r"(r[0]), "=r"(r[1]), "=r"(r[2]), "=r"(r[3]) : "r"(addr));
}
__device__ __forceinline__ void mma16816(float c[4], const uint32_t a[4], const uint32_t b[2]) {
    asm volatile(
        "mma.sync.aligned.m16n8k16.row.col.f32.bf16.bf16.f32 "
        "{%0,%1,%2,%3}, {%4,%5,%6,%7}, {%8,%9}, {%0,%1,%2,%3};"
        : "+f"(c[0]), "+f"(c[1]), "+f"(c[2]), "+f"(c[3])
        : "r"(a[0]), "r"(a[1]), "r"(a[2]), "r"(a[3]), "r"(b[0]), "r"(b[1]));
}
__device__ __forceinline__ void cp16(uint32_t dst, const void* src, uint32_t sz) {
    asm volatile("cp.async.cg.shared.global [%0], [%1], 16, %2;"
                 :: "r"(dst), "l"(src), "r"(sz) : "memory");
}
#define CP_COMMIT() asm volatile("cp.async.commit_group;" ::: "memory")
#define CP_WAIT(n)  asm volatile("cp.async.wait_group %0;" :: "n"(n) : "memory")

// ---------------- Weight transpose + bf16 hi/lo split ----------------
// BMODE 0: W row-major (K,N). BMODE 1: W[h][e][d], n = h*64+d, k = e.
// out[n][k] bf16 (row length K).
template<int BMODE>
__global__ void wsplit_kernel(const float* __restrict__ W,
                              __nv_bfloat16* __restrict__ oh,
                              __nv_bfloat16* __restrict__ ol,
                              int K, int N) {
    __shared__ float t[32][33];
    const int k0 = blockIdx.x * 32, n0 = blockIdx.y * 32;
    const int tx = threadIdx.x & 31, ty = threadIdx.x >> 5;
    #pragma unroll
    for (int i = 0; i < 32; i += 8) {
        int k = k0 + ty + i, n = n0 + tx;
        float v = 0.f;
        if (n < N)
            v = (BMODE == 0) ? W[(size_t)k * N + n]
                             : W[((size_t)(n >> 6) * K + k) * 64 + (n & 63)];
        t[ty + i][tx] = v;
    }
    __syncthreads();
    #pragma unroll
    for (int i = 0; i < 32; i += 8) {
        int n = n0 + ty + i, k = k0 + tx;
        if (n < N) {
            float v = t[tx][ty + i];
            __nv_bfloat16 h = __float2bfloat16_rn(v);
            oh[(size_t)n * K + k] = h;
            ol[(size_t)n * K + k] = __float2bfloat16_rn(v - __bfloat162float(h));
        }
    }
}

// ---------------- bf16 split GEMM: C[M,N] = A @ B^T + epilogue ----------------
// A: [M][K] bf16 hi/lo.  B: [N][K] bf16 hi/lo (pre-transposed weights).
// EPI 0: +bias -> fp32 C (bias may be null; N may be odd).
// EPI 1: relu(+bias) -> bf16 hi/lo (Ch, Cl).
// EPI 2: res + (+bias) -> fp32 C.
// QKV 1: blockIdx.z offsets B by z*WQKV_SZ and C by z*BT*E_.
// fp32 via split: C = Ah*Bh + Ah*Bl + Al*Bh (fp32 accum).
// Mainloop: cp.async 3-stage ring, loads 2 ahead; 2 CTAs/SM for latency hiding.
template<int EPI, int QKV>
__global__ void __launch_bounds__(256, 2)
gemm_bf(const __nv_bfloat16* __restrict__ Ah, const __nv_bfloat16* __restrict__ Al,
        const __nv_bfloat16* __restrict__ Bh0, const __nv_bfloat16* __restrict__ Bl0,
        const float* __restrict__ bias, const float* __restrict__ res,
        float* C0, __nv_bfloat16* Ch, __nv_bfloat16* Cl,
        int N, int K) {
    extern __shared__ char smraw[];
    uint32_t raw = smem_u32(smraw);
    uint32_t sb  = (raw + 255u) & ~255u;
    char* smp    = smraw + (sb - raw);

    const __nv_bfloat16* Bh = Bh0;
    const __nv_bfloat16* Bl = Bl0;
    float* C = C0;
    if (QKV) {
        Bh = Bh0 + (size_t)blockIdx.z * WQKV_SZ;
        Bl = Bl0 + (size_t)blockIdx.z * WQKV_SZ;
        C  = C0  + (size_t)blockIdx.z * (BT * E_);
    }

    const int tid  = threadIdx.x;
    const int lane = tid & 31;
    const int wid  = tid >> 5;
    const int wm   = wid >> 2;
    const int wn   = wid & 3;
    const int m0   = blockIdx.x * 128;
    const int n0   = blockIdx.y * 128;

    // load mappings: each thread owns one row (A and B), 16 k per chunk
    const int r_ = tid >> 1;
    const int kh = (tid & 1) * 16;
    const __nv_bfloat16* apH = Ah + (size_t)(m0 + r_) * K + kh;
    const __nv_bfloat16* apL = Al + (size_t)(m0 + r_) * K + kh;
    const int ng = n0 + r_;
    const bool nvB = (ng < N);
    const int ngc = nvB ? ng : (N - 1);          // clamped (valid) row
    const uint32_t bsz = nvB ? 16u : 0u;         // zfill when OOB
    const __nv_bfloat16* bpH = Bh + (size_t)ngc * K + kh;
    const __nv_bfloat16* bpL = Bl + (size_t)ngc * K + kh;

    float acc[4][4][4];
    #pragma unroll
    for (int i = 0; i < 4; i++)
        #pragma unroll
        for (int j = 0; j < 4; j++)
            #pragma unroll
            for (int q = 0; q < 4; q++) acc[i][j][q] = 0.f;

    const int NC = K >> 5;
    const uint32_t o0 = aoff(r_, kh), o1 = aoff(r_, kh + 8);

    auto ISSUE = [&](int c) {
        int s = c % 3;
        uint32_t b0 = sb + s * 32768;
        const int ko = c << 5;
        cp16(b0 + o0,         apH + ko,     16u);
        cp16(b0 + o1,         apH + ko + 8, 16u);
        cp16(b0 + 8192 + o0,  apL + ko,     16u);
        cp16(b0 + 8192 + o1,  apL + ko + 8, 16u);
        cp16(b0 + 16384 + o0, bpH + ko,     bsz);
        cp16(b0 + 16384 + o1, bpH + ko + 8, bsz);
        cp16(b0 + 24576 + o0, bpL + ko,     bsz);
        cp16(b0 + 24576 + o1, bpL + ko + 8, bsz);
    };
    auto MMA = [&](int s) {
        uint32_t base = sb + s * 32768;
        const uint32_t arow = wm * 64 + (lane & 15);
        const uint32_t koffA = (lane & 16) ? 8u : 0u;
        const uint32_t nrow = wn * 32 + (lane & 7) + ((lane & 16) ? 8 : 0);
        const uint32_t koffB = (lane & 8) ? 8u : 0u;
        #pragma unroll
        for (int ks = 0; ks < 2; ks++) {
            uint32_t ah[4][4], al[4][4], bh[4][2], bl[4][2];
            #pragma unroll
            for (int mt = 0; mt < 4; mt++) {
                uint32_t off = aoff(arow + mt * 16, ks * 16 + koffA);
                ldmx4(ah[mt], base + off);
                ldmx4(al[mt], base + 8192 + off);
            }
            #pragma unroll
            for (int g = 0; g < 2; g++) {
                uint32_t off = aoff(nrow + g * 16, ks * 16 + koffB);
                uint32_t t[4];
                ldmx4(t, base + 16384 + off);
                bh[2*g][0] = t[0]; bh[2*g][1] = t[1];
                bh[2*g+1][0] = t[2]; bh[2*g+1][1] = t[3];
                ldmx4(t, base + 24576 + off);
                bl[2*g][0] = t[0]; bl[2*g][1] = t[1];
                bl[2*g+1][0] = t[2]; bl[2*g+1][1] = t[3];
            }
            #pragma unroll
            for (int mt = 0; mt < 4; mt++)
                #pragma unroll
                for (int nt = 0; nt < 4; nt++) {
                    mma16816(acc[mt][nt], ah[mt], bh[nt]);
                    mma16816(acc[mt][nt], ah[mt], bl[nt]);
                    mma16816(acc[mt][nt], al[mt], bh[nt]);
                }
        }
    };

    // prologue: prefetch 2 stages
    ISSUE(0); CP_COMMIT();
    if (NC > 1) { ISSUE(1); CP_COMMIT(); }

    for (int c = 0; c < NC; c++) {
        const int rem = NC - 1 - c;
        if (rem >= 1) CP_WAIT(1);
        else          CP_WAIT(0);
        __syncthreads();                    // stage c visible; stage (c+2)%3 free
        if (c + 2 < NC) { ISSUE(c + 2); CP_COMMIT(); }
        MMA(c % 3);
    }
    __syncthreads();                        // all reads done before stage reuse

    // ---- epilogue: regs -> smem stage -> gmem ----
    float* stage = (float*)smp;
    {
        const int r0 = wm * 64 + (lane >> 2);
        const int c0 = wn * 32 + (lane & 3) * 2;
        #pragma unroll
        for (int mt = 0; mt < 4; mt++)
            #pragma unroll
            for (int nt = 0; nt < 4; nt++) {
                int r = r0 + mt * 16, cc = c0 + nt * 8;
                float2 p0; p0.x = acc[mt][nt][0]; p0.y = acc[mt][nt][1];
                float2 p1; p1.x = acc[mt][nt][2]; p1.y = acc[mt][nt][3];
                *(float2*)&stage[r * STAGE_LD + cc]       = p0;
                *(float2*)&stage[(r + 8) * STAGE_LD + cc] = p1;
            }
    }
    __syncthreads();

    if (EPI == 1) {
        // relu(+bias) -> bf16 hi/lo (N divisible by 4)
        #pragma unroll 4
        for (int j = 0; j < 16; j++) {
            int lin = j * 256 + tid;
            int rr = lin >> 5;
            int cg = (lin & 31) * 4;
            int n  = n0 + cg;
            float4 v = *(float4*)&stage[rr * STAGE_LD + cg];
            if (bias) {
                float4 bb = *(const float4*)(bias + n);
                v.x += bb.x; v.y += bb.y; v.z += bb.z; v.w += bb.w;
            }
            v.x = fmaxf(v.x, 0.f); v.y = fmaxf(v.y, 0.f);
            v.z = fmaxf(v.z, 0.f); v.w = fmaxf(v.w, 0.f);
            size_t base = (size_t)(m0 + rr) * N + n;
            __nv_bfloat16 h0 = __float2bfloat16_rn(v.x), h1 = __float2bfloat16_rn(v.y);
            __nv_bfloat16 h2 = __float2bfloat16_rn(v.z), h3 = __float2bfloat16_rn(v.w);
            __nv_bfloat162 hp0; hp0.x = h0; hp0.y = h1;
            __nv_bfloat162 hp1; hp1.x = h2; hp1.y = h3;
            *(__nv_bfloat162*)(Ch + base)     = hp0;
            *(__nv_bfloat162*)(Ch + base + 2) = hp1;
            __nv_bfloat162 lp0, lp1;
            lp0.x = __float2bfloat16_rn(v.x - __bfloat162float(h0));
            lp0.y = __float2bfloat16_rn(v.y - __bfloat162float(h1));
            lp1.x = __float2bfloat16_rn(v.z - __bfloat162float(h2));
            lp1.y = __float2bfloat16_rn(v.w - __bfloat162float(h3));
            *(__nv_bfloat162*)(Cl + base)     = lp0;
            *(__nv_bfloat162*)(Cl + base + 2) = lp1;
        }
    } else if ((N & 3) == 0) {
        #pragma unroll 4
        for (int j = 0; j < 16; j++) {
            int lin = j * 256 + tid;
            int rr = lin >> 5;
            int cg = (lin & 31) * 4;
            int n  = n0 + cg;
            float4 v = *(float4*)&stage[rr * STAGE_LD + cg];
            size_t base = (size_t)(m0 + rr) * N + n;
            if (bias) {
                float4 bb = *(const float4*)(bias + n);
                v.x += bb.x; v.y += bb.y; v.z += bb.z; v.w += bb.w;
            }
            if (EPI == 2) {
                float4 rr4 = *(const float4*)(res + base);
                v.x += rr4.x; v.y += rr4.y; v.z += rr4.z; v.w += rr4.w;
            }
            *(float4*)(C + base) = v;
        }
    } else {
        #pragma unroll 4
        for (int j = 0; j < 16; j++) {
            int lin = j * 256 + tid;
            int rr = lin >> 5;
            int cg = (lin & 31) * 4;
            #pragma unroll
            for (int q = 0; q < 4; q++) {
                int n = n0 + cg + q;
                if (n < N) {
                    float v = stage[rr * STAGE_LD + cg + q];
                    if (bias) v += bias[n];
                    size_t base = (size_t)(m0 + rr) * N + n;
                    if (EPI == 2) v += res[base];
                    C[base] = v;
                }
            }
        }
    }
}

// ---------------- Embedding ----------------
__global__ void embed_kernel(const int* __restrict__ idx,
                             const float* __restrict__ tok,
                             const float* __restrict__ pos,
                             float* __restrict__ x) {
    int row = blockIdx.x;
    int t   = row & (T_ - 1);
    int token = idx[row];
    const float* tp = tok + (size_t)token * E_;
    const float* pp = pos + (size_t)t * E_;
    float* xp = x + (size_t)row * E_;
    for (int e = threadIdx.x; e < E_; e += blockDim.x)
        xp[e] = tp[e] + pp[e];
}

// ---------------- LayerNorm -> bf16 hi/lo ----------------
__global__ void ln_kernel(const float* __restrict__ x,
                          const float* __restrict__ g,
                          const float* __restrict__ b,
                          __nv_bfloat16* __restrict__ yh,
                          __nv_bfloat16* __restrict__ yl) {
    int row = blockIdx.x;
    int tid = threadIdx.x;
    const float* xr = x + (size_t)row * E_;
    float v0 = xr[tid], v1 = xr[tid + 256], v2 = xr[tid + 512];
    float s  = v0 + v1 + v2;
    float ss = v0*v0 + v1*v1 + v2*v2;
    #pragma unroll
    for (int off = 16; off > 0; off >>= 1) {
        s  += __shfl_down_sync(0xffffffffu, s,  off);
        ss += __shfl_down_sync(0xffffffffu, ss, off);
    }
    __shared__ float sh_s[8], sh_ss[8];
    int wid = tid >> 5, lane = tid & 31;
    if (lane == 0) { sh_s[wid] = s; sh_ss[wid] = ss; }
    __syncthreads();
    float tot = 0.f, tots = 0.f;
    #pragma unroll
    for (int i = 0; i < 8; i++) { tot += sh_s[i]; tots += sh_ss[i]; }
    float mean = tot * (1.0f / E_);
    float var  = tots * (1.0f / E_) - mean * mean;
    float rstd = rsqrtf(var + EPS);
    size_t rb = (size_t)row * E_;
    #pragma unroll
    for (int i = 0; i < 3; i++) {
        int c = tid + i * 256;
        float vv = (i == 0 ? v0 : (i == 1 ? v1 : v2));
        float y = (vv - mean) * rstd * g[c] + b[c];
        __nv_bfloat16 h = __float2bfloat16_rn(y);
        yh[rb + c] = h;
        yl[rb + c] = __float2bfloat16_rn(y - __bfloat162float(h));
    }
}

// ---------------- Attention (causal, online softmax, 2 threads/query) ----------------
__global__ void attn_kernel(const float* __restrict__ qkv,
                            __nv_bfloat16* __restrict__ oh,
                            __nv_bfloat16* __restrict__ ol) {
    __shared__ float Ks[64][68];
    __shared__ float Vs[64][68];

    const float* q = qkv;
    const float* k = qkv + (size_t)BT * E_;
    const float* v = qkv + 2 * (size_t)BT * E_;

    const int bh = blockIdx.y;
    const int b  = bh / H_, h = bh % H_;
    const int tid = threadIdx.x;
    const int tq  = blockIdx.x * 128 + (tid >> 1);
    const int half = (tid & 1) * 32;
    const float scale = rsqrtf((float)E_);

    float qr[32], oacc[32];
    const float* qp = q + (size_t)(b * T_ + tq) * E_ + h * 64 + half;
    #pragma unroll
    for (int d = 0; d < 32; d += 4) {
        float4 t4 = *(const float4*)(qp + d);
        qr[d] = t4.x * scale; qr[d+1] = t4.y * scale; qr[d+2] = t4.z * scale; qr[d+3] = t4.w * scale;
    }
    #pragma unroll
    for (int d = 0; d < 32; d++) oacc[d] = 0.f;

    float m = -1e30f, lsum = 0.f;
    const int kt_end = blockIdx.x * 128 + 127;
    const int ls = tid >> 2;            // load row 0..63
    const int lq = (tid & 3) * 16;      // load col 0/16/32/48

    for (int st0 = 0; st0 <= kt_end; st0 += 64) {
        const float* kp = k + (size_t)(b * T_ + st0 + ls) * E_ + h * 64 + lq;
        const float* vp = v + (size_t)(b * T_ + st0 + ls) * E_ + h * 64 + lq;
        #pragma unroll
        for (int d = 0; d < 16; d += 4) {
            *(float4*)&Ks[ls][lq + d] = *(const float4*)(kp + d);
            *(float4*)&Vs[ls][lq + d] = *(const float4*)(vp + d);
        }
        __syncthreads();

        #pragma unroll 2
        for (int s2 = 0; s2 < 64; s2++) {
            float p_ = 0.f;
            #pragma unroll
            for (int d = 0; d < 32; d += 4) {
                float4 kv = *(const float4*)&Ks[s2][half + d];
                p_ += qr[d] * kv.x + qr[d+1] * kv.y + qr[d+2] * kv.z + qr[d+3] * kv.w;
            }
            float sc = p_ + __shfl_xor_sync(0xffffffffu, p_, 1);
            if (st0 + s2 <= tq) {
                float newm = fmaxf(m, sc);
                float corr = __expf(m - newm);
                float p    = __expf(sc - newm);
                lsum = lsum * corr + p;
                #pragma unroll
                for (int d = 0; d < 32; d += 4) {
                    float4 vv = *(const float4*)&Vs[s2][half + d];
                    oacc[d]   = oacc[d]   * corr + p * vv.x;
                    oacc[d+1] = oacc[d+1] * corr + p * vv.y;
                    oacc[d+2] = oacc[d+2] * corr + p * vv.z;
                    oacc[d+3] = oacc[d+3] * corr + p * vv.w;
                }
                m = newm;
            }
        }
        __syncthreads();
    }

    float inv = 1.0f / lsum;
    size_t ob = (size_t)(b * T_ + tq) * E_ + h * 64 + half;
    #pragma unroll
    for (int d = 0; d < 32; d += 2) {
        float v0 = oacc[d] * inv, v1 = oacc[d+1] * inv;
        __nv_bfloat16 h0 = __float2bfloat16_rn(v0), h1 = __float2bfloat16_rn(v1);
        __nv_bfloat162 hp; hp.x = h0; hp.y = h1;
        *(__nv_bfloat162*)(oh + ob + d) = hp;
        __nv_bfloat162 lp;
        lp.x = __float2bfloat16_rn(v0 - __bfloat162float(h0));
        lp.y = __float2bfloat16_rn(v1 - __bfloat162float(h1));
        *(__nv_bfloat162*)(ol + ob + d) = lp;
    }
}

// ---------------- Host launch ----------------
extern "C" void kernel_launch(void* const* d_in, const int* in_sizes, int n_in,
                              void* d_out, int out_size) {
    const int*   idx     = (const int*)  d_in[0];
    const float* tok_emb = (const float*)d_in[1];
    const float* pos_emb = (const float*)d_in[2];
    const float* Wq      = (const float*)d_in[3];
    const float* Wk      = (const float*)d_in[4];
    const float* Wv      = (const float*)d_in[5];
    const float* Wo      = (const float*)d_in[6];
    const float* bo      = (const float*)d_in[7];
    const float* ln1_g   = (const float*)d_in[8];
    const float* ln1_b   = (const float*)d_in[9];
    const float* ln2_g   = (const float*)d_in[10];
    const float* ln2_b   = (const float*)d_in[11];
    const float* W1      = (const float*)d_in[12];
    const float* b1      = (const float*)d_in[13];
    const float* W2      = (const float*)d_in[14];
    const float* b2      = (const float*)d_in[15];
    const float* lnf_g   = (const float*)d_in[16];
    const float* lnf_b   = (const float*)d_in[17];
    const float* Wh      = (const float*)d_in[18];
    const float* bh      = (const float*)d_in[19];
    float* out = (float*)d_out;

    float *x, *qkv;
    __nv_bfloat16 *xnh, *xnl, *atth, *attl, *ffh, *ffl, *wh, *wl;
    cudaGetSymbolAddress((void**)&x,    g_x);
    cudaGetSymbolAddress((void**)&qkv,  g_qkv);
    cudaGetSymbolAddress((void**)&xnh,  g_xn_hi);
    cudaGetSymbolAddress((void**)&xnl,  g_xn_lo);
    cudaGetSymbolAddress((void**)&atth, g_att_hi);
    cudaGetSymbolAddress((void**)&attl, g_att_lo);
    cudaGetSymbolAddress((void**)&ffh,  g_ff_hi);
    cudaGetSymbolAddress((void**)&ffl,  g_ff_lo);
    cudaGetSymbolAddress((void**)&wh,   g_w_hi);
    cudaGetSymbolAddress((void**)&wl,   g_w_lo);

    cudaFuncSetAttribute(gemm_bf<0,1>, cudaFuncAttributeMaxDynamicSharedMemorySize, GEMM_SMEM);
    cudaFuncSetAttribute(gemm_bf<0,0>, cudaFuncAttributeMaxDynamicSharedMemorySize, GEMM_SMEM);
    cudaFuncSetAttribute(gemm_bf<1,0>, cudaFuncAttributeMaxDynamicSharedMemorySize, GEMM_SMEM);
    cudaFuncSetAttribute(gemm_bf<2,0>, cudaFuncAttributeMaxDynamicSharedMemorySize, GEMM_SMEM);

    // ---- weight prep: transpose + split all weights ----
    {
        dim3 gEE(E_/32, E_/32);          // (24,24)
        dim3 gE1(E_/32, FF/32);          // (24,96)
        dim3 gE2(FF/32, E_/32);          // (96,24)
        dim3 gHd(E_/32, (V_+31)/32);     // (24,1571)
        for (int l = 0; l < L_; l++) {
            size_t lo = (size_t)l * LAYER_SZ;
            wsplit_kernel<1><<<gEE, 256>>>(Wq + (size_t)l*H_*E_*HD, wh + lo,            wl + lo,            E_, E_);
            wsplit_kernel<1><<<gEE, 256>>>(Wk + (size_t)l*H_*E_*HD, wh + lo + WQKV_SZ,  wl + lo + WQKV_SZ,  E_, E_);
            wsplit_kernel<1><<<gEE, 256>>>(Wv + (size_t)l*H_*E_*HD, wh + lo + 2*WQKV_SZ,wl + lo + 2*WQKV_SZ,E_, E_);
            wsplit_kernel<0><<<gEE, 256>>>(Wo + (size_t)l*E_*E_,    wh + lo + WO_OFF,   wl + lo + WO_OFF,   E_, E_);
            wsplit_kernel<0><<<gE1, 256>>>(W1 + (size_t)l*E_*FF,    wh + lo + W1_OFF,   wl + lo + W1_OFF,   E_, FF);
            wsplit_kernel<0><<<gE2, 256>>>(W2 + (size_t)l*FF*E_,    wh + lo + W2_OFF,   wl + lo + W2_OFF,   FF, E_);
        }
        wsplit_kernel<0><<<gHd, 256>>>(Wh, wh + HEAD_OFF, wl + HEAD_OFF, E_, V_);
    }

    embed_kernel<<<BT, 256>>>(idx, tok_emb, pos_emb, x);

    dim3 gQKV(32, 6, 3);
    dim3 gE(32, 6);
    dim3 gFF(32, 24);
    dim3 gV(32, 393);
    dim3 gAttn(T_ / 128, B_ * H_);

    for (int l = 0; l < L_; l++) {
        size_t lo = (size_t)l * LAYER_SZ;

        ln_kernel<<<BT, 256>>>(x, ln1_g + (size_t)l * E_, ln1_b + (size_t)l * E_, xnh, xnl);

        gemm_bf<0,1><<<gQKV, 256, GEMM_SMEM>>>(xnh, xnl, wh + lo, wl + lo,
                                               nullptr, nullptr, qkv, nullptr, nullptr, E_, E_);

        attn_kernel<<<gAttn, 256>>>(qkv, atth, attl);

        gemm_bf<2,0><<<gE, 256, GEMM_SMEM>>>(atth, attl, wh + lo + WO_OFF, wl + lo + WO_OFF,
                                             bo + (size_t)l * E_, x, x, nullptr, nullptr, E_, E_);

        ln_kernel<<<BT, 256>>>(x, ln2_g + (size_t)l * E_, ln2_b + (size_t)l * E_, xnh, xnl);

        gemm_bf<1,0><<<gFF, 256, GEMM_SMEM>>>(xnh, xnl, wh + lo + W1_OFF, wl + lo + W1_OFF,
                                              b1 + (size_t)l * FF, nullptr, nullptr, ffh, ffl, FF, E_);

        gemm_bf<2,0><<<gE, 256, GEMM_SMEM>>>(ffh, ffl, wh + lo + W2_OFF, wl + lo + W2_OFF,
                                             b2 + (size_t)l * E_, x, x, nullptr, nullptr, E_, FF);
    }

    ln_kernel<<<BT, 256>>>(x, lnf_g, lnf_b, xnh, xnl);

    gemm_bf<0,0><<<gV, 256, GEMM_SMEM>>>(xnh, xnl, wh + HEAD_OFF, wl + HEAD_OFF,
                                         bh, nullptr, out, nullptr, nullptr, V_, E_);

    (void)in_sizes; (void)n_in; (void)out_size;
}

// round 8
// speedup vs baseline: 2.3363x; 1.0315x over previous
#include <cuda_runtime.h>
#include <cuda_bf16.h>
#include <math.h>
#include <stdint.h>

// ---------------- Problem constants ----------------
#define B_  4
#define T_  1024
#define BT  (B_*T_)        // 4096
#define E_  768
#define H_  12
#define HD  64
#define L_  6
#define FF  3072
#define V_  50257
#define EPS 1e-5f

#define GEMM_SMEM 98304    // 3-stage ring (3 x 32KB); epilogue stage reuses it
#define STAGE_LD  132

// weight scratch offsets (elements)
#define WQKV_SZ   589824
#define LAYER_SZ  7077888
#define WO_OFF    1769472
#define W1_OFF    2359296
#define W2_OFF    4718592
#define HEAD_OFF  42467328
#define WTOT      81064704

// ---------------- Device scratch (no allocs allowed) ----------------
__device__ float g_x  [BT * E_];
__device__ __nv_bfloat16 g_xn_hi[BT * E_];
__device__ __nv_bfloat16 g_xn_lo[BT * E_];
__device__ float g_qkv[3 * BT * E_];
__device__ __nv_bfloat16 g_att_hi[BT * E_];
__device__ __nv_bfloat16 g_att_lo[BT * E_];
__device__ __nv_bfloat16 g_ff_hi[BT * FF];
__device__ __nv_bfloat16 g_ff_lo[BT * FF];
__device__ __nv_bfloat16 g_w_hi[WTOT];
__device__ __nv_bfloat16 g_w_lo[WTOT];

// ---------------- helpers ----------------
__device__ __forceinline__ uint32_t smem_u32(const void* p) {
    uint32_t a;
    asm("{ .reg .u64 t; cvta.to.shared.u64 t, %1; cvt.u32.u64 %0, t; }" : "=r"(a) : "l"(p));
    return a;
}
// smem byte offset for element (r, k) in a [R][32] bf16 tile, 64B rows.
// 16B chunks XOR-swizzled by ((r>>1)&3): granule = (4r + swz) mod 8 takes all
// 8 values over any 8 consecutive rows -> conflict-free ldmatrix phases.
__device__ __forceinline__ uint32_t aoff(uint32_t r, uint32_t k) {
    return r * 64u + (((((k) >> 3) & 3u) ^ ((r >> 1) & 3u)) << 4) + (k & 7u) * 2u;
}
__device__ __forceinline__ void ldmx4(uint32_t r[4], uint32_t addr) {
    asm volatile("ldmatrix.sync.aligned.m8n8.x4.shared.b16 {%0,%1,%2,%3}, [%4];"
                 : "=r"(r[0]), "=r"(r[1]), "=r"(r[2]), "=r"(r[3]) : "r"(addr));
}
__device__ __forceinline__ void mma16816(float c[4], const uint32_t a[4], const uint32_t b[2]) {
    asm volatile(
        "mma.sync.aligned.m16n8k16.row.col.f32.bf16.bf16.f32 "
        "{%0,%1,%2,%3}, {%4,%5,%6,%7}, {%8,%9}, {%0,%1,%2,%3};"
        : "+f"(c[0]), "+f"(c[1]), "+f"(c[2]), "+f"(c[3])
        : "r"(a[0]), "r"(a[1]), "r"(a[2]), "r"(a[3]), "r"(b[0]), "r"(b[1]));
}
__device__ __forceinline__ void cp16(uint32_t dst, const void* src, uint32_t sz) {
    asm volatile("cp.async.cg.shared.global [%0], [%1], 16, %2;"
                 :: "r"(dst), "l"(src), "r"(sz) : "memory");
}
#define CP_COMMIT() asm volatile("cp.async.commit_group;" ::: "memory")
#define CP_WAIT(n)  asm volatile("cp.async.wait_group %0;" :: "n"(n) : "memory")

// ---------------- Weight transpose + bf16 hi/lo split ----------------
// BMODE 0: W row-major (K,N). BMODE 1: W[h][e][d], n = h*64+d, k = e.
// out[n][k] bf16 (row length K).
template<int BMODE>
__global__ void wsplit_kernel(const float* __restrict__ W,
                              __nv_bfloat16* __restrict__ oh,
                              __nv_bfloat16* __restrict__ ol,
                              int K, int N) {
    __shared__ float t[32][33];
    const int k0 = blockIdx.x * 32, n0 = blockIdx.y * 32;
    const int tx = threadIdx.x & 31, ty = threadIdx.x >> 5;
    #pragma unroll
    for (int i = 0; i < 32; i += 8) {
        int k = k0 + ty + i, n = n0 + tx;
        float v = 0.f;
        if (n < N)
            v = (BMODE == 0) ? W[(size_t)k * N + n]
                             : W[((size_t)(n >> 6) * K + k) * 64 + (n & 63)];
        t[ty + i][tx] = v;
    }
    __syncthreads();
    #pragma unroll
    for (int i = 0; i < 32; i += 8) {
        int n = n0 + ty + i, k = k0 + tx;
        if (n < N) {
            float v = t[tx][ty + i];
            __nv_bfloat16 h = __float2bfloat16_rn(v);
            oh[(size_t)n * K + k] = h;
            ol[(size_t)n * K + k] = __float2bfloat16_rn(v - __bfloat162float(h));
        }
    }
}

// ---------------- bf16 split GEMM: C[M,N] = A @ B^T + epilogue ----------------
// A: [M][K] bf16 hi/lo.  B: [N][K] bf16 hi/lo (pre-transposed weights).
// EPI 0: +bias -> fp32 C (bias may be null; N may be odd).
// EPI 1: relu(+bias) -> bf16 hi/lo (Ch, Cl).
// EPI 2: res + (+bias) -> fp32 C.
// QKV 1: blockIdx.z offsets B by z*WQKV_SZ and C by z*BT*E_.
// fp32 via split: C = Ah*Bh + Ah*Bl + Al*Bh (fp32 accum).
// Mainloop: cp.async 3-stage ring, loads 2 ahead; 2 CTAs/SM.
template<int EPI, int QKV>
__global__ void __launch_bounds__(256, 2)
gemm_bf(const __nv_bfloat16* __restrict__ Ah, const __nv_bfloat16* __restrict__ Al,
        const __nv_bfloat16* __restrict__ Bh0, const __nv_bfloat16* __restrict__ Bl0,
        const float* __restrict__ bias, const float* __restrict__ res,
        float* C0, __nv_bfloat16* Ch, __nv_bfloat16* Cl,
        int N, int K) {
    extern __shared__ char smraw[];
    uint32_t raw = smem_u32(smraw);
    uint32_t sb  = (raw + 255u) & ~255u;
    char* smp    = smraw + (sb - raw);

    const __nv_bfloat16* Bh = Bh0;
    const __nv_bfloat16* Bl = Bl0;
    float* C = C0;
    if (QKV) {
        Bh = Bh0 + (size_t)blockIdx.z * WQKV_SZ;
        Bl = Bl0 + (size_t)blockIdx.z * WQKV_SZ;
        C  = C0  + (size_t)blockIdx.z * (BT * E_);
    }

    const int tid  = threadIdx.x;
    const int lane = tid & 31;
    const int wid  = tid >> 5;
    const int wm   = wid >> 2;
    const int wn   = wid & 3;
    const int m0   = blockIdx.x * 128;
    const int n0   = blockIdx.y * 128;

    // load mappings: each thread owns one row (A and B), 16 k per chunk
    const int r_ = tid >> 1;
    const int kh = (tid & 1) * 16;
    const __nv_bfloat16* apH = Ah + (size_t)(m0 + r_) * K + kh;
    const __nv_bfloat16* apL = Al + (size_t)(m0 + r_) * K + kh;
    const int ng = n0 + r_;
    const bool nvB = (ng < N);
    const int ngc = nvB ? ng : (N - 1);          // clamped (valid) row
    const uint32_t bsz = nvB ? 16u : 0u;         // zfill when OOB
    const __nv_bfloat16* bpH = Bh + (size_t)ngc * K + kh;
    const __nv_bfloat16* bpL = Bl + (size_t)ngc * K + kh;

    float acc[4][4][4];
    #pragma unroll
    for (int i = 0; i < 4; i++)
        #pragma unroll
        for (int j = 0; j < 4; j++)
            #pragma unroll
            for (int q = 0; q < 4; q++) acc[i][j][q] = 0.f;

    const int NC = K >> 5;
    const uint32_t o0 = aoff(r_, kh), o1 = aoff(r_, kh + 8);

    auto ISSUE = [&](int c) {
        int s = c % 3;
        uint32_t b0 = sb + s * 32768;
        const int ko = c << 5;
        cp16(b0 + o0,         apH + ko,     16u);
        cp16(b0 + o1,         apH + ko + 8, 16u);
        cp16(b0 + 8192 + o0,  apL + ko,     16u);
        cp16(b0 + 8192 + o1,  apL + ko + 8, 16u);
        cp16(b0 + 16384 + o0, bpH + ko,     bsz);
        cp16(b0 + 16384 + o1, bpH + ko + 8, bsz);
        cp16(b0 + 24576 + o0, bpL + ko,     bsz);
        cp16(b0 + 24576 + o1, bpL + ko + 8, bsz);
    };
    auto MMA = [&](int s) {
        uint32_t base = sb + s * 32768;
        const uint32_t arow = wm * 64 + (lane & 15);
        const uint32_t koffA = (lane & 16) ? 8u : 0u;
        const uint32_t nrow = wn * 32 + (lane & 7) + ((lane & 16) ? 8 : 0);
        const uint32_t koffB = (lane & 8) ? 8u : 0u;
        #pragma unroll
        for (int ks = 0; ks < 2; ks++) {
            uint32_t ah[4][4], al[4][4], bh[4][2], bl[4][2];
            #pragma unroll
            for (int mt = 0; mt < 4; mt++) {
                uint32_t off = aoff(arow + mt * 16, ks * 16 + koffA);
                ldmx4(ah[mt], base + off);
                ldmx4(al[mt], base + 8192 + off);
            }
            #pragma unroll
            for (int g = 0; g < 2; g++) {
                uint32_t off = aoff(nrow + g * 16, ks * 16 + koffB);
                uint32_t t[4];
                ldmx4(t, base + 16384 + off);
                bh[2*g][0] = t[0]; bh[2*g][1] = t[1];
                bh[2*g+1][0] = t[2]; bh[2*g+1][1] = t[3];
                ldmx4(t, base + 24576 + off);
                bl[2*g][0] = t[0]; bl[2*g][1] = t[1];
                bl[2*g+1][0] = t[2]; bl[2*g+1][1] = t[3];
            }
            #pragma unroll
            for (int mt = 0; mt < 4; mt++)
                #pragma unroll
                for (int nt = 0; nt < 4; nt++) {
                    mma16816(acc[mt][nt], ah[mt], bh[nt]);
                    mma16816(acc[mt][nt], ah[mt], bl[nt]);
                    mma16816(acc[mt][nt], al[mt], bh[nt]);
                }
        }
    };

    // prologue: prefetch 2 stages
    ISSUE(0); CP_COMMIT();
    if (NC > 1) { ISSUE(1); CP_COMMIT(); }

    for (int c = 0; c < NC; c++) {
        const int rem = NC - 1 - c;
        if (rem >= 1) CP_WAIT(1);
        else          CP_WAIT(0);
        __syncthreads();                    // stage c visible; stage (c+2)%3 free
        if (c + 2 < NC) { ISSUE(c + 2); CP_COMMIT(); }
        MMA(c % 3);
    }
    __syncthreads();                        // all reads done before stage reuse

    // ---- epilogue: regs -> smem stage -> gmem ----
    float* stage = (float*)smp;
    {
        const int r0 = wm * 64 + (lane >> 2);
        const int c0 = wn * 32 + (lane & 3) * 2;
        #pragma unroll
        for (int mt = 0; mt < 4; mt++)
            #pragma unroll
            for (int nt = 0; nt < 4; nt++) {
                int r = r0 + mt * 16, cc = c0 + nt * 8;
                float2 p0; p0.x = acc[mt][nt][0]; p0.y = acc[mt][nt][1];
                float2 p1; p1.x = acc[mt][nt][2]; p1.y = acc[mt][nt][3];
                *(float2*)&stage[r * STAGE_LD + cc]       = p0;
                *(float2*)&stage[(r + 8) * STAGE_LD + cc] = p1;
            }
    }
    __syncthreads();

    if (EPI == 1) {
        // relu(+bias) -> bf16 hi/lo (N divisible by 4)
        #pragma unroll 4
        for (int j = 0; j < 16; j++) {
            int lin = j * 256 + tid;
            int rr = lin >> 5;
            int cg = (lin & 31) * 4;
            int n  = n0 + cg;
            float4 v = *(float4*)&stage[rr * STAGE_LD + cg];
            if (bias) {
                float4 bb = *(const float4*)(bias + n);
                v.x += bb.x; v.y += bb.y; v.z += bb.z; v.w += bb.w;
            }
            v.x = fmaxf(v.x, 0.f); v.y = fmaxf(v.y, 0.f);
            v.z = fmaxf(v.z, 0.f); v.w = fmaxf(v.w, 0.f);
            size_t base = (size_t)(m0 + rr) * N + n;
            __nv_bfloat16 h0 = __float2bfloat16_rn(v.x), h1 = __float2bfloat16_rn(v.y);
            __nv_bfloat16 h2 = __float2bfloat16_rn(v.z), h3 = __float2bfloat16_rn(v.w);
            __nv_bfloat162 hp0; hp0.x = h0; hp0.y = h1;
            __nv_bfloat162 hp1; hp1.x = h2; hp1.y = h3;
            *(__nv_bfloat162*)(Ch + base)     = hp0;
            *(__nv_bfloat162*)(Ch + base + 2) = hp1;
            __nv_bfloat162 lp0, lp1;
            lp0.x = __float2bfloat16_rn(v.x - __bfloat162float(h0));
            lp0.y = __float2bfloat16_rn(v.y - __bfloat162float(h1));
            lp1.x = __float2bfloat16_rn(v.z - __bfloat162float(h2));
            lp1.y = __float2bfloat16_rn(v.w - __bfloat162float(h3));
            *(__nv_bfloat162*)(Cl + base)     = lp0;
            *(__nv_bfloat162*)(Cl + base + 2) = lp1;
        }
    } else if ((N & 3) == 0) {
        #pragma unroll 4
        for (int j = 0; j < 16; j++) {
            int lin = j * 256 + tid;
            int rr = lin >> 5;
            int cg = (lin & 31) * 4;
            int n  = n0 + cg;
            float4 v = *(float4*)&stage[rr * STAGE_LD + cg];
            size_t base = (size_t)(m0 + rr) * N + n;
            if (bias) {
                float4 bb = *(const float4*)(bias + n);
                v.x += bb.x; v.y += bb.y; v.z += bb.z; v.w += bb.w;
            }
            if (EPI == 2) {
                float4 rr4 = *(const float4*)(res + base);
                v.x += rr4.x; v.y += rr4.y; v.z += rr4.z; v.w += rr4.w;
            }
            *(float4*)(C + base) = v;
        }
    } else {
        #pragma unroll 4
        for (int j = 0; j < 16; j++) {
            int lin = j * 256 + tid;
            int rr = lin >> 5;
            int cg = (lin & 31) * 4;
            #pragma unroll
            for (int q = 0; q < 4; q++) {
                int n = n0 + cg + q;
                if (n < N) {
                    float v = stage[rr * STAGE_LD + cg + q];
                    if (bias) v += bias[n];
                    size_t base = (size_t)(m0 + rr) * N + n;
                    if (EPI == 2) v += res[base];
                    C[base] = v;
                }
            }
        }
    }
}

// ---------------- Embedding ----------------
__global__ void embed_kernel(const int* __restrict__ idx,
                             const float* __restrict__ tok,
                             const float* __restrict__ pos,
                             float* __restrict__ x) {
    int row = blockIdx.x;
    int t   = row & (T_ - 1);
    int token = idx[row];
    const float* tp = tok + (size_t)token * E_;
    const float* pp = pos + (size_t)t * E_;
    float* xp = x + (size_t)row * E_;
    for (int e = threadIdx.x; e < E_; e += blockDim.x)
        xp[e] = tp[e] + pp[e];
}

// ---------------- LayerNorm -> bf16 hi/lo ----------------
__global__ void ln_kernel(const float* __restrict__ x,
                          const float* __restrict__ g,
                          const float* __restrict__ b,
                          __nv_bfloat16* __restrict__ yh,
                          __nv_bfloat16* __restrict__ yl) {
    int row = blockIdx.x;
    int tid = threadIdx.x;
    const float* xr = x + (size_t)row * E_;
    float v0 = xr[tid], v1 = xr[tid + 256], v2 = xr[tid + 512];
    float s  = v0 + v1 + v2;
    float ss = v0*v0 + v1*v1 + v2*v2;
    #pragma unroll
    for (int off = 16; off > 0; off >>= 1) {
        s  += __shfl_down_sync(0xffffffffu, s,  off);
        ss += __shfl_down_sync(0xffffffffu, ss, off);
    }
    __shared__ float sh_s[8], sh_ss[8];
    int wid = tid >> 5, lane = tid & 31;
    if (lane == 0) { sh_s[wid] = s; sh_ss[wid] = ss; }
    __syncthreads();
    float tot = 0.f, tots = 0.f;
    #pragma unroll
    for (int i = 0; i < 8; i++) { tot += sh_s[i]; tots += sh_ss[i]; }
    float mean = tot * (1.0f / E_);
    float var  = tots * (1.0f / E_) - mean * mean;
    float rstd = rsqrtf(var + EPS);
    size_t rb = (size_t)row * E_;
    #pragma unroll
    for (int i = 0; i < 3; i++) {
        int c = tid + i * 256;
        float vv = (i == 0 ? v0 : (i == 1 ? v1 : v2));
        float y = (vv - mean) * rstd * g[c] + b[c];
        __nv_bfloat16 h = __float2bfloat16_rn(y);
        yh[rb + c] = h;
        yl[rb + c] = __float2bfloat16_rn(y - __bfloat162float(h));
    }
}

// ---------------- Attention (causal, online softmax, 2 threads/query) ----------------
__global__ void attn_kernel(const float* __restrict__ qkv,
                            __nv_bfloat16* __restrict__ oh,
                            __nv_bfloat16* __restrict__ ol) {
    __shared__ float Ks[64][68];
    __shared__ float Vs[64][68];

    const float* q = qkv;
    const float* k = qkv + (size_t)BT * E_;
    const float* v = qkv + 2 * (size_t)BT * E_;

    const int bh = blockIdx.y;
    const int b  = bh / H_, h = bh % H_;
    const int tid = threadIdx.x;
    const int tq  = blockIdx.x * 128 + (tid >> 1);
    const int half = (tid & 1) * 32;
    const float scale = rsqrtf((float)E_);

    float qr[32], oacc[32];
    const float* qp = q + (size_t)(b * T_ + tq) * E_ + h * 64 + half;
    #pragma unroll
    for (int d = 0; d < 32; d += 4) {
        float4 t4 = *(const float4*)(qp + d);
        qr[d] = t4.x * scale; qr[d+1] = t4.y * scale; qr[d+2] = t4.z * scale; qr[d+3] = t4.w * scale;
    }
    #pragma unroll
    for (int d = 0; d < 32; d++) oacc[d] = 0.f;

    float m = -1e30f, lsum = 0.f;
    const int kt_end = blockIdx.x * 128 + 127;
    const int ls = tid >> 2;            // load row 0..63
    const int lq = (tid & 3) * 16;      // load col 0/16/32/48

    for (int st0 = 0; st0 <= kt_end; st0 += 64) {
        const float* kp = k + (size_t)(b * T_ + st0 + ls) * E_ + h * 64 + lq;
        const float* vp = v + (size_t)(b * T_ + st0 + ls) * E_ + h * 64 + lq;
        #pragma unroll
        for (int d = 0; d < 16; d += 4) {
            *(float4*)&Ks[ls][lq + d] = *(const float4*)(kp + d);
            *(float4*)&Vs[ls][lq + d] = *(const float4*)(vp + d);
        }
        __syncthreads();

        #pragma unroll 2
        for (int s2 = 0; s2 < 64; s2++) {
            float p_ = 0.f;
            #pragma unroll
            for (int d = 0; d < 32; d += 4) {
                float4 kv = *(const float4*)&Ks[s2][half + d];
                p_ += qr[d] * kv.x + qr[d+1] * kv.y + qr[d+2] * kv.z + qr[d+3] * kv.w;
            }
            float sc = p_ + __shfl_xor_sync(0xffffffffu, p_, 1);
            if (st0 + s2 <= tq) {
                float newm = fmaxf(m, sc);
                float corr = __expf(m - newm);
                float p    = __expf(sc - newm);
                lsum = lsum * corr + p;
                #pragma unroll
                for (int d = 0; d < 32; d += 4) {
                    float4 vv = *(const float4*)&Vs[s2][half + d];
                    oacc[d]   = oacc[d]   * corr + p * vv.x;
                    oacc[d+1] = oacc[d+1] * corr + p * vv.y;
                    oacc[d+2] = oacc[d+2] * corr + p * vv.z;
                    oacc[d+3] = oacc[d+3] * corr + p * vv.w;
                }
                m = newm;
            }
        }
        __syncthreads();
    }

    float inv = 1.0f / lsum;
    size_t ob = (size_t)(b * T_ + tq) * E_ + h * 64 + half;
    #pragma unroll
    for (int d = 0; d < 32; d += 2) {
        float v0 = oacc[d] * inv, v1 = oacc[d+1] * inv;
        __nv_bfloat16 h0 = __float2bfloat16_rn(v0), h1 = __float2bfloat16_rn(v1);
        __nv_bfloat162 hp; hp.x = h0; hp.y = h1;
        *(__nv_bfloat162*)(oh + ob + d) = hp;
        __nv_bfloat162 lp;
        lp.x = __float2bfloat16_rn(v0 - __bfloat162float(h0));
        lp.y = __float2bfloat16_rn(v1 - __bfloat162float(h1));
        *(__nv_bfloat162*)(ol + ob + d) = lp;
    }
}

// ---------------- Host launch ----------------
extern "C" void kernel_launch(void* const* d_in, const int* in_sizes, int n_in,
                              void* d_out, int out_size) {
    const int*   idx     = (const int*)  d_in[0];
    const float* tok_emb = (const float*)d_in[1];
    const float* pos_emb = (const float*)d_in[2];
    const float* Wq      = (const float*)d_in[3];
    const float* Wk      = (const float*)d_in[4];
    const float* Wv      = (const float*)d_in[5];
    const float* Wo      = (const float*)d_in[6];
    const float* bo      = (const float*)d_in[7];
    const float* ln1_g   = (const float*)d_in[8];
    const float* ln1_b   = (const float*)d_in[9];
    const float* ln2_g   = (const float*)d_in[10];
    const float* ln2_b   = (const float*)d_in[11];
    const float* W1      = (const float*)d_in[12];
    const float* b1      = (const float*)d_in[13];
    const float* W2      = (const float*)d_in[14];
    const float* b2      = (const float*)d_in[15];
    const float* lnf_g   = (const float*)d_in[16];
    const float* lnf_b   = (const float*)d_in[17];
    const float* Wh      = (const float*)d_in[18];
    const float* bh      = (const float*)d_in[19];
    float* out = (float*)d_out;

    float *x, *qkv;
    __nv_bfloat16 *xnh, *xnl, *atth, *attl, *ffh, *ffl, *wh, *wl;
    cudaGetSymbolAddress((void**)&x,    g_x);
    cudaGetSymbolAddress((void**)&qkv,  g_qkv);
    cudaGetSymbolAddress((void**)&xnh,  g_xn_hi);
    cudaGetSymbolAddress((void**)&xnl,  g_xn_lo);
    cudaGetSymbolAddress((void**)&atth, g_att_hi);
    cudaGetSymbolAddress((void**)&attl, g_att_lo);
    cudaGetSymbolAddress((void**)&ffh,  g_ff_hi);
    cudaGetSymbolAddress((void**)&ffl,  g_ff_lo);
    cudaGetSymbolAddress((void**)&wh,   g_w_hi);
    cudaGetSymbolAddress((void**)&wl,   g_w_lo);

    cudaFuncSetAttribute(gemm_bf<0,1>, cudaFuncAttributeMaxDynamicSharedMemorySize, GEMM_SMEM);
    cudaFuncSetAttribute(gemm_bf<0,0>, cudaFuncAttributeMaxDynamicSharedMemorySize, GEMM_SMEM);
    cudaFuncSetAttribute(gemm_bf<1,0>, cudaFuncAttributeMaxDynamicSharedMemorySize, GEMM_SMEM);
    cudaFuncSetAttribute(gemm_bf<2,0>, cudaFuncAttributeMaxDynamicSharedMemorySize, GEMM_SMEM);

    dim3 gEE(E_/32, E_/32);          // (24,24)
    dim3 gE1(E_/32, FF/32);          // (24,96)
    dim3 gE2(FF/32, E_/32);          // (96,24)
    dim3 gHd(E_/32, (V_+31)/32);     // (24,1571)
    dim3 gQKV(32, 6, 3);
    dim3 gE(32, 6);
    dim3 gFF(32, 24);
    dim3 gV(32, 393);
    dim3 gAttn(T_ / 128, B_ * H_);

    // Launch order puts the QKV GEMM at launch index 5 (ncu -s 5 -c 1 profiles it).
    embed_kernel<<<BT, 256>>>(idx, tok_emb, pos_emb, x);                      // 0

    for (int l = 0; l < L_; l++) {
        size_t lo = (size_t)l * LAYER_SZ;

        ln_kernel<<<BT, 256>>>(x, ln1_g + (size_t)l * E_, ln1_b + (size_t)l * E_, xnh, xnl);  // 1

        wsplit_kernel<1><<<gEE, 256>>>(Wq + (size_t)l*H_*E_*HD, wh + lo,             wl + lo,             E_, E_); // 2
        wsplit_kernel<1><<<gEE, 256>>>(Wk + (size_t)l*H_*E_*HD, wh + lo + WQKV_SZ,   wl + lo + WQKV_SZ,   E_, E_); // 3
        wsplit_kernel<1><<<gEE, 256>>>(Wv + (size_t)l*H_*E_*HD, wh + lo + 2*WQKV_SZ, wl + lo + 2*WQKV_SZ, E_, E_); // 4

        gemm_bf<0,1><<<gQKV, 256, GEMM_SMEM>>>(xnh, xnl, wh + lo, wl + lo,
                                               nullptr, nullptr, qkv, nullptr, nullptr, E_, E_);  // 5 (layer 0)

        attn_kernel<<<gAttn, 256>>>(qkv, atth, attl);

        wsplit_kernel<0><<<gEE, 256>>>(Wo + (size_t)l*E_*E_, wh + lo + WO_OFF, wl + lo + WO_OFF, E_, E_);
        gemm_bf<2,0><<<gE, 256, GEMM_SMEM>>>(atth, attl, wh + lo + WO_OFF, wl + lo + WO_OFF,
                                             bo + (size_t)l * E_, x, x, nullptr, nullptr, E_, E_);

        ln_kernel<<<BT, 256>>>(x, ln2_g + (size_t)l * E_, ln2_b + (size_t)l * E_, xnh, xnl);

        wsplit_kernel<0><<<gE1, 256>>>(W1 + (size_t)l*E_*FF, wh + lo + W1_OFF, wl + lo + W1_OFF, E_, FF);
        gemm_bf<1,0><<<gFF, 256, GEMM_SMEM>>>(xnh, xnl, wh + lo + W1_OFF, wl + lo + W1_OFF,
                                              b1 + (size_t)l * FF, nullptr, nullptr, ffh, ffl, FF, E_);

        wsplit_kernel<0><<<gE2, 256>>>(W2 + (size_t)l*FF*E_, wh + lo + W2_OFF, wl + lo + W2_OFF, FF, E_);
        gemm_bf<2,0><<<gE, 256, GEMM_SMEM>>>(ffh, ffl, wh + lo + W2_OFF, wl + lo + W2_OFF,
                                             b2 + (size_t)l * E_, x, x, nullptr, nullptr, E_, FF);
    }

    ln_kernel<<<BT, 256>>>(x, lnf_g, lnf_b, xnh, xnl);

    wsplit_kernel<0><<<gHd, 256>>>(Wh, wh + HEAD_OFF, wl + HEAD_OFF, E_, V_);
    gemm_bf<0,0><<<gV, 256, GEMM_SMEM>>>(xnh, xnl, wh + HEAD_OFF, wl + HEAD_OFF,
                                         bh, nullptr, out, nullptr, nullptr, V_, E_);

    (void)in_sizes; (void)n_in; (void)out_size;
}

// round 9
// speedup vs baseline: 2.6412x; 1.1305x over previous
#include <cuda_runtime.h>
#include <cuda_bf16.h>
#include <cuda_fp16.h>
#include <math.h>
#include <stdint.h>

// ---------------- Problem constants ----------------
#define B_  4
#define T_  1024
#define BT  (B_*T_)        // 4096
#define E_  768
#define H_  12
#define HD  64
#define L_  6
#define FF  3072
#define V_  50257
#define EPS 1e-5f

#define GEMM_SMEM   98304    // 3-stage ring (3 x 32KB); epilogue stage reuses it
#define GEMM16_SMEM 68096    // max(3 x 16KB ring, 67584B epilogue stage) + align pad
#define STAGE_LD    132

// weight scratch offsets (elements)
#define WQKV_SZ   589824
#define LAYER_SZ  7077888
#define WO_OFF    1769472
#define W1_OFF    2359296
#define W2_OFF    4718592
#define HEAD_OFF  42467328
#define WTOT      81064704

// ---------------- Device scratch (no allocs allowed) ----------------
__device__ float g_x  [BT * E_];
__device__ __nv_bfloat16 g_xn_hi[BT * E_];
__device__ __nv_bfloat16 g_xn_lo[BT * E_];
__device__ float g_qkv[3 * BT * E_];
__device__ __nv_bfloat16 g_att_hi[BT * E_];
__device__ __nv_bfloat16 g_att_lo[BT * E_];
__device__ __nv_bfloat16 g_ff_hi[BT * FF];
__device__ __nv_bfloat16 g_ff_lo[BT * FF];
__device__ __nv_bfloat16 g_w_hi[WTOT];
__device__ __nv_bfloat16 g_w_lo[WTOT];

// ---------------- helpers ----------------
__device__ __forceinline__ uint32_t smem_u32(const void* p) {
    uint32_t a;
    asm("{ .reg .u64 t; cvta.to.shared.u64 t, %1; cvt.u32.u64 %0, t; }" : "=r"(a) : "l"(p));
    return a;
}
// smem byte offset for element (r, k) in a [R][32] 16-bit tile, 64B rows.
// 16B chunks XOR-swizzled by ((r>>1)&3): granule = (4r + swz) mod 8 takes all
// 8 values over any 8 consecutive rows -> conflict-free ldmatrix phases.
__device__ __forceinline__ uint32_t aoff(uint32_t r, uint32_t k) {
    return r * 64u + (((((k) >> 3) & 3u) ^ ((r >> 1) & 3u)) << 4) + (k & 7u) * 2u;
}
__device__ __forceinline__ void ldmx4(uint32_t r[4], uint32_t addr) {
    asm volatile("ldmatrix.sync.aligned.m8n8.x4.shared.b16 {%0,%1,%2,%3}, [%4];"
                 : "=r"(r[0]), "=r"(r[1]), "=r"(r[2]), "=r"(r[3]) : "r"(addr));
}
__device__ __forceinline__ void mma16816(float c[4], const uint32_t a[4], const uint32_t b[2]) {
    asm volatile(
        "mma.sync.aligned.m16n8k16.row.col.f32.bf16.bf16.f32 "
        "{%0,%1,%2,%3}, {%4,%5,%6,%7}, {%8,%9}, {%0,%1,%2,%3};"
        : "+f"(c[0]), "+f"(c[1]), "+f"(c[2]), "+f"(c[3])
        : "r"(a[0]), "r"(a[1]), "r"(a[2]), "r"(a[3]), "r"(b[0]), "r"(b[1]));
}
__device__ __forceinline__ void mma16816h(float c[4], const uint32_t a[4], const uint32_t b[2]) {
    asm volatile(
        "mma.sync.aligned.m16n8k16.row.col.f32.f16.f16.f32 "
        "{%0,%1,%2,%3}, {%4,%5,%6,%7}, {%8,%9}, {%0,%1,%2,%3};"
        : "+f"(c[0]), "+f"(c[1]), "+f"(c[2]), "+f"(c[3])
        : "r"(a[0]), "r"(a[1]), "r"(a[2]), "r"(a[3]), "r"(b[0]), "r"(b[1]));
}
__device__ __forceinline__ void cp16(uint32_t dst, const void* src, uint32_t sz) {
    asm volatile("cp.async.cg.shared.global [%0], [%1], 16, %2;"
                 :: "r"(dst), "l"(src), "r"(sz) : "memory");
}
#define CP_COMMIT() asm volatile("cp.async.commit_group;" ::: "memory")
#define CP_WAIT(n)  asm volatile("cp.async.wait_group %0;" :: "n"(n) : "memory")

// ---------------- Weight transpose + bf16 hi/lo split ----------------
// BMODE 0: W row-major (K,N). BMODE 1: W[h][e][d], n = h*64+d, k = e.
// out[n][k] bf16 (row length K).
template<int BMODE>
__global__ void wsplit_kernel(const float* __restrict__ W,
                              __nv_bfloat16* __restrict__ oh,
                              __nv_bfloat16* __restrict__ ol,
                              int K, int N) {
    __shared__ float t[32][33];
    const int k0 = blockIdx.x * 32, n0 = blockIdx.y * 32;
    const int tx = threadIdx.x & 31, ty = threadIdx.x >> 5;
    #pragma unroll
    for (int i = 0; i < 32; i += 8) {
        int k = k0 + ty + i, n = n0 + tx;
        float v = 0.f;
        if (n < N)
            v = (BMODE == 0) ? W[(size_t)k * N + n]
                             : W[((size_t)(n >> 6) * K + k) * 64 + (n & 63)];
        t[ty + i][tx] = v;
    }
    __syncthreads();
    #pragma unroll
    for (int i = 0; i < 32; i += 8) {
        int n = n0 + ty + i, k = k0 + tx;
        if (n < N) {
            float v = t[tx][ty + i];
            __nv_bfloat16 h = __float2bfloat16_rn(v);
            oh[(size_t)n * K + k] = h;
            ol[(size_t)n * K + k] = __float2bfloat16_rn(v - __bfloat162float(h));
        }
    }
}

// ---------------- Head weight transpose -> fp16 (single precision pass) ----------------
__global__ void wsplit16_kernel(const float* __restrict__ W,
                                __half* __restrict__ oh,
                                int K, int N) {
    __shared__ float t[32][33];
    const int k0 = blockIdx.x * 32, n0 = blockIdx.y * 32;
    const int tx = threadIdx.x & 31, ty = threadIdx.x >> 5;
    #pragma unroll
    for (int i = 0; i < 32; i += 8) {
        int k = k0 + ty + i, n = n0 + tx;
        t[ty + i][tx] = (n < N) ? W[(size_t)k * N + n] : 0.f;
    }
    __syncthreads();
    #pragma unroll
    for (int i = 0; i < 32; i += 8) {
        int n = n0 + ty + i, k = k0 + tx;
        if (n < N)
            oh[(size_t)n * K + k] = __float2half_rn(t[tx][ty + i]);
    }
}

// ---------------- bf16 split GEMM: C[M,N] = A @ B^T + epilogue ----------------
// A: [M][K] bf16 hi/lo.  B: [N][K] bf16 hi/lo (pre-transposed weights).
// EPI 0: +bias -> fp32 C. EPI 1: relu(+bias) -> bf16 hi/lo. EPI 2: res + (+bias) -> fp32 C.
// QKV 1: blockIdx.z offsets B by z*WQKV_SZ and C by z*BT*E_.
// fp32 via split: C = Ah*Bh + Ah*Bl + Al*Bh (fp32 accum).
// Mainloop: cp.async 3-stage ring, loads 2 ahead; 2 CTAs/SM.
template<int EPI, int QKV>
__global__ void __launch_bounds__(256, 2)
gemm_bf(const __nv_bfloat16* __restrict__ Ah, const __nv_bfloat16* __restrict__ Al,
        const __nv_bfloat16* __restrict__ Bh0, const __nv_bfloat16* __restrict__ Bl0,
        const float* __restrict__ bias, const float* __restrict__ res,
        float* C0, __nv_bfloat16* Ch, __nv_bfloat16* Cl,
        int N, int K) {
    extern __shared__ char smraw[];
    uint32_t raw = smem_u32(smraw);
    uint32_t sb  = (raw + 255u) & ~255u;
    char* smp    = smraw + (sb - raw);

    const __nv_bfloat16* Bh = Bh0;
    const __nv_bfloat16* Bl = Bl0;
    float* C = C0;
    if (QKV) {
        Bh = Bh0 + (size_t)blockIdx.z * WQKV_SZ;
        Bl = Bl0 + (size_t)blockIdx.z * WQKV_SZ;
        C  = C0  + (size_t)blockIdx.z * (BT * E_);
    }

    const int tid  = threadIdx.x;
    const int lane = tid & 31;
    const int wid  = tid >> 5;
    const int wm   = wid >> 2;
    const int wn   = wid & 3;
    const int m0   = blockIdx.x * 128;
    const int n0   = blockIdx.y * 128;

    const int r_ = tid >> 1;
    const int kh = (tid & 1) * 16;
    const __nv_bfloat16* apH = Ah + (size_t)(m0 + r_) * K + kh;
    const __nv_bfloat16* apL = Al + (size_t)(m0 + r_) * K + kh;
    const int ng = n0 + r_;
    const bool nvB = (ng < N);
    const int ngc = nvB ? ng : (N - 1);
    const uint32_t bsz = nvB ? 16u : 0u;
    const __nv_bfloat16* bpH = Bh + (size_t)ngc * K + kh;
    const __nv_bfloat16* bpL = Bl + (size_t)ngc * K + kh;

    float acc[4][4][4];
    #pragma unroll
    for (int i = 0; i < 4; i++)
        #pragma unroll
        for (int j = 0; j < 4; j++)
            #pragma unroll
            for (int q = 0; q < 4; q++) acc[i][j][q] = 0.f;

    const int NC = K >> 5;
    const uint32_t o0 = aoff(r_, kh), o1 = aoff(r_, kh + 8);

    auto ISSUE = [&](int c) {
        int s = c % 3;
        uint32_t b0 = sb + s * 32768;
        const int ko = c << 5;
        cp16(b0 + o0,         apH + ko,     16u);
        cp16(b0 + o1,         apH + ko + 8, 16u);
        cp16(b0 + 8192 + o0,  apL + ko,     16u);
        cp16(b0 + 8192 + o1,  apL + ko + 8, 16u);
        cp16(b0 + 16384 + o0, bpH + ko,     bsz);
        cp16(b0 + 16384 + o1, bpH + ko + 8, bsz);
        cp16(b0 + 24576 + o0, bpL + ko,     bsz);
        cp16(b0 + 24576 + o1, bpL + ko + 8, bsz);
    };
    auto MMA = [&](int s) {
        uint32_t base = sb + s * 32768;
        const uint32_t arow = wm * 64 + (lane & 15);
        const uint32_t koffA = (lane & 16) ? 8u : 0u;
        const uint32_t nrow = wn * 32 + (lane & 7) + ((lane & 16) ? 8 : 0);
        const uint32_t koffB = (lane & 8) ? 8u : 0u;
        #pragma unroll
        for (int ks = 0; ks < 2; ks++) {
            uint32_t ah[4][4], al[4][4], bh[4][2], bl[4][2];
            #pragma unroll
            for (int mt = 0; mt < 4; mt++) {
                uint32_t off = aoff(arow + mt * 16, ks * 16 + koffA);
                ldmx4(ah[mt], base + off);
                ldmx4(al[mt], base + 8192 + off);
            }
            #pragma unroll
            for (int g = 0; g < 2; g++) {
                uint32_t off = aoff(nrow + g * 16, ks * 16 + koffB);
                uint32_t t[4];
                ldmx4(t, base + 16384 + off);
                bh[2*g][0] = t[0]; bh[2*g][1] = t[1];
                bh[2*g+1][0] = t[2]; bh[2*g+1][1] = t[3];
                ldmx4(t, base + 24576 + off);
                bl[2*g][0] = t[0]; bl[2*g][1] = t[1];
                bl[2*g+1][0] = t[2]; bl[2*g+1][1] = t[3];
            }
            #pragma unroll
            for (int mt = 0; mt < 4; mt++)
                #pragma unroll
                for (int nt = 0; nt < 4; nt++) {
                    mma16816(acc[mt][nt], ah[mt], bh[nt]);
                    mma16816(acc[mt][nt], ah[mt], bl[nt]);
                    mma16816(acc[mt][nt], al[mt], bh[nt]);
                }
        }
    };

    ISSUE(0); CP_COMMIT();
    if (NC > 1) { ISSUE(1); CP_COMMIT(); }

    for (int c = 0; c < NC; c++) {
        const int rem = NC - 1 - c;
        if (rem >= 1) CP_WAIT(1);
        else          CP_WAIT(0);
        __syncthreads();
        if (c + 2 < NC) { ISSUE(c + 2); CP_COMMIT(); }
        MMA(c % 3);
    }
    __syncthreads();

    // ---- epilogue: regs -> smem stage -> gmem ----
    float* stage = (float*)smp;
    {
        const int r0 = wm * 64 + (lane >> 2);
        const int c0 = wn * 32 + (lane & 3) * 2;
        #pragma unroll
        for (int mt = 0; mt < 4; mt++)
            #pragma unroll
            for (int nt = 0; nt < 4; nt++) {
                int r = r0 + mt * 16, cc = c0 + nt * 8;
                float2 p0; p0.x = acc[mt][nt][0]; p0.y = acc[mt][nt][1];
                float2 p1; p1.x = acc[mt][nt][2]; p1.y = acc[mt][nt][3];
                *(float2*)&stage[r * STAGE_LD + cc]       = p0;
                *(float2*)&stage[(r + 8) * STAGE_LD + cc] = p1;
            }
    }
    __syncthreads();

    if (EPI == 1) {
        #pragma unroll 4
        for (int j = 0; j < 16; j++) {
            int lin = j * 256 + tid;
            int rr = lin >> 5;
            int cg = (lin & 31) * 4;
            int n  = n0 + cg;
            float4 v = *(float4*)&stage[rr * STAGE_LD + cg];
            if (bias) {
                float4 bb = *(const float4*)(bias + n);
                v.x += bb.x; v.y += bb.y; v.z += bb.z; v.w += bb.w;
            }
            v.x = fmaxf(v.x, 0.f); v.y = fmaxf(v.y, 0.f);
            v.z = fmaxf(v.z, 0.f); v.w = fmaxf(v.w, 0.f);
            size_t base = (size_t)(m0 + rr) * N + n;
            __nv_bfloat16 h0 = __float2bfloat16_rn(v.x), h1 = __float2bfloat16_rn(v.y);
            __nv_bfloat16 h2 = __float2bfloat16_rn(v.z), h3 = __float2bfloat16_rn(v.w);
            __nv_bfloat162 hp0; hp0.x = h0; hp0.y = h1;
            __nv_bfloat162 hp1; hp1.x = h2; hp1.y = h3;
            *(__nv_bfloat162*)(Ch + base)     = hp0;
            *(__nv_bfloat162*)(Ch + base + 2) = hp1;
            __nv_bfloat162 lp0, lp1;
            lp0.x = __float2bfloat16_rn(v.x - __bfloat162float(h0));
            lp0.y = __float2bfloat16_rn(v.y - __bfloat162float(h1));
            lp1.x = __float2bfloat16_rn(v.z - __bfloat162float(h2));
            lp1.y = __float2bfloat16_rn(v.w - __bfloat162float(h3));
            *(__nv_bfloat162*)(Cl + base)     = lp0;
            *(__nv_bfloat162*)(Cl + base + 2) = lp1;
        }
    } else {
        #pragma unroll 4
        for (int j = 0; j < 16; j++) {
            int lin = j * 256 + tid;
            int rr = lin >> 5;
            int cg = (lin & 31) * 4;
            int n  = n0 + cg;
            float4 v = *(float4*)&stage[rr * STAGE_LD + cg];
            size_t base = (size_t)(m0 + rr) * N + n;
            if (bias) {
                float4 bb = *(const float4*)(bias + n);
                v.x += bb.x; v.y += bb.y; v.z += bb.z; v.w += bb.w;
            }
            if (EPI == 2) {
                float4 rr4 = *(const float4*)(res + base);
                v.x += rr4.x; v.y += rr4.y; v.z += rr4.z; v.w += rr4.w;
            }
            *(float4*)(C + base) = v;
        }
    }
}

// ---------------- fp16 single-pass GEMM (head): C = A @ B^T + bias, fp32 out ----------------
// A: [M][K] fp16.  B: [N][K] fp16.  N may be odd. 3-stage 16KB ring.
__global__ void __launch_bounds__(256, 2)
gemm16(const __half* __restrict__ Ah, const __half* __restrict__ Bh,
       const float* __restrict__ bias, float* __restrict__ C,
       int N, int K) {
    extern __shared__ char smraw[];
    uint32_t raw = smem_u32(smraw);
    uint32_t sb  = (raw + 255u) & ~255u;
    char* smp    = smraw + (sb - raw);

    const int tid  = threadIdx.x;
    const int lane = tid & 31;
    const int wid  = tid >> 5;
    const int wm   = wid >> 2;
    const int wn   = wid & 3;
    const int m0   = blockIdx.x * 128;
    const int n0   = blockIdx.y * 128;

    const int r_ = tid >> 1;
    const int kh = (tid & 1) * 16;
    const __half* apH = Ah + (size_t)(m0 + r_) * K + kh;
    const int ng = n0 + r_;
    const bool nvB = (ng < N);
    const int ngc = nvB ? ng : (N - 1);
    const uint32_t bsz = nvB ? 16u : 0u;
    const __half* bpH = Bh + (size_t)ngc * K + kh;

    float acc[4][4][4];
    #pragma unroll
    for (int i = 0; i < 4; i++)
        #pragma unroll
        for (int j = 0; j < 4; j++)
            #pragma unroll
            for (int q = 0; q < 4; q++) acc[i][j][q] = 0.f;

    const int NC = K >> 5;
    const uint32_t o0 = aoff(r_, kh), o1 = aoff(r_, kh + 8);

    auto ISSUE = [&](int c) {
        int s = c % 3;
        uint32_t b0 = sb + s * 16384;
        const int ko = c << 5;
        cp16(b0 + o0,        apH + ko,     16u);
        cp16(b0 + o1,        apH + ko + 8, 16u);
        cp16(b0 + 8192 + o0, bpH + ko,     bsz);
        cp16(b0 + 8192 + o1, bpH + ko + 8, bsz);
    };
    auto MMA = [&](int s) {
        uint32_t base = sb + s * 16384;
        const uint32_t arow = wm * 64 + (lane & 15);
        const uint32_t koffA = (lane & 16) ? 8u : 0u;
        const uint32_t nrow = wn * 32 + (lane & 7) + ((lane & 16) ? 8 : 0);
        const uint32_t koffB = (lane & 8) ? 8u : 0u;
        #pragma unroll
        for (int ks = 0; ks < 2; ks++) {
            uint32_t ah[4][4], bh[4][2];
            #pragma unroll
            for (int mt = 0; mt < 4; mt++) {
                uint32_t off = aoff(arow + mt * 16, ks * 16 + koffA);
                ldmx4(ah[mt], base + off);
            }
            #pragma unroll
            for (int g = 0; g < 2; g++) {
                uint32_t off = aoff(nrow + g * 16, ks * 16 + koffB);
                uint32_t t[4];
                ldmx4(t, base + 8192 + off);
                bh[2*g][0] = t[0]; bh[2*g][1] = t[1];
                bh[2*g+1][0] = t[2]; bh[2*g+1][1] = t[3];
            }
            #pragma unroll
            for (int mt = 0; mt < 4; mt++)
                #pragma unroll
                for (int nt = 0; nt < 4; nt++)
                    mma16816h(acc[mt][nt], ah[mt], bh[nt]);
        }
    };

    ISSUE(0); CP_COMMIT();
    if (NC > 1) { ISSUE(1); CP_COMMIT(); }

    for (int c = 0; c < NC; c++) {
        const int rem = NC - 1 - c;
        if (rem >= 1) CP_WAIT(1);
        else          CP_WAIT(0);
        __syncthreads();
        if (c + 2 < NC) { ISSUE(c + 2); CP_COMMIT(); }
        MMA(c % 3);
    }
    __syncthreads();

    float* stage = (float*)smp;
    {
        const int r0 = wm * 64 + (lane >> 2);
        const int c0 = wn * 32 + (lane & 3) * 2;
        #pragma unroll
        for (int mt = 0; mt < 4; mt++)
            #pragma unroll
            for (int nt = 0; nt < 4; nt++) {
                int r = r0 + mt * 16, cc = c0 + nt * 8;
                float2 p0; p0.x = acc[mt][nt][0]; p0.y = acc[mt][nt][1];
                float2 p1; p1.x = acc[mt][nt][2]; p1.y = acc[mt][nt][3];
                *(float2*)&stage[r * STAGE_LD + cc]       = p0;
                *(float2*)&stage[(r + 8) * STAGE_LD + cc] = p1;
            }
    }
    __syncthreads();

    #pragma unroll 4
    for (int j = 0; j < 16; j++) {
        int lin = j * 256 + tid;
        int rr = lin >> 5;
        int cg = (lin & 31) * 4;
        #pragma unroll
        for (int q = 0; q < 4; q++) {
            int n = n0 + cg + q;
            if (n < N) {
                float v = stage[rr * STAGE_LD + cg + q];
                if (bias) v += bias[n];
                C[(size_t)(m0 + rr) * N + n] = v;
            }
        }
    }
}

// ---------------- Embedding ----------------
__global__ void embed_kernel(const int* __restrict__ idx,
                             const float* __restrict__ tok,
                             const float* __restrict__ pos,
                             float* __restrict__ x) {
    int row = blockIdx.x;
    int t   = row & (T_ - 1);
    int token = idx[row];
    const float* tp = tok + (size_t)token * E_;
    const float* pp = pos + (size_t)t * E_;
    float* xp = x + (size_t)row * E_;
    for (int e = threadIdx.x; e < E_; e += blockDim.x)
        xp[e] = tp[e] + pp[e];
}

// ---------------- LayerNorm -> bf16 hi/lo ----------------
__global__ void ln_kernel(const float* __restrict__ x,
                          const float* __restrict__ g,
                          const float* __restrict__ b,
                          __nv_bfloat16* __restrict__ yh,
                          __nv_bfloat16* __restrict__ yl) {
    int row = blockIdx.x;
    int tid = threadIdx.x;
    const float* xr = x + (size_t)row * E_;
    float v0 = xr[tid], v1 = xr[tid + 256], v2 = xr[tid + 512];
    float s  = v0 + v1 + v2;
    float ss = v0*v0 + v1*v1 + v2*v2;
    #pragma unroll
    for (int off = 16; off > 0; off >>= 1) {
        s  += __shfl_down_sync(0xffffffffu, s,  off);
        ss += __shfl_down_sync(0xffffffffu, ss, off);
    }
    __shared__ float sh_s[8], sh_ss[8];
    int wid = tid >> 5, lane = tid & 31;
    if (lane == 0) { sh_s[wid] = s; sh_ss[wid] = ss; }
    __syncthreads();
    float tot = 0.f, tots = 0.f;
    #pragma unroll
    for (int i = 0; i < 8; i++) { tot += sh_s[i]; tots += sh_ss[i]; }
    float mean = tot * (1.0f / E_);
    float var  = tots * (1.0f / E_) - mean * mean;
    float rstd = rsqrtf(var + EPS);
    size_t rb = (size_t)row * E_;
    #pragma unroll
    for (int i = 0; i < 3; i++) {
        int c = tid + i * 256;
        float vv = (i == 0 ? v0 : (i == 1 ? v1 : v2));
        float y = (vv - mean) * rstd * g[c] + b[c];
        __nv_bfloat16 h = __float2bfloat16_rn(y);
        yh[rb + c] = h;
        yl[rb + c] = __float2bfloat16_rn(y - __bfloat162float(h));
    }
}

// ---------------- Final LayerNorm -> fp16 (feeds fp16 head GEMM) ----------------
__global__ void ln16_kernel(const float* __restrict__ x,
                            const float* __restrict__ g,
                            const float* __restrict__ b,
                            __half* __restrict__ y) {
    int row = blockIdx.x;
    int tid = threadIdx.x;
    const float* xr = x + (size_t)row * E_;
    float v0 = xr[tid], v1 = xr[tid + 256], v2 = xr[tid + 512];
    float s  = v0 + v1 + v2;
    float ss = v0*v0 + v1*v1 + v2*v2;
    #pragma unroll
    for (int off = 16; off > 0; off >>= 1) {
        s  += __shfl_down_sync(0xffffffffu, s,  off);
        ss += __shfl_down_sync(0xffffffffu, ss, off);
    }
    __shared__ float sh_s[8], sh_ss[8];
    int wid = tid >> 5, lane = tid & 31;
    if (lane == 0) { sh_s[wid] = s; sh_ss[wid] = ss; }
    __syncthreads();
    float tot = 0.f, tots = 0.f;
    #pragma unroll
    for (int i = 0; i < 8; i++) { tot += sh_s[i]; tots += sh_ss[i]; }
    float mean = tot * (1.0f / E_);
    float var  = tots * (1.0f / E_) - mean * mean;
    float rstd = rsqrtf(var + EPS);
    size_t rb = (size_t)row * E_;
    #pragma unroll
    for (int i = 0; i < 3; i++) {
        int c = tid + i * 256;
        float vv = (i == 0 ? v0 : (i == 1 ? v1 : v2));
        y[rb + c] = __float2half_rn((vv - mean) * rstd * g[c] + b[c]);
    }
}

// ---------------- Attention (causal, online softmax, 2 threads/query) ----------------
__global__ void attn_kernel(const float* __restrict__ qkv,
                            __nv_bfloat16* __restrict__ oh,
                            __nv_bfloat16* __restrict__ ol) {
    __shared__ float Ks[64][68];
    __shared__ float Vs[64][68];

    const float* q = qkv;
    const float* k = qkv + (size_t)BT * E_;
    const float* v = qkv + 2 * (size_t)BT * E_;

    const int bh = blockIdx.y;
    const int b  = bh / H_, h = bh % H_;
    const int tid = threadIdx.x;
    const int tq  = blockIdx.x * 128 + (tid >> 1);
    const int half = (tid & 1) * 32;
    const float scale = rsqrtf((float)E_);

    float qr[32], oacc[32];
    const float* qp = q + (size_t)(b * T_ + tq) * E_ + h * 64 + half;
    #pragma unroll
    for (int d = 0; d < 32; d += 4) {
        float4 t4 = *(const float4*)(qp + d);
        qr[d] = t4.x * scale; qr[d+1] = t4.y * scale; qr[d+2] = t4.z * scale; qr[d+3] = t4.w * scale;
    }
    #pragma unroll
    for (int d = 0; d < 32; d++) oacc[d] = 0.f;

    float m = -1e30f, lsum = 0.f;
    const int kt_end = blockIdx.x * 128 + 127;
    const int ls = tid >> 2;
    const int lq = (tid & 3) * 16;

    for (int st0 = 0; st0 <= kt_end; st0 += 64) {
        const float* kp = k + (size_t)(b * T_ + st0 + ls) * E_ + h * 64 + lq;
        const float* vp = v + (size_t)(b * T_ + st0 + ls) * E_ + h * 64 + lq;
        #pragma unroll
        for (int d = 0; d < 16; d += 4) {
            *(float4*)&Ks[ls][lq + d] = *(const float4*)(kp + d);
            *(float4*)&Vs[ls][lq + d] = *(const float4*)(vp + d);
        }
        __syncthreads();

        #pragma unroll 2
        for (int s2 = 0; s2 < 64; s2++) {
            float p_ = 0.f;
            #pragma unroll
            for (int d = 0; d < 32; d += 4) {
                float4 kv = *(const float4*)&Ks[s2][half + d];
                p_ += qr[d] * kv.x + qr[d+1] * kv.y + qr[d+2] * kv.z + qr[d+3] * kv.w;
            }
            float sc = p_ + __shfl_xor_sync(0xffffffffu, p_, 1);
            if (st0 + s2 <= tq) {
                float newm = fmaxf(m, sc);
                float corr = __expf(m - newm);
                float p    = __expf(sc - newm);
                lsum = lsum * corr + p;
                #pragma unroll
                for (int d = 0; d < 32; d += 4) {
                    float4 vv = *(const float4*)&Vs[s2][half + d];
                    oacc[d]   = oacc[d]   * corr + p * vv.x;
                    oacc[d+1] = oacc[d+1] * corr + p * vv.y;
                    oacc[d+2] = oacc[d+2] * corr + p * vv.z;
                    oacc[d+3] = oacc[d+3] * corr + p * vv.w;
                }
                m = newm;
            }
        }
        __syncthreads();
    }

    float inv = 1.0f / lsum;
    size_t ob = (size_t)(b * T_ + tq) * E_ + h * 64 + half;
    #pragma unroll
    for (int d = 0; d < 32; d += 2) {
        float v0 = oacc[d] * inv, v1 = oacc[d+1] * inv;
        __nv_bfloat16 h0 = __float2bfloat16_rn(v0), h1 = __float2bfloat16_rn(v1);
        __nv_bfloat162 hp; hp.x = h0; hp.y = h1;
        *(__nv_bfloat162*)(oh + ob + d) = hp;
        __nv_bfloat162 lp;
        lp.x = __float2bfloat16_rn(v0 - __bfloat162float(h0));
        lp.y = __float2bfloat16_rn(v1 - __bfloat162float(h1));
        *(__nv_bfloat162*)(ol + ob + d) = lp;
    }
}

// ---------------- Host launch ----------------
extern "C" void kernel_launch(void* const* d_in, const int* in_sizes, int n_in,
                              void* d_out, int out_size) {
    const int*   idx     = (const int*)  d_in[0];
    const float* tok_emb = (const float*)d_in[1];
    const float* pos_emb = (const float*)d_in[2];
    const float* Wq      = (const float*)d_in[3];
    const float* Wk      = (const float*)d_in[4];
    const float* Wv      = (const float*)d_in[5];
    const float* Wo      = (const float*)d_in[6];
    const float* bo      = (const float*)d_in[7];
    const float* ln1_g   = (const float*)d_in[8];
    const float* ln1_b   = (const float*)d_in[9];
    const float* ln2_g   = (const float*)d_in[10];
    const float* ln2_b   = (const float*)d_in[11];
    const float* W1      = (const float*)d_in[12];
    const float* b1      = (const float*)d_in[13];
    const float* W2      = (const float*)d_in[14];
    const float* b2      = (const float*)d_in[15];
    const float* lnf_g   = (const float*)d_in[16];
    const float* lnf_b   = (const float*)d_in[17];
    const float* Wh      = (const float*)d_in[18];
    const float* bh      = (const float*)d_in[19];
    float* out = (float*)d_out;

    float *x, *qkv;
    __nv_bfloat16 *xnh, *xnl, *atth, *attl, *ffh, *ffl, *wh, *wl;
    cudaGetSymbolAddress((void**)&x,    g_x);
    cudaGetSymbolAddress((void**)&qkv,  g_qkv);
    cudaGetSymbolAddress((void**)&xnh,  g_xn_hi);
    cudaGetSymbolAddress((void**)&xnl,  g_xn_lo);
    cudaGetSymbolAddress((void**)&atth, g_att_hi);
    cudaGetSymbolAddress((void**)&attl, g_att_lo);
    cudaGetSymbolAddress((void**)&ffh,  g_ff_hi);
    cudaGetSymbolAddress((void**)&ffl,  g_ff_lo);
    cudaGetSymbolAddress((void**)&wh,   g_w_hi);
    cudaGetSymbolAddress((void**)&wl,   g_w_lo);

    cudaFuncSetAttribute(gemm_bf<0,1>, cudaFuncAttributeMaxDynamicSharedMemorySize, GEMM_SMEM);
    cudaFuncSetAttribute(gemm_bf<1,0>, cudaFuncAttributeMaxDynamicSharedMemorySize, GEMM_SMEM);
    cudaFuncSetAttribute(gemm_bf<2,0>, cudaFuncAttributeMaxDynamicSharedMemorySize, GEMM_SMEM);
    cudaFuncSetAttribute(gemm16,       cudaFuncAttributeMaxDynamicSharedMemorySize, GEMM16_SMEM);

    dim3 gEE(E_/32, E_/32);          // (24,24)
    dim3 gE1(E_/32, FF/32);          // (24,96)
    dim3 gE2(FF/32, E_/32);          // (96,24)
    dim3 gHd(E_/32, (V_+31)/32);     // (24,1571)
    dim3 gQKV(32, 6, 3);
    dim3 gE(32, 6);
    dim3 gFF(32, 24);
    dim3 gV(32, 393);
    dim3 gAttn(T_ / 128, B_ * H_);

    embed_kernel<<<BT, 256>>>(idx, tok_emb, pos_emb, x);

    for (int l = 0; l < L_; l++) {
        size_t lo = (size_t)l * LAYER_SZ;

        ln_kernel<<<BT, 256>>>(x, ln1_g + (size_t)l * E_, ln1_b + (size_t)l * E_, xnh, xnl);

        wsplit_kernel<1><<<gEE, 256>>>(Wq + (size_t)l*H_*E_*HD, wh + lo,             wl + lo,             E_, E_);
        wsplit_kernel<1><<<gEE, 256>>>(Wk + (size_t)l*H_*E_*HD, wh + lo + WQKV_SZ,   wl + lo + WQKV_SZ,   E_, E_);
        wsplit_kernel<1><<<gEE, 256>>>(Wv + (size_t)l*H_*E_*HD, wh + lo + 2*WQKV_SZ, wl + lo + 2*WQKV_SZ, E_, E_);

        gemm_bf<0,1><<<gQKV, 256, GEMM_SMEM>>>(xnh, xnl, wh + lo, wl + lo,
                                               nullptr, nullptr, qkv, nullptr, nullptr, E_, E_);

        attn_kernel<<<gAttn, 256>>>(qkv, atth, attl);

        wsplit_kernel<0><<<gEE, 256>>>(Wo + (size_t)l*E_*E_, wh + lo + WO_OFF, wl + lo + WO_OFF, E_, E_);
        gemm_bf<2,0><<<gE, 256, GEMM_SMEM>>>(atth, attl, wh + lo + WO_OFF, wl + lo + WO_OFF,
                                             bo + (size_t)l * E_, x, x, nullptr, nullptr, E_, E_);

        ln_kernel<<<BT, 256>>>(x, ln2_g + (size_t)l * E_, ln2_b + (size_t)l * E_, xnh, xnl);

        wsplit_kernel<0><<<gE1, 256>>>(W1 + (size_t)l*E_*FF, wh + lo + W1_OFF, wl + lo + W1_OFF, E_, FF);
        gemm_bf<1,0><<<gFF, 256, GEMM_SMEM>>>(xnh, xnl, wh + lo + W1_OFF, wl + lo + W1_OFF,
                                              b1 + (size_t)l * FF, nullptr, nullptr, ffh, ffl, FF, E_);

        wsplit_kernel<0><<<gE2, 256>>>(W2 + (size_t)l*FF*E_, wh + lo + W2_OFF, wl + lo + W2_OFF, FF, E_);
        gemm_bf<2,0><<<gE, 256, GEMM_SMEM>>>(ffh, ffl, wh + lo + W2_OFF, wl + lo + W2_OFF,
                                             b2 + (size_t)l * E_, x, x, nullptr, nullptr, E_, FF);
    }

    // fp16 single-pass head: final LN -> fp16, head weight -> fp16, 1-pass GEMM
    __half* xn16 = (__half*)xnh;
    __half* wh16 = (__half*)(wh + HEAD_OFF);
    ln16_kernel<<<BT, 256>>>(x, lnf_g, lnf_b, xn16);
    wsplit16_kernel<<<gHd, 256>>>(Wh, wh16, E_, V_);
    gemm16<<<gV, 256, GEMM16_SMEM>>>(xn16, wh16, bh, out, V_, E_);

    (void)in_sizes; (void)n_in; (void)out_size;
}

// round 10
// speedup vs baseline: 4.1680x; 1.5781x over previous
#include <cuda_runtime.h>
#include <cuda_bf16.h>
#include <cuda_fp16.h>
#include <math.h>
#include <stdint.h>

// ---------------- Problem constants ----------------
#define B_  4
#define T_  1024
#define BT  (B_*T_)        // 4096
#define E_  768
#define H_  12
#define HD  64
#define L_  6
#define FF  3072
#define V_  50257
#define EPS 1e-5f

#define GEMM_SMEM   98304
#define GEMM16_SMEM 68096
#define ATT_SMEM    33024
#define STAGE_LD    132

// weight scratch offsets (elements)
#define WQKV_SZ   589824
#define LAYER_SZ  7077888
#define WO_OFF    1769472
#define W1_OFF    2359296
#define W2_OFF    4718592
#define HEAD_OFF  42467328
#define WTOT      81064704

// ---------------- Device scratch (no allocs allowed) ----------------
__device__ float g_x  [BT * E_];
__device__ __nv_bfloat16 g_xn_hi[BT * E_];
__device__ __nv_bfloat16 g_xn_lo[BT * E_];
__device__ __half g_qkv_h[3 * BT * E_];
__device__ __half g_qkv_l[3 * BT * E_];
__device__ __nv_bfloat16 g_att_hi[BT * E_];
__device__ __nv_bfloat16 g_att_lo[BT * E_];
__device__ __nv_bfloat16 g_ff_hi[BT * FF];
__device__ __nv_bfloat16 g_ff_lo[BT * FF];
__device__ __nv_bfloat16 g_w_hi[WTOT];
__device__ __nv_bfloat16 g_w_lo[WTOT];

// ---------------- helpers ----------------
__device__ __forceinline__ uint32_t smem_u32(const void* p) {
    uint32_t a;
    asm("{ .reg .u64 t; cvta.to.shared.u64 t, %1; cvt.u32.u64 %0, t; }" : "=r"(a) : "l"(p));
    return a;
}
// [R][32] 16-bit tile, 64B rows; conflict-free ldmatrix swizzle
__device__ __forceinline__ uint32_t aoff(uint32_t r, uint32_t k) {
    return r * 64u + (((((k) >> 3) & 3u) ^ ((r >> 1) & 3u)) << 4) + (k & 7u) * 2u;
}
// [R][64] 16-bit tile, 128B rows; conflict-free ldmatrix swizzle
__device__ __forceinline__ uint32_t voff(uint32_t r, uint32_t k) {
    return r * 128u + ((((k >> 3) & 7u) ^ (r & 7u)) << 4) + (k & 7u) * 2u;
}
__device__ __forceinline__ void ldmx4(uint32_t r[4], uint32_t addr) {
    asm volatile("ldmatrix.sync.aligned.m8n8.x4.shared.b16 {%0,%1,%2,%3}, [%4];"
                 : "=r"(r[0]), "=r"(r[1]), "=r"(r[2]), "=r"(r[3]) : "r"(addr));
}
__device__ __forceinline__ void mma16816(float c[4], const uint32_t a[4], const uint32_t b[2]) {
    asm volatile(
        "mma.sync.aligned.m16n8k16.row.col.f32.bf16.bf16.f32 "
        "{%0,%1,%2,%3}, {%4,%5,%6,%7}, {%8,%9}, {%0,%1,%2,%3};"
        : "+f"(c[0]), "+f"(c[1]), "+f"(c[2]), "+f"(c[3])
        : "r"(a[0]), "r"(a[1]), "r"(a[2]), "r"(a[3]), "r"(b[0]), "r"(b[1]));
}
__device__ __forceinline__ void mma16816h(float c[4], const uint32_t a[4], const uint32_t b[2]) {
    asm volatile(
        "mma.sync.aligned.m16n8k16.row.col.f32.f16.f16.f32 "
        "{%0,%1,%2,%3}, {%4,%5,%6,%7}, {%8,%9}, {%0,%1,%2,%3};"
        : "+f"(c[0]), "+f"(c[1]), "+f"(c[2]), "+f"(c[3])
        : "r"(a[0]), "r"(a[1]), "r"(a[2]), "r"(a[3]), "r"(b[0]), "r"(b[1]));
}
__device__ __forceinline__ void cp16(uint32_t dst, const void* src, uint32_t sz) {
    asm volatile("cp.async.cg.shared.global [%0], [%1], 16, %2;"
                 :: "r"(dst), "l"(src), "r"(sz) : "memory");
}
#define CP_COMMIT() asm volatile("cp.async.commit_group;" ::: "memory")
#define CP_WAIT(n)  asm volatile("cp.async.wait_group %0;" :: "n"(n) : "memory")
__device__ __forceinline__ uint32_t pack_h2(__half a, __half b) {
    __half2 t = __halves2half2(a, b);
    return *(uint32_t*)&t;
}

// ---------------- Weight transpose + bf16 hi/lo split ----------------
template<int BMODE>
__global__ void wsplit_kernel(const float* __restrict__ W,
                              __nv_bfloat16* __restrict__ oh,
                              __nv_bfloat16* __restrict__ ol,
                              int K, int N) {
    __shared__ float t[32][33];
    const int k0 = blockIdx.x * 32, n0 = blockIdx.y * 32;
    const int tx = threadIdx.x & 31, ty = threadIdx.x >> 5;
    #pragma unroll
    for (int i = 0; i < 32; i += 8) {
        int k = k0 + ty + i, n = n0 + tx;
        float v = 0.f;
        if (n < N)
            v = (BMODE == 0) ? W[(size_t)k * N + n]
                             : W[((size_t)(n >> 6) * K + k) * 64 + (n & 63)];
        t[ty + i][tx] = v;
    }
    __syncthreads();
    #pragma unroll
    for (int i = 0; i < 32; i += 8) {
        int n = n0 + ty + i, k = k0 + tx;
        if (n < N) {
            float v = t[tx][ty + i];
            __nv_bfloat16 h = __float2bfloat16_rn(v);
            oh[(size_t)n * K + k] = h;
            ol[(size_t)n * K + k] = __float2bfloat16_rn(v - __bfloat162float(h));
        }
    }
}

// ---------------- Head weight transpose -> fp16 ----------------
__global__ void wsplit16_kernel(const float* __restrict__ W,
                                __half* __restrict__ oh,
                                int K, int N) {
    __shared__ float t[32][33];
    const int k0 = blockIdx.x * 32, n0 = blockIdx.y * 32;
    const int tx = threadIdx.x & 31, ty = threadIdx.x >> 5;
    #pragma unroll
    for (int i = 0; i < 32; i += 8) {
        int k = k0 + ty + i, n = n0 + tx;
        t[ty + i][tx] = (n < N) ? W[(size_t)k * N + n] : 0.f;
    }
    __syncthreads();
    #pragma unroll
    for (int i = 0; i < 32; i += 8) {
        int n = n0 + ty + i, k = k0 + tx;
        if (n < N)
            oh[(size_t)n * K + k] = __float2half_rn(t[tx][ty + i]);
    }
}

// ---------------- bf16 split GEMM ----------------
// EPI 0: +bias -> fp32. EPI 1: relu(+bias) -> bf16 hi/lo. EPI 2: res+(+bias) -> fp32.
// EPI 3: (+bias) -> fp16 hi/lo (Ch/Cl reinterpreted as __half*).
template<int EPI, int QKV>
__global__ void __launch_bounds__(256, 2)
gemm_bf(const __nv_bfloat16* __restrict__ Ah, const __nv_bfloat16* __restrict__ Al,
        const __nv_bfloat16* __restrict__ Bh0, const __nv_bfloat16* __restrict__ Bl0,
        const float* __restrict__ bias, const float* __restrict__ res,
        float* C0, __nv_bfloat16* Ch0, __nv_bfloat16* Cl0,
        int N, int K) {
    extern __shared__ char smraw[];
    uint32_t raw = smem_u32(smraw);
    uint32_t sb  = (raw + 255u) & ~255u;
    char* smp    = smraw + (sb - raw);

    const __nv_bfloat16* Bh = Bh0;
    const __nv_bfloat16* Bl = Bl0;
    float* C = C0;
    __nv_bfloat16* Ch = Ch0;
    __nv_bfloat16* Cl = Cl0;
    if (QKV) {
        Bh = Bh0 + (size_t)blockIdx.z * WQKV_SZ;
        Bl = Bl0 + (size_t)blockIdx.z * WQKV_SZ;
        Ch = Ch0 + (size_t)blockIdx.z * (BT * E_);
        Cl = Cl0 + (size_t)blockIdx.z * (BT * E_);
    }

    const int tid  = threadIdx.x;
    const int lane = tid & 31;
    const int wid  = tid >> 5;
    const int wm   = wid >> 2;
    const int wn   = wid & 3;
    const int m0   = blockIdx.x * 128;
    const int n0   = blockIdx.y * 128;

    const int r_ = tid >> 1;
    const int kh = (tid & 1) * 16;
    const __nv_bfloat16* apH = Ah + (size_t)(m0 + r_) * K + kh;
    const __nv_bfloat16* apL = Al + (size_t)(m0 + r_) * K + kh;
    const int ng = n0 + r_;
    const bool nvB = (ng < N);
    const int ngc = nvB ? ng : (N - 1);
    const uint32_t bsz = nvB ? 16u : 0u;
    const __nv_bfloat16* bpH = Bh + (size_t)ngc * K + kh;
    const __nv_bfloat16* bpL = Bl + (size_t)ngc * K + kh;

    float acc[4][4][4];
    #pragma unroll
    for (int i = 0; i < 4; i++)
        #pragma unroll
        for (int j = 0; j < 4; j++)
            #pragma unroll
            for (int q = 0; q < 4; q++) acc[i][j][q] = 0.f;

    const int NC = K >> 5;
    const uint32_t o0 = aoff(r_, kh), o1 = aoff(r_, kh + 8);

    auto ISSUE = [&](int c) {
        int s = c % 3;
        uint32_t b0 = sb + s * 32768;
        const int ko = c << 5;
        cp16(b0 + o0,         apH + ko,     16u);
        cp16(b0 + o1,         apH + ko + 8, 16u);
        cp16(b0 + 8192 + o0,  apL + ko,     16u);
        cp16(b0 + 8192 + o1,  apL + ko + 8, 16u);
        cp16(b0 + 16384 + o0, bpH + ko,     bsz);
        cp16(b0 + 16384 + o1, bpH + ko + 8, bsz);
        cp16(b0 + 24576 + o0, bpL + ko,     bsz);
        cp16(b0 + 24576 + o1, bpL + ko + 8, bsz);
    };
    auto MMA = [&](int s) {
        uint32_t base = sb + s * 32768;
        const uint32_t arow = wm * 64 + (lane & 15);
        const uint32_t koffA = (lane & 16) ? 8u : 0u;
        const uint32_t nrow = wn * 32 + (lane & 7) + ((lane & 16) ? 8 : 0);
        const uint32_t koffB = (lane & 8) ? 8u : 0u;
        #pragma unroll
        for (int ks = 0; ks < 2; ks++) {
            uint32_t ah[4][4], al[4][4], bh[4][2], bl[4][2];
            #pragma unroll
            for (int mt = 0; mt < 4; mt++) {
                uint32_t off = aoff(arow + mt * 16, ks * 16 + koffA);
                ldmx4(ah[mt], base + off);
                ldmx4(al[mt], base + 8192 + off);
            }
            #pragma unroll
            for (int g = 0; g < 2; g++) {
                uint32_t off = aoff(nrow + g * 16, ks * 16 + koffB);
                uint32_t t[4];
                ldmx4(t, base + 16384 + off);
                bh[2*g][0] = t[0]; bh[2*g][1] = t[1];
                bh[2*g+1][0] = t[2]; bh[2*g+1][1] = t[3];
                ldmx4(t, base + 24576 + off);
                bl[2*g][0] = t[0]; bl[2*g][1] = t[1];
                bl[2*g+1][0] = t[2]; bl[2*g+1][1] = t[3];
            }
            #pragma unroll
            for (int mt = 0; mt < 4; mt++)
                #pragma unroll
                for (int nt = 0; nt < 4; nt++) {
                    mma16816(acc[mt][nt], ah[mt], bh[nt]);
                    mma16816(acc[mt][nt], ah[mt], bl[nt]);
                    mma16816(acc[mt][nt], al[mt], bh[nt]);
                }
        }
    };

    ISSUE(0); CP_COMMIT();
    if (NC > 1) { ISSUE(1); CP_COMMIT(); }

    for (int c = 0; c < NC; c++) {
        const int rem = NC - 1 - c;
        if (rem >= 1) CP_WAIT(1);
        else          CP_WAIT(0);
        __syncthreads();
        if (c + 2 < NC) { ISSUE(c + 2); CP_COMMIT(); }
        MMA(c % 3);
    }
    __syncthreads();

    float* stage = (float*)smp;
    {
        const int r0 = wm * 64 + (lane >> 2);
        const int c0 = wn * 32 + (lane & 3) * 2;
        #pragma unroll
        for (int mt = 0; mt < 4; mt++)
            #pragma unroll
            for (int nt = 0; nt < 4; nt++) {
                int r = r0 + mt * 16, cc = c0 + nt * 8;
                float2 p0; p0.x = acc[mt][nt][0]; p0.y = acc[mt][nt][1];
                float2 p1; p1.x = acc[mt][nt][2]; p1.y = acc[mt][nt][3];
                *(float2*)&stage[r * STAGE_LD + cc]       = p0;
                *(float2*)&stage[(r + 8) * STAGE_LD + cc] = p1;
            }
    }
    __syncthreads();

    if (EPI == 1) {
        #pragma unroll 4
        for (int j = 0; j < 16; j++) {
            int lin = j * 256 + tid;
            int rr = lin >> 5;
            int cg = (lin & 31) * 4;
            int n  = n0 + cg;
            float4 v = *(float4*)&stage[rr * STAGE_LD + cg];
            if (bias) {
                float4 bb = *(const float4*)(bias + n);
                v.x += bb.x; v.y += bb.y; v.z += bb.z; v.w += bb.w;
            }
            v.x = fmaxf(v.x, 0.f); v.y = fmaxf(v.y, 0.f);
            v.z = fmaxf(v.z, 0.f); v.w = fmaxf(v.w, 0.f);
            size_t base = (size_t)(m0 + rr) * N + n;
            __nv_bfloat16 h0 = __float2bfloat16_rn(v.x), h1 = __float2bfloat16_rn(v.y);
            __nv_bfloat16 h2 = __float2bfloat16_rn(v.z), h3 = __float2bfloat16_rn(v.w);
            __nv_bfloat162 hp0; hp0.x = h0; hp0.y = h1;
            __nv_bfloat162 hp1; hp1.x = h2; hp1.y = h3;
            *(__nv_bfloat162*)(Ch + base)     = hp0;
            *(__nv_bfloat162*)(Ch + base + 2) = hp1;
            __nv_bfloat162 lp0, lp1;
            lp0.x = __float2bfloat16_rn(v.x - __bfloat162float(h0));
            lp0.y = __float2bfloat16_rn(v.y - __bfloat162float(h1));
            lp1.x = __float2bfloat16_rn(v.z - __bfloat162float(h2));
            lp1.y = __float2bfloat16_rn(v.w - __bfloat162float(h3));
            *(__nv_bfloat162*)(Cl + base)     = lp0;
            *(__nv_bfloat162*)(Cl + base + 2) = lp1;
        }
    } else if (EPI == 3) {
        __half* Hh = (__half*)Ch;
        __half* Hl = (__half*)Cl;
        #pragma unroll 4
        for (int j = 0; j < 16; j++) {
            int lin = j * 256 + tid;
            int rr = lin >> 5;
            int cg = (lin & 31) * 4;
            int n  = n0 + cg;
            float4 v = *(float4*)&stage[rr * STAGE_LD + cg];
            if (bias) {
                float4 bb = *(const float4*)(bias + n);
                v.x += bb.x; v.y += bb.y; v.z += bb.z; v.w += bb.w;
            }
            size_t base = (size_t)(m0 + rr) * N + n;
            __half h0 = __float2half_rn(v.x), h1 = __float2half_rn(v.y);
            __half h2 = __float2half_rn(v.z), h3 = __float2half_rn(v.w);
            uint2 hp; hp.x = pack_h2(h0, h1); hp.y = pack_h2(h2, h3);
            *(uint2*)(Hh + base) = hp;
            uint2 lp;
            lp.x = pack_h2(__float2half_rn(v.x - __half2float(h0)),
                           __float2half_rn(v.y - __half2float(h1)));
            lp.y = pack_h2(__float2half_rn(v.z - __half2float(h2)),
                           __float2half_rn(v.w - __half2float(h3)));
            *(uint2*)(Hl + base) = lp;
        }
    } else {
        #pragma unroll 4
        for (int j = 0; j < 16; j++) {
            int lin = j * 256 + tid;
            int rr = lin >> 5;
            int cg = (lin & 31) * 4;
            int n  = n0 + cg;
            float4 v = *(float4*)&stage[rr * STAGE_LD + cg];
            size_t base = (size_t)(m0 + rr) * N + n;
            if (bias) {
                float4 bb = *(const float4*)(bias + n);
                v.x += bb.x; v.y += bb.y; v.z += bb.z; v.w += bb.w;
            }
            if (EPI == 2) {
                float4 rr4 = *(const float4*)(res + base);
                v.x += rr4.x; v.y += rr4.y; v.z += rr4.z; v.w += rr4.w;
            }
            *(float4*)(C + base) = v;
        }
    }
}

// ---------------- fp16 single-pass GEMM (head) ----------------
__global__ void __launch_bounds__(256, 2)
gemm16(const __half* __restrict__ Ah, const __half* __restrict__ Bh,
       const float* __restrict__ bias, float* __restrict__ C,
       int N, int K) {
    extern __shared__ char smraw[];
    uint32_t raw = smem_u32(smraw);
    uint32_t sb  = (raw + 255u) & ~255u;
    char* smp    = smraw + (sb - raw);

    const int tid  = threadIdx.x;
    const int lane = tid & 31;
    const int wid  = tid >> 5;
    const int wm   = wid >> 2;
    const int wn   = wid & 3;
    const int m0   = blockIdx.x * 128;
    const int n0   = blockIdx.y * 128;

    const int r_ = tid >> 1;
    const int kh = (tid & 1) * 16;
    const __half* apH = Ah + (size_t)(m0 + r_) * K + kh;
    const int ng = n0 + r_;
    const bool nvB = (ng < N);
    const int ngc = nvB ? ng : (N - 1);
    const uint32_t bsz = nvB ? 16u : 0u;
    const __half* bpH = Bh + (size_t)ngc * K + kh;

    float acc[4][4][4];
    #pragma unroll
    for (int i = 0; i < 4; i++)
        #pragma unroll
        for (int j = 0; j < 4; j++)
            #pragma unroll
            for (int q = 0; q < 4; q++) acc[i][j][q] = 0.f;

    const int NC = K >> 5;
    const uint32_t o0 = aoff(r_, kh), o1 = aoff(r_, kh + 8);

    auto ISSUE = [&](int c) {
        int s = c % 3;
        uint32_t b0 = sb + s * 16384;
        const int ko = c << 5;
        cp16(b0 + o0,        apH + ko,     16u);
        cp16(b0 + o1,        apH + ko + 8, 16u);
        cp16(b0 + 8192 + o0, bpH + ko,     bsz);
        cp16(b0 + 8192 + o1, bpH + ko + 8, bsz);
    };
    auto MMA = [&](int s) {
        uint32_t base = sb + s * 16384;
        const uint32_t arow = wm * 64 + (lane & 15);
        const uint32_t koffA = (lane & 16) ? 8u : 0u;
        const uint32_t nrow = wn * 32 + (lane & 7) + ((lane & 16) ? 8 : 0);
        const uint32_t koffB = (lane & 8) ? 8u : 0u;
        #pragma unroll
        for (int ks = 0; ks < 2; ks++) {
            uint32_t ah[4][4], bh[4][2];
            #pragma unroll
            for (int mt = 0; mt < 4; mt++) {
                uint32_t off = aoff(arow + mt * 16, ks * 16 + koffA);
                ldmx4(ah[mt], base + off);
            }
            #pragma unroll
            for (int g = 0; g < 2; g++) {
                uint32_t off = aoff(nrow + g * 16, ks * 16 + koffB);
                uint32_t t[4];
                ldmx4(t, base + 8192 + off);
                bh[2*g][0] = t[0]; bh[2*g][1] = t[1];
                bh[2*g+1][0] = t[2]; bh[2*g+1][1] = t[3];
            }
            #pragma unroll
            for (int mt = 0; mt < 4; mt++)
                #pragma unroll
                for (int nt = 0; nt < 4; nt++)
                    mma16816h(acc[mt][nt], ah[mt], bh[nt]);
        }
    };

    ISSUE(0); CP_COMMIT();
    if (NC > 1) { ISSUE(1); CP_COMMIT(); }

    for (int c = 0; c < NC; c++) {
        const int rem = NC - 1 - c;
        if (rem >= 1) CP_WAIT(1);
        else          CP_WAIT(0);
        __syncthreads();
        if (c + 2 < NC) { ISSUE(c + 2); CP_COMMIT(); }
        MMA(c % 3);
    }
    __syncthreads();

    float* stage = (float*)smp;
    {
        const int r0 = wm * 64 + (lane >> 2);
        const int c0 = wn * 32 + (lane & 3) * 2;
        #pragma unroll
        for (int mt = 0; mt < 4; mt++)
            #pragma unroll
            for (int nt = 0; nt < 4; nt++) {
                int r = r0 + mt * 16, cc = c0 + nt * 8;
                float2 p0; p0.x = acc[mt][nt][0]; p0.y = acc[mt][nt][1];
                float2 p1; p1.x = acc[mt][nt][2]; p1.y = acc[mt][nt][3];
                *(float2*)&stage[r * STAGE_LD + cc]       = p0;
                *(float2*)&stage[(r + 8) * STAGE_LD + cc] = p1;
            }
    }
    __syncthreads();

    #pragma unroll 4
    for (int j = 0; j < 16; j++) {
        int lin = j * 256 + tid;
        int rr = lin >> 5;
        int cg = (lin & 31) * 4;
        #pragma unroll
        for (int q = 0; q < 4; q++) {
            int n = n0 + cg + q;
            if (n < N) {
                float v = stage[rr * STAGE_LD + cg + q];
                if (bias) v += bias[n];
                C[(size_t)(m0 + rr) * N + n] = v;
            }
        }
    }
}

// ---------------- Embedding ----------------
__global__ void embed_kernel(const int* __restrict__ idx,
                             const float* __restrict__ tok,
                             const float* __restrict__ pos,
                             float* __restrict__ x) {
    int row = blockIdx.x;
    int t   = row & (T_ - 1);
    int token = idx[row];
    const float* tp = tok + (size_t)token * E_;
    const float* pp = pos + (size_t)t * E_;
    float* xp = x + (size_t)row * E_;
    for (int e = threadIdx.x; e < E_; e += blockDim.x)
        xp[e] = tp[e] + pp[e];
}

// ---------------- LayerNorm -> bf16 hi/lo ----------------
__global__ void ln_kernel(const float* __restrict__ x,
                          const float* __restrict__ g,
                          const float* __restrict__ b,
                          __nv_bfloat16* __restrict__ yh,
                          __nv_bfloat16* __restrict__ yl) {
    int row = blockIdx.x;
    int tid = threadIdx.x;
    const float* xr = x + (size_t)row * E_;
    float v0 = xr[tid], v1 = xr[tid + 256], v2 = xr[tid + 512];
    float s  = v0 + v1 + v2;
    float ss = v0*v0 + v1*v1 + v2*v2;
    #pragma unroll
    for (int off = 16; off > 0; off >>= 1) {
        s  += __shfl_down_sync(0xffffffffu, s,  off);
        ss += __shfl_down_sync(0xffffffffu, ss, off);
    }
    __shared__ float sh_s[8], sh_ss[8];
    int wid = tid >> 5, lane = tid & 31;
    if (lane == 0) { sh_s[wid] = s; sh_ss[wid] = ss; }
    __syncthreads();
    float tot = 0.f, tots = 0.f;
    #pragma unroll
    for (int i = 0; i < 8; i++) { tot += sh_s[i]; tots += sh_ss[i]; }
    float mean = tot * (1.0f / E_);
    float var  = tots * (1.0f / E_) - mean * mean;
    float rstd = rsqrtf(var + EPS);
    size_t rb = (size_t)row * E_;
    #pragma unroll
    for (int i = 0; i < 3; i++) {
        int c = tid + i * 256;
        float vv = (i == 0 ? v0 : (i == 1 ? v1 : v2));
        float y = (vv - mean) * rstd * g[c] + b[c];
        __nv_bfloat16 h = __float2bfloat16_rn(y);
        yh[rb + c] = h;
        yl[rb + c] = __float2bfloat16_rn(y - __bfloat162float(h));
    }
}

// ---------------- Final LayerNorm -> fp16 ----------------
__global__ void ln16_kernel(const float* __restrict__ x,
                            const float* __restrict__ g,
                            const float* __restrict__ b,
                            __half* __restrict__ y) {
    int row = blockIdx.x;
    int tid = threadIdx.x;
    const float* xr = x + (size_t)row * E_;
    float v0 = xr[tid], v1 = xr[tid + 256], v2 = xr[tid + 512];
    float s  = v0 + v1 + v2;
    float ss = v0*v0 + v1*v1 + v2*v2;
    #pragma unroll
    for (int off = 16; off > 0; off >>= 1) {
        s  += __shfl_down_sync(0xffffffffu, s,  off);
        ss += __shfl_down_sync(0xffffffffu, ss, off);
    }
    __shared__ float sh_s[8], sh_ss[8];
    int wid = tid >> 5, lane = tid & 31;
    if (lane == 0) { sh_s[wid] = s; sh_ss[wid] = ss; }
    __syncthreads();
    float tot = 0.f, tots = 0.f;
    #pragma unroll
    for (int i = 0; i < 8; i++) { tot += sh_s[i]; tots += sh_ss[i]; }
    float mean = tot * (1.0f / E_);
    float var  = tots * (1.0f / E_) - mean * mean;
    float rstd = rsqrtf(var + EPS);
    size_t rb = (size_t)row * E_;
    #pragma unroll
    for (int i = 0; i < 3; i++) {
        int c = tid + i * 256;
        float vv = (i == 0 ? v0 : (i == 1 ? v1 : v2));
        y[rb + c] = __float2half_rn((vv - mean) * rstd * g[c] + b[c]);
    }
}

// ---------------- Tensor-core flash attention ----------------
// CTA: 64 queries (4 warps x 16 rows), 64-key tiles. fp16 split QK (3-pass),
// fp32 softmax, register-repacked P, fp16 split PV (3-pass).
__global__ void __launch_bounds__(128, 2)
attn_mma(const __half* __restrict__ QKVh, const __half* __restrict__ QKVl,
         __nv_bfloat16* __restrict__ Oh, __nv_bfloat16* __restrict__ Ol) {
    extern __shared__ char smraw[];
    uint32_t raw = smem_u32(smraw);
    uint32_t sb  = (raw + 255u) & ~255u;
    char* smp    = smraw + (sb - raw);
    const uint32_t s_kh = sb, s_kl = sb + 8192, s_vh = sb + 16384, s_vl = sb + 24576;
    char *p_kh = smp, *p_kl = smp + 8192, *p_vh = smp + 16384, *p_vl = smp + 24576;

    const int qb = blockIdx.x, bhid = blockIdx.y;
    const int b = bhid / H_, h = bhid % H_;
    const int tid = threadIdx.x, lane = tid & 31, wq = tid >> 5;
    const float scale = rsqrtf((float)E_);

    const __half* Qh = QKVh;             const __half* Ql = QKVl;
    const __half* Kh = QKVh + BT * E_;   const __half* Kl = QKVl + BT * E_;
    const __half* Vh = QKVh + 2*BT*E_;   const __half* Vl = QKVl + 2*BT*E_;

    const uint32_t koffA = (lane & 16) ? 8u : 0u;
    const uint32_t brow  = (lane & 7) + ((lane & 16) ? 8 : 0);
    const uint32_t koffB = (lane & 8) ? 8u : 0u;

    // ---- stage Q into smem, load A fragments, release smem ----
    uint32_t aQh[4][4], aQl[4][4];
    {
        int r = tid >> 1, hf = (tid & 1) * 32;
        const uint4* qph = (const uint4*)(Qh + (size_t)(b*T_ + qb*64 + r)*E_ + h*64 + hf);
        const uint4* qpl = (const uint4*)(Ql + (size_t)(b*T_ + qb*64 + r)*E_ + h*64 + hf);
        #pragma unroll
        for (int j = 0; j < 4; j++) {
            *(uint4*)(p_kh + voff(r, hf + j*8)) = qph[j];
            *(uint4*)(p_kl + voff(r, hf + j*8)) = qpl[j];
        }
        __syncthreads();
        #pragma unroll
        for (int ks = 0; ks < 4; ks++) {
            ldmx4(aQh[ks], s_kh + voff(wq*16 + (lane & 15), ks*16 + koffA));
            ldmx4(aQl[ks], s_kl + voff(wq*16 + (lane & 15), ks*16 + koffA));
        }
        __syncthreads();
    }

    float m0 = -1e30f, m1 = -1e30f, l0 = 0.f, l1 = 0.f;
    float O[8][4];
    #pragma unroll
    for (int nt = 0; nt < 8; nt++)
        #pragma unroll
        for (int q = 0; q < 4; q++) O[nt][q] = 0.f;

    const int q0 = qb*64 + wq*16 + (lane >> 2);
    const int q1 = q0 + 8;

    for (int st0 = 0; st0 <= qb*64; st0 += 64) {
        // ---- load K rows + V transposed into smem ----
        {
            int s = tid >> 1, hf = (tid & 1) * 32;
            const uint4* kph = (const uint4*)(Kh + (size_t)(b*T_ + st0 + s)*E_ + h*64 + hf);
            const uint4* kpl = (const uint4*)(Kl + (size_t)(b*T_ + st0 + s)*E_ + h*64 + hf);
            #pragma unroll
            for (int j = 0; j < 4; j++) {
                *(uint4*)(p_kh + voff(s, hf + j*8)) = kph[j];
                *(uint4*)(p_kl + voff(s, hf + j*8)) = kpl[j];
            }
            uint4 tvh[4], tvl[4];
            const uint4* vph = (const uint4*)(Vh + (size_t)(b*T_ + st0 + s)*E_ + h*64 + hf);
            const uint4* vpl = (const uint4*)(Vl + (size_t)(b*T_ + st0 + s)*E_ + h*64 + hf);
            #pragma unroll
            for (int j = 0; j < 4; j++) { tvh[j] = vph[j]; tvl[j] = vpl[j]; }
            const __half* hv = (const __half*)tvh;
            const __half* lv = (const __half*)tvl;
            #pragma unroll
            for (int j = 0; j < 32; j++) {
                *(__half*)(p_vh + voff(hf + j, s)) = hv[j];
                *(__half*)(p_vl + voff(hf + j, s)) = lv[j];
            }
        }
        __syncthreads();

        // ---- S = Q K^T (3-pass fp16 split) ----
        float S[8][4];
        #pragma unroll
        for (int nt = 0; nt < 8; nt++)
            #pragma unroll
            for (int q = 0; q < 4; q++) S[nt][q] = 0.f;
        #pragma unroll
        for (int ks = 0; ks < 4; ks++) {
            uint32_t bKh[8][2], bKl[8][2];
            #pragma unroll
            for (int g = 0; g < 4; g++) {
                uint32_t t[4];
                ldmx4(t, s_kh + voff(g*16 + brow, ks*16 + koffB));
                bKh[2*g][0] = t[0]; bKh[2*g][1] = t[1];
                bKh[2*g+1][0] = t[2]; bKh[2*g+1][1] = t[3];
                ldmx4(t, s_kl + voff(g*16 + brow, ks*16 + koffB));
                bKl[2*g][0] = t[0]; bKl[2*g][1] = t[1];
                bKl[2*g+1][0] = t[2]; bKl[2*g+1][1] = t[3];
            }
            #pragma unroll
            for (int nt = 0; nt < 8; nt++) {
                mma16816h(S[nt], aQh[ks], bKh[nt]);
                mma16816h(S[nt], aQl[ks], bKh[nt]);
                mma16816h(S[nt], aQh[ks], bKl[nt]);
            }
        }

        // ---- scale + causal mask (diagonal tile only) ----
        const bool diag = (st0 == qb*64);
        #pragma unroll
        for (int nt = 0; nt < 8; nt++) {
            S[nt][0] *= scale; S[nt][1] *= scale; S[nt][2] *= scale; S[nt][3] *= scale;
            if (diag) {
                int sg = st0 + nt*8 + (lane & 3)*2;
                if (sg     > q0) S[nt][0] = -1e30f;
                if (sg + 1 > q0) S[nt][1] = -1e30f;
                if (sg     > q1) S[nt][2] = -1e30f;
                if (sg + 1 > q1) S[nt][3] = -1e30f;
            }
        }

        // ---- online softmax ----
        float rx0 = -1e30f, rx1 = -1e30f;
        #pragma unroll
        for (int nt = 0; nt < 8; nt++) {
            rx0 = fmaxf(rx0, fmaxf(S[nt][0], S[nt][1]));
            rx1 = fmaxf(rx1, fmaxf(S[nt][2], S[nt][3]));
        }
        rx0 = fmaxf(rx0, __shfl_xor_sync(0xffffffffu, rx0, 1));
        rx0 = fmaxf(rx0, __shfl_xor_sync(0xffffffffu, rx0, 2));
        rx1 = fmaxf(rx1, __shfl_xor_sync(0xffffffffu, rx1, 1));
        rx1 = fmaxf(rx1, __shfl_xor_sync(0xffffffffu, rx1, 2));
        float mn0 = fmaxf(m0, rx0), mn1 = fmaxf(m1, rx1);
        float c0 = __expf(m0 - mn0), c1 = __expf(m1 - mn1);

        float rs0 = 0.f, rs1 = 0.f;
        uint32_t aPh[4][4], aPl[4][4];
        #pragma unroll
        for (int ks = 0; ks < 4; ks++) {
            #pragma unroll
            for (int hf = 0; hf < 2; hf++) {
                int nt = 2*ks + hf;
                float p0 = __expf(S[nt][0] - mn0);
                float p1 = __expf(S[nt][1] - mn0);
                float p2 = __expf(S[nt][2] - mn1);
                float p3 = __expf(S[nt][3] - mn1);
                rs0 += p0 + p1; rs1 += p2 + p3;
                __half h0 = __float2half_rn(p0), h1 = __float2half_rn(p1);
                __half h2 = __float2half_rn(p2), h3 = __float2half_rn(p3);
                aPh[ks][2*hf]     = pack_h2(h0, h1);
                aPh[ks][2*hf + 1] = pack_h2(h2, h3);
                aPl[ks][2*hf]     = pack_h2(__float2half_rn(p0 - __half2float(h0)),
                                            __float2half_rn(p1 - __half2float(h1)));
                aPl[ks][2*hf + 1] = pack_h2(__float2half_rn(p2 - __half2float(h2)),
                                            __float2half_rn(p3 - __half2float(h3)));
            }
        }
        rs0 += __shfl_xor_sync(0xffffffffu, rs0, 1);
        rs0 += __shfl_xor_sync(0xffffffffu, rs0, 2);
        rs1 += __shfl_xor_sync(0xffffffffu, rs1, 1);
        rs1 += __shfl_xor_sync(0xffffffffu, rs1, 2);
        l0 = l0 * c0 + rs0;
        l1 = l1 * c1 + rs1;

        #pragma unroll
        for (int nt = 0; nt < 8; nt++) {
            O[nt][0] *= c0; O[nt][1] *= c0; O[nt][2] *= c1; O[nt][3] *= c1;
        }

        // ---- O += P V (3-pass fp16 split) ----
        #pragma unroll
        for (int ks = 0; ks < 4; ks++) {
            uint32_t bVh[8][2], bVl[8][2];
            #pragma unroll
            for (int g = 0; g < 4; g++) {
                uint32_t t[4];
                ldmx4(t, s_vh + voff(g*16 + brow, ks*16 + koffB));
                bVh[2*g][0] = t[0]; bVh[2*g][1] = t[1];
                bVh[2*g+1][0] = t[2]; bVh[2*g+1][1] = t[3];
                ldmx4(t, s_vl + voff(g*16 + brow, ks*16 + koffB));
                bVl[2*g][0] = t[0]; bVl[2*g][1] = t[1];
                bVl[2*g+1][0] = t[2]; bVl[2*g+1][1] = t[3];
            }
            #pragma unroll
            for (int nt = 0; nt < 8; nt++) {
                mma16816h(O[nt], aPh[ks], bVh[nt]);
                mma16816h(O[nt], aPl[ks], bVh[nt]);
                mma16816h(O[nt], aPh[ks], bVl[nt]);
            }
        }
        m0 = mn0; m1 = mn1;
        __syncthreads();
    }

    // ---- write O (bf16 hi/lo) ----
    float i0 = 1.f / l0, i1 = 1.f / l1;
    size_t base0 = (size_t)(b*T_ + q0) * E_ + h*64 + (lane & 3)*2;
    size_t base1 = (size_t)(b*T_ + q1) * E_ + h*64 + (lane & 3)*2;
    #pragma unroll
    for (int nt = 0; nt < 8; nt++) {
        int d = nt * 8;
        float v0 = O[nt][0] * i0, v1 = O[nt][1] * i0;
        float v2 = O[nt][2] * i1, v3 = O[nt][3] * i1;
        __nv_bfloat16 h0 = __float2bfloat16_rn(v0), h1 = __float2bfloat16_rn(v1);
        __nv_bfloat16 h2 = __float2bfloat16_rn(v2), h3 = __float2bfloat16_rn(v3);
        __nv_bfloat162 hp0; hp0.x = h0; hp0.y = h1;
        __nv_bfloat162 hp1; hp1.x = h2; hp1.y = h3;
        *(__nv_bfloat162*)(Oh + base0 + d) = hp0;
        *(__nv_bfloat162*)(Oh + base1 + d) = hp1;
        __nv_bfloat162 lp0, lp1;
        lp0.x = __float2bfloat16_rn(v0 - __bfloat162float(h0));
        lp0.y = __float2bfloat16_rn(v1 - __bfloat162float(h1));
        lp1.x = __float2bfloat16_rn(v2 - __bfloat162float(h2));
        lp1.y = __float2bfloat16_rn(v3 - __bfloat162float(h3));
        *(__nv_bfloat162*)(Ol + base0 + d) = lp0;
        *(__nv_bfloat162*)(Ol + base1 + d) = lp1;
    }
}

// ---------------- Host launch ----------------
extern "C" void kernel_launch(void* const* d_in, const int* in_sizes, int n_in,
                              void* d_out, int out_size) {
    const int*   idx     = (const int*)  d_in[0];
    const float* tok_emb = (const float*)d_in[1];
    const float* pos_emb = (const float*)d_in[2];
    const float* Wq      = (const float*)d_in[3];
    const float* Wk      = (const float*)d_in[4];
    const float* Wv      = (const float*)d_in[5];
    const float* Wo      = (const float*)d_in[6];
    const float* bo      = (const float*)d_in[7];
    const float* ln1_g   = (const float*)d_in[8];
    const float* ln1_b   = (const float*)d_in[9];
    const float* ln2_g   = (const float*)d_in[10];
    const float* ln2_b   = (const float*)d_in[11];
    const float* W1      = (const float*)d_in[12];
    const float* b1      = (const float*)d_in[13];
    const float* W2      = (const float*)d_in[14];
    const float* b2      = (const float*)d_in[15];
    const float* lnf_g   = (const float*)d_in[16];
    const float* lnf_b   = (const float*)d_in[17];
    const float* Wh      = (const float*)d_in[18];
    const float* bh      = (const float*)d_in[19];
    float* out = (float*)d_out;

    float *x;
    __half *qkvh, *qkvl;
    __nv_bfloat16 *xnh, *xnl, *atth, *attl, *ffh, *ffl, *wh, *wl;
    cudaGetSymbolAddress((void**)&x,    g_x);
    cudaGetSymbolAddress((void**)&qkvh, g_qkv_h);
    cudaGetSymbolAddress((void**)&qkvl, g_qkv_l);
    cudaGetSymbolAddress((void**)&xnh,  g_xn_hi);
    cudaGetSymbolAddress((void**)&xnl,  g_xn_lo);
    cudaGetSymbolAddress((void**)&atth, g_att_hi);
    cudaGetSymbolAddress((void**)&attl, g_att_lo);
    cudaGetSymbolAddress((void**)&ffh,  g_ff_hi);
    cudaGetSymbolAddress((void**)&ffl,  g_ff_lo);
    cudaGetSymbolAddress((void**)&wh,   g_w_hi);
    cudaGetSymbolAddress((void**)&wl,   g_w_lo);

    cudaFuncSetAttribute(gemm_bf<3,1>, cudaFuncAttributeMaxDynamicSharedMemorySize, GEMM_SMEM);
    cudaFuncSetAttribute(gemm_bf<1,0>, cudaFuncAttributeMaxDynamicSharedMemorySize, GEMM_SMEM);
    cudaFuncSetAttribute(gemm_bf<2,0>, cudaFuncAttributeMaxDynamicSharedMemorySize, GEMM_SMEM);
    cudaFuncSetAttribute(gemm16,       cudaFuncAttributeMaxDynamicSharedMemorySize, GEMM16_SMEM);
    cudaFuncSetAttribute(attn_mma,     cudaFuncAttributeMaxDynamicSharedMemorySize, ATT_SMEM);

    dim3 gEE(E_/32, E_/32);
    dim3 gE1(E_/32, FF/32);
    dim3 gE2(FF/32, E_/32);
    dim3 gHd(E_/32, (V_+31)/32);
    dim3 gQKV(32, 6, 3);
    dim3 gE(32, 6);
    dim3 gFF(32, 24);
    dim3 gV(32, 393);
    dim3 gAttn(T_ / 64, B_ * H_);

    embed_kernel<<<BT, 256>>>(idx, tok_emb, pos_emb, x);

    for (int l = 0; l < L_; l++) {
        size_t lo = (size_t)l * LAYER_SZ;

        ln_kernel<<<BT, 256>>>(x, ln1_g + (size_t)l * E_, ln1_b + (size_t)l * E_, xnh, xnl);

        wsplit_kernel<1><<<gEE, 256>>>(Wq + (size_t)l*H_*E_*HD, wh + lo,             wl + lo,             E_, E_);
        wsplit_kernel<1><<<gEE, 256>>>(Wk + (size_t)l*H_*E_*HD, wh + lo + WQKV_SZ,   wl + lo + WQKV_SZ,   E_, E_);
        wsplit_kernel<1><<<gEE, 256>>>(Wv + (size_t)l*H_*E_*HD, wh + lo + 2*WQKV_SZ, wl + lo + 2*WQKV_SZ, E_, E_);

        gemm_bf<3,1><<<gQKV, 256, GEMM_SMEM>>>(xnh, xnl, wh + lo, wl + lo,
                                               nullptr, nullptr, nullptr,
                                               (__nv_bfloat16*)qkvh, (__nv_bfloat16*)qkvl, E_, E_);

        attn_mma<<<gAttn, 128, ATT_SMEM>>>(qkvh, qkvl, atth, attl);

        wsplit_kernel<0><<<gEE, 256>>>(Wo + (size_t)l*E_*E_, wh + lo + WO_OFF, wl + lo + WO_OFF, E_, E_);
        gemm_bf<2,0><<<gE, 256, GEMM_SMEM>>>(atth, attl, wh + lo + WO_OFF, wl + lo + WO_OFF,
                                             bo + (size_t)l * E_, x, x, nullptr, nullptr, E_, E_);

        ln_kernel<<<BT, 256>>>(x, ln2_g + (size_t)l * E_, ln2_b + (size_t)l * E_, xnh, xnl);

        wsplit_kernel<0><<<gE1, 256>>>(W1 + (size_t)l*E_*FF, wh + lo + W1_OFF, wl + lo + W1_OFF, E_, FF);
        gemm_bf<1,0><<<gFF, 256, GEMM_SMEM>>>(xnh, xnl, wh + lo + W1_OFF, wl + lo + W1_OFF,
                                              b1 + (size_t)l * FF, nullptr, nullptr, ffh, ffl, FF, E_);

        wsplit_kernel<0><<<gE2, 256>>>(W2 + (size_t)l*FF*E_, wh + lo + W2_OFF, wl + lo + W2_OFF, FF, E_);
        gemm_bf<2,0><<<gE, 256, GEMM_SMEM>>>(ffh, ffl, wh + lo + W2_OFF, wl + lo + W2_OFF,
                                             b2 + (size_t)l * E_, x, x, nullptr, nullptr, E_, FF);
    }

    // fp16 single-pass head
    __half* xn16 = (__half*)xnh;
    __half* wh16 = (__half*)(wh + HEAD_OFF);
    ln16_kernel<<<BT, 256>>>(x, lnf_g, lnf_b, xn16);
    wsplit16_kernel<<<gHd, 256>>>(Wh, wh16, E_, V_);
    gemm16<<<gV, 256, GEMM16_SMEM>>>(xn16, wh16, bh, out, V_, E_);

    (void)in_sizes; (void)n_in; (void)out_size;
}

// round 11
// speedup vs baseline: 4.3095x; 1.0339x over previous
#include <cuda_runtime.h>
#include <cuda_bf16.h>
#include <cuda_fp16.h>
#include <math.h>
#include <stdint.h>

// ---------------- Problem constants ----------------
#define B_  4
#define T_  1024
#define BT  (B_*T_)        // 4096
#define E_  768
#define H_  12
#define HD  64
#define L_  6
#define FF  3072
#define V_  50257
#define EPS 1e-5f

#define GEMM_SMEM   73984    // 3-stage ring (3 x 24KB) + align; epilogue reuses
#define GEMM16_SMEM 68096
#define ATT_SMEM    33024
#define STAGE_LD    132      // head epilogue stage stride (128-wide)
#define STAGE_LD2   68       // layer epilogue stage stride (64-wide)

// weight scratch offsets (elements)
#define WQKV_SZ   589824
#define LAYER_SZ  7077888
#define WO_OFF    1769472
#define W1_OFF    2359296
#define W2_OFF    4718592
#define HEAD_OFF  42467328
#define WTOT      81064704

// ---------------- Device scratch (no allocs allowed) ----------------
__device__ float g_x  [BT * E_];
__device__ __nv_bfloat16 g_xn_hi[BT * E_];
__device__ __nv_bfloat16 g_xn_lo[BT * E_];
__device__ __half g_qkv_h[3 * BT * E_];
__device__ __half g_qkv_l[3 * BT * E_];
__device__ __nv_bfloat16 g_att_hi[BT * E_];
__device__ __nv_bfloat16 g_att_lo[BT * E_];
__device__ __nv_bfloat16 g_ff_hi[BT * FF];
__device__ __nv_bfloat16 g_ff_lo[BT * FF];
__device__ __nv_bfloat16 g_w_hi[WTOT];
__device__ __nv_bfloat16 g_w_lo[WTOT];

// ---------------- helpers ----------------
__device__ __forceinline__ uint32_t smem_u32(const void* p) {
    uint32_t a;
    asm("{ .reg .u64 t; cvta.to.shared.u64 t, %1; cvt.u32.u64 %0, t; }" : "=r"(a) : "l"(p));
    return a;
}
// [R][32] 16-bit tile, 64B rows; conflict-free ldmatrix swizzle
__device__ __forceinline__ uint32_t aoff(uint32_t r, uint32_t k) {
    return r * 64u + (((((k) >> 3) & 3u) ^ ((r >> 1) & 3u)) << 4) + (k & 7u) * 2u;
}
// [R][64] 16-bit tile, 128B rows; conflict-free ldmatrix swizzle
__device__ __forceinline__ uint32_t voff(uint32_t r, uint32_t k) {
    return r * 128u + ((((k >> 3) & 7u) ^ (r & 7u)) << 4) + (k & 7u) * 2u;
}
__device__ __forceinline__ void ldmx4(uint32_t r[4], uint32_t addr) {
    asm volatile("ldmatrix.sync.aligned.m8n8.x4.shared.b16 {%0,%1,%2,%3}, [%4];"
                 : "=r"(r[0]), "=r"(r[1]), "=r"(r[2]), "=r"(r[3]) : "r"(addr));
}
__device__ __forceinline__ void mma16816(float c[4], const uint32_t a[4], const uint32_t b[2]) {
    asm volatile(
        "mma.sync.aligned.m16n8k16.row.col.f32.bf16.bf16.f32 "
        "{%0,%1,%2,%3}, {%4,%5,%6,%7}, {%8,%9}, {%0,%1,%2,%3};"
        : "+f"(c[0]), "+f"(c[1]), "+f"(c[2]), "+f"(c[3])
        : "r"(a[0]), "r"(a[1]), "r"(a[2]), "r"(a[3]), "r"(b[0]), "r"(b[1]));
}
__device__ __forceinline__ void mma16816h(float c[4], const uint32_t a[4], const uint32_t b[2]) {
    asm volatile(
        "mma.sync.aligned.m16n8k16.row.col.f32.f16.f16.f32 "
        "{%0,%1,%2,%3}, {%4,%5,%6,%7}, {%8,%9}, {%0,%1,%2,%3};"
        : "+f"(c[0]), "+f"(c[1]), "+f"(c[2]), "+f"(c[3])
        : "r"(a[0]), "r"(a[1]), "r"(a[2]), "r"(a[3]), "r"(b[0]), "r"(b[1]));
}
__device__ __forceinline__ void cp16(uint32_t dst, const void* src, uint32_t sz) {
    asm volatile("cp.async.cg.shared.global [%0], [%1], 16, %2;"
                 :: "r"(dst), "l"(src), "r"(sz) : "memory");
}
#define CP_COMMIT() asm volatile("cp.async.commit_group;" ::: "memory")
#define CP_WAIT(n)  asm volatile("cp.async.wait_group %0;" :: "n"(n) : "memory")
__device__ __forceinline__ uint32_t pack_h2(__half a, __half b) {
    __half2 t = __halves2half2(a, b);
    return *(uint32_t*)&t;
}

// ---------------- Batched weight transpose + bf16 hi/lo split ----------------
// QKV weights (BMODE1 head-blocked): z = l*3 + {q,k,v}
__global__ void wsplit_qkv_all(const float* __restrict__ Wq, const float* __restrict__ Wk,
                               const float* __restrict__ Wv,
                               __nv_bfloat16* __restrict__ oh0, __nv_bfloat16* __restrict__ ol0) {
    __shared__ float t[32][33];
    const int z = blockIdx.z, l = z / 3, w = z - l * 3;
    const float* W = (w == 0 ? Wq : (w == 1 ? Wk : Wv)) + (size_t)l * H_ * E_ * HD;
    size_t off = (size_t)l * LAYER_SZ + (size_t)w * WQKV_SZ;
    __nv_bfloat16* oh = oh0 + off;
    __nv_bfloat16* ol = ol0 + off;
    const int K = E_;
    const int k0 = blockIdx.x * 32, n0 = blockIdx.y * 32;
    const int tx = threadIdx.x & 31, ty = threadIdx.x >> 5;
    #pragma unroll
    for (int i = 0; i < 32; i += 8) {
        int k = k0 + ty + i, n = n0 + tx;
        t[ty + i][tx] = W[((size_t)(n >> 6) * K + k) * 64 + (n & 63)];
    }
    __syncthreads();
    #pragma unroll
    for (int i = 0; i < 32; i += 8) {
        int n = n0 + ty + i, k = k0 + tx;
        float v = t[tx][ty + i];
        __nv_bfloat16 h = __float2bfloat16_rn(v);
        oh[(size_t)n * K + k] = h;
        ol[(size_t)n * K + k] = __float2bfloat16_rn(v - __bfloat162float(h));
    }
}

// Row-major weights (BMODE0), z = layer; stride-batched
__global__ void wsplit_all0(const float* __restrict__ W0, long wstride,
                            __nv_bfloat16* __restrict__ oh0, __nv_bfloat16* __restrict__ ol0,
                            long ostride, int K, int N) {
    __shared__ float t[32][33];
    const float* W = W0 + (size_t)blockIdx.z * wstride;
    __nv_bfloat16* oh = oh0 + (size_t)blockIdx.z * ostride;
    __nv_bfloat16* ol = ol0 + (size_t)blockIdx.z * ostride;
    const int k0 = blockIdx.x * 32, n0 = blockIdx.y * 32;
    const int tx = threadIdx.x & 31, ty = threadIdx.x >> 5;
    #pragma unroll
    for (int i = 0; i < 32; i += 8) {
        int k = k0 + ty + i, n = n0 + tx;
        t[ty + i][tx] = W[(size_t)k * N + n];
    }
    __syncthreads();
    #pragma unroll
    for (int i = 0; i < 32; i += 8) {
        int n = n0 + ty + i, k = k0 + tx;
        float v = t[tx][ty + i];
        __nv_bfloat16 h = __float2bfloat16_rn(v);
        oh[(size_t)n * K + k] = h;
        ol[(size_t)n * K + k] = __float2bfloat16_rn(v - __bfloat162float(h));
    }
}

// ---------------- Head weight transpose -> fp16 ----------------
__global__ void wsplit16_kernel(const float* __restrict__ W,
                                __half* __restrict__ oh,
                                int K, int N) {
    __shared__ float t[32][33];
    const int k0 = blockIdx.x * 32, n0 = blockIdx.y * 32;
    const int tx = threadIdx.x & 31, ty = threadIdx.x >> 5;
    #pragma unroll
    for (int i = 0; i < 32; i += 8) {
        int k = k0 + ty + i, n = n0 + tx;
        t[ty + i][tx] = (n < N) ? W[(size_t)k * N + n] : 0.f;
    }
    __syncthreads();
    #pragma unroll
    for (int i = 0; i < 32; i += 8) {
        int n = n0 + ty + i, k = k0 + tx;
        if (n < N)
            oh[(size_t)n * K + k] = __float2half_rn(t[tx][ty + i]);
    }
}

// ---------------- bf16 split GEMM, CTA tile 128x64 ----------------
// A: [M][K] bf16 hi/lo.  B: [N][K] bf16 hi/lo.  N multiple of 64.
// EPI 1: relu(+bias) -> bf16 hi/lo. EPI 2: res+(+bias) -> fp32.
// EPI 3: (+bias) -> fp16 hi/lo (Ch/Cl as __half*).
// QKV 1: blockIdx.z offsets B by z*WQKV_SZ and Ch/Cl by z*BT*E_.
template<int EPI, int QKV>
__global__ void __launch_bounds__(256, 2)
gemm_bf(const __nv_bfloat16* __restrict__ Ah, const __nv_bfloat16* __restrict__ Al,
        const __nv_bfloat16* __restrict__ Bh0, const __nv_bfloat16* __restrict__ Bl0,
        const float* __restrict__ bias, const float* __restrict__ res,
        float* C, __nv_bfloat16* Ch0, __nv_bfloat16* Cl0,
        int N, int K) {
    extern __shared__ char smraw[];
    uint32_t raw = smem_u32(smraw);
    uint32_t sb  = (raw + 255u) & ~255u;
    char* smp    = smraw + (sb - raw);

    const __nv_bfloat16* Bh = Bh0;
    const __nv_bfloat16* Bl = Bl0;
    __nv_bfloat16* Ch = Ch0;
    __nv_bfloat16* Cl = Cl0;
    if (QKV) {
        Bh = Bh0 + (size_t)blockIdx.z * WQKV_SZ;
        Bl = Bl0 + (size_t)blockIdx.z * WQKV_SZ;
        Ch = Ch0 + (size_t)blockIdx.z * (BT * E_);
        Cl = Cl0 + (size_t)blockIdx.z * (BT * E_);
    }

    const int tid  = threadIdx.x;
    const int lane = tid & 31;
    const int wid  = tid >> 5;
    const int wm   = wid >> 2;          // 0..1 (64 M-rows each)
    const int wn   = wid & 3;           // 0..3 (16 N-cols each)
    const int m0   = blockIdx.x * 128;
    const int n0   = blockIdx.y * 64;

    // A loads: 128 rows x 32 k; thread -> (row=tid>>1, khalf)
    const int rA = tid >> 1;
    const int kA = (tid & 1) * 16;
    const __nv_bfloat16* apH = Ah + (size_t)(m0 + rA) * K + kA;
    const __nv_bfloat16* apL = Al + (size_t)(m0 + rA) * K + kA;
    // B loads: 64 rows x 32 k; thread -> (row=tid>>2, kq=(tid&3)*8)
    const int rB = tid >> 2;
    const int kB = (tid & 3) * 8;
    const int ng = n0 + rB;
    const bool nvB = (ng < N);
    const uint32_t bsz = nvB ? 16u : 0u;
    const __nv_bfloat16* bpH = Bh + (size_t)(nvB ? ng : 0) * K + kB;
    const __nv_bfloat16* bpL = Bl + (size_t)(nvB ? ng : 0) * K + kB;

    float acc[4][2][4];
    #pragma unroll
    for (int i = 0; i < 4; i++)
        #pragma unroll
        for (int j = 0; j < 2; j++)
            #pragma unroll
            for (int q = 0; q < 4; q++) acc[i][j][q] = 0.f;

    const int NC = K >> 5;
    const uint32_t oA0 = aoff(rA, kA), oA1 = aoff(rA, kA + 8);
    const uint32_t oB  = aoff(rB, kB);

    auto ISSUE = [&](int c) {
        int s = c % 3;
        uint32_t b0 = sb + s * 24576;
        const int ko = c << 5;
        cp16(b0 + oA0,         apH + ko,     16u);
        cp16(b0 + oA1,         apH + ko + 8, 16u);
        cp16(b0 + 8192 + oA0,  apL + ko,     16u);
        cp16(b0 + 8192 + oA1,  apL + ko + 8, 16u);
        cp16(b0 + 16384 + oB,  bpH + ko,     bsz);
        cp16(b0 + 20480 + oB,  bpL + ko,     bsz);
    };
    auto MMA = [&](int s) {
        uint32_t base = sb + s * 24576;
        const uint32_t arow = wm * 64 + (lane & 15);
        const uint32_t koffA = (lane & 16) ? 8u : 0u;
        const uint32_t nrow = wn * 16 + (lane & 7) + ((lane & 16) ? 8 : 0);
        const uint32_t koffB = (lane & 8) ? 8u : 0u;
        #pragma unroll
        for (int ks = 0; ks < 2; ks++) {
            uint32_t ah[4][4], al[4][4], bh[2][2], bl[2][2];
            #pragma unroll
            for (int mt = 0; mt < 4; mt++) {
                uint32_t off = aoff(arow + mt * 16, ks * 16 + koffA);
                ldmx4(ah[mt], base + off);
                ldmx4(al[mt], base + 8192 + off);
            }
            {
                uint32_t off = aoff(nrow, ks * 16 + koffB);
                uint32_t t[4];
                ldmx4(t, base + 16384 + off);
                bh[0][0] = t[0]; bh[0][1] = t[1];
                bh[1][0] = t[2]; bh[1][1] = t[3];
                ldmx4(t, base + 20480 + off);
                bl[0][0] = t[0]; bl[0][1] = t[1];
                bl[1][0] = t[2]; bl[1][1] = t[3];
            }
            #pragma unroll
            for (int mt = 0; mt < 4; mt++)
                #pragma unroll
                for (int nt = 0; nt < 2; nt++) {
                    mma16816(acc[mt][nt], ah[mt], bh[nt]);
                    mma16816(acc[mt][nt], ah[mt], bl[nt]);
                    mma16816(acc[mt][nt], al[mt], bh[nt]);
                }
        }
    };

    ISSUE(0); CP_COMMIT();
    if (NC > 1) { ISSUE(1); CP_COMMIT(); }

    for (int c = 0; c < NC; c++) {
        const int rem = NC - 1 - c;
        if (rem >= 1) CP_WAIT(1);
        else          CP_WAIT(0);
        __syncthreads();
        if (c + 2 < NC) { ISSUE(c + 2); CP_COMMIT(); }
        MMA(c % 3);
    }
    __syncthreads();

    // ---- epilogue: regs -> smem stage (128x64, stride 68) -> gmem ----
    float* stage = (float*)smp;
    {
        const int r0 = wm * 64 + (lane >> 2);
        const int c0 = wn * 16 + (lane & 3) * 2;
        #pragma unroll
        for (int mt = 0; mt < 4; mt++)
            #pragma unroll
            for (int nt = 0; nt < 2; nt++) {
                int r = r0 + mt * 16, cc = c0 + nt * 8;
                float2 p0; p0.x = acc[mt][nt][0]; p0.y = acc[mt][nt][1];
                float2 p1; p1.x = acc[mt][nt][2]; p1.y = acc[mt][nt][3];
                *(float2*)&stage[r * STAGE_LD2 + cc]       = p0;
                *(float2*)&stage[(r + 8) * STAGE_LD2 + cc] = p1;
            }
    }
    __syncthreads();

    if (EPI == 1) {
        #pragma unroll 4
        for (int j = 0; j < 8; j++) {
            int lin = j * 256 + tid;
            int rr = lin >> 4;
            int cg = (lin & 15) * 4;
            int n  = n0 + cg;
            float4 v = *(float4*)&stage[rr * STAGE_LD2 + cg];
            if (bias) {
                float4 bb = *(const float4*)(bias + n);
                v.x += bb.x; v.y += bb.y; v.z += bb.z; v.w += bb.w;
            }
            v.x = fmaxf(v.x, 0.f); v.y = fmaxf(v.y, 0.f);
            v.z = fmaxf(v.z, 0.f); v.w = fmaxf(v.w, 0.f);
            size_t base = (size_t)(m0 + rr) * N + n;
            __nv_bfloat16 h0 = __float2bfloat16_rn(v.x), h1 = __float2bfloat16_rn(v.y);
            __nv_bfloat16 h2 = __float2bfloat16_rn(v.z), h3 = __float2bfloat16_rn(v.w);
            __nv_bfloat162 hp0; hp0.x = h0; hp0.y = h1;
            __nv_bfloat162 hp1; hp1.x = h2; hp1.y = h3;
            *(__nv_bfloat162*)(Ch + base)     = hp0;
            *(__nv_bfloat162*)(Ch + base + 2) = hp1;
            __nv_bfloat162 lp0, lp1;
            lp0.x = __float2bfloat16_rn(v.x - __bfloat162float(h0));
            lp0.y = __float2bfloat16_rn(v.y - __bfloat162float(h1));
            lp1.x = __float2bfloat16_rn(v.z - __bfloat162float(h2));
            lp1.y = __float2bfloat16_rn(v.w - __bfloat162float(h3));
            *(__nv_bfloat162*)(Cl + base)     = lp0;
            *(__nv_bfloat162*)(Cl + base + 2) = lp1;
        }
    } else if (EPI == 3) {
        __half* Hh = (__half*)Ch;
        __half* Hl = (__half*)Cl;
        #pragma unroll 4
        for (int j = 0; j < 8; j++) {
            int lin = j * 256 + tid;
            int rr = lin >> 4;
            int cg = (lin & 15) * 4;
            int n  = n0 + cg;
            float4 v = *(float4*)&stage[rr * STAGE_LD2 + cg];
            if (bias) {
                float4 bb = *(const float4*)(bias + n);
                v.x += bb.x; v.y += bb.y; v.z += bb.z; v.w += bb.w;
            }
            size_t base = (size_t)(m0 + rr) * N + n;
            __half h0 = __float2half_rn(v.x), h1 = __float2half_rn(v.y);
            __half h2 = __float2half_rn(v.z), h3 = __float2half_rn(v.w);
            uint2 hp; hp.x = pack_h2(h0, h1); hp.y = pack_h2(h2, h3);
            *(uint2*)(Hh + base) = hp;
            uint2 lp;
            lp.x = pack_h2(__float2half_rn(v.x - __half2float(h0)),
                           __float2half_rn(v.y - __half2float(h1)));
            lp.y = pack_h2(__float2half_rn(v.z - __half2float(h2)),
                           __float2half_rn(v.w - __half2float(h3)));
            *(uint2*)(Hl + base) = lp;
        }
    } else {
        #pragma unroll 4
        for (int j = 0; j < 8; j++) {
            int lin = j * 256 + tid;
            int rr = lin >> 4;
            int cg = (lin & 15) * 4;
            int n  = n0 + cg;
            float4 v = *(float4*)&stage[rr * STAGE_LD2 + cg];
            size_t base = (size_t)(m0 + rr) * N + n;
            if (bias) {
                float4 bb = *(const float4*)(bias + n);
                v.x += bb.x; v.y += bb.y; v.z += bb.z; v.w += bb.w;
            }
            if (EPI == 2) {
                float4 rr4 = *(const float4*)(res + base);
                v.x += rr4.x; v.y += rr4.y; v.z += rr4.z; v.w += rr4.w;
            }
            *(float4*)(C + base) = v;
        }
    }
}

// ---------------- fp16 single-pass GEMM (head, 128x128 tile) ----------------
__global__ void __launch_bounds__(256, 2)
gemm16(const __half* __restrict__ Ah, const __half* __restrict__ Bh,
       const float* __restrict__ bias, float* __restrict__ C,
       int N, int K) {
    extern __shared__ char smraw[];
    uint32_t raw = smem_u32(smraw);
    uint32_t sb  = (raw + 255u) & ~255u;
    char* smp    = smraw + (sb - raw);

    const int tid  = threadIdx.x;
    const int lane = tid & 31;
    const int wid  = tid >> 5;
    const int wm   = wid >> 2;
    const int wn   = wid & 3;
    const int m0   = blockIdx.x * 128;
    const int n0   = blockIdx.y * 128;

    const int r_ = tid >> 1;
    const int kh = (tid & 1) * 16;
    const __half* apH = Ah + (size_t)(m0 + r_) * K + kh;
    const int ng = n0 + r_;
    const bool nvB = (ng < N);
    const int ngc = nvB ? ng : (N - 1);
    const uint32_t bsz = nvB ? 16u : 0u;
    const __half* bpH = Bh + (size_t)ngc * K + kh;

    float acc[4][4][4];
    #pragma unroll
    for (int i = 0; i < 4; i++)
        #pragma unroll
        for (int j = 0; j < 4; j++)
            #pragma unroll
            for (int q = 0; q < 4; q++) acc[i][j][q] = 0.f;

    const int NC = K >> 5;
    const uint32_t o0 = aoff(r_, kh), o1 = aoff(r_, kh + 8);

    auto ISSUE = [&](int c) {
        int s = c % 3;
        uint32_t b0 = sb + s * 16384;
        const int ko = c << 5;
        cp16(b0 + o0,        apH + ko,     16u);
        cp16(b0 + o1,        apH + ko + 8, 16u);
        cp16(b0 + 8192 + o0, bpH + ko,     bsz);
        cp16(b0 + 8192 + o1, bpH + ko + 8, bsz);
    };
    auto MMA = [&](int s) {
        uint32_t base = sb + s * 16384;
        const uint32_t arow = wm * 64 + (lane & 15);
        const uint32_t koffA = (lane & 16) ? 8u : 0u;
        const uint32_t nrow = wn * 32 + (lane & 7) + ((lane & 16) ? 8 : 0);
        const uint32_t koffB = (lane & 8) ? 8u : 0u;
        #pragma unroll
        for (int ks = 0; ks < 2; ks++) {
            uint32_t ah[4][4], bh[4][2];
            #pragma unroll
            for (int mt = 0; mt < 4; mt++) {
                uint32_t off = aoff(arow + mt * 16, ks * 16 + koffA);
                ldmx4(ah[mt], base + off);
            }
            #pragma unroll
            for (int g = 0; g < 2; g++) {
                uint32_t off = aoff(nrow + g * 16, ks * 16 + koffB);
                uint32_t t[4];
                ldmx4(t, base + 8192 + off);
                bh[2*g][0] = t[0]; bh[2*g][1] = t[1];
                bh[2*g+1][0] = t[2]; bh[2*g+1][1] = t[3];
            }
            #pragma unroll
            for (int mt = 0; mt < 4; mt++)
                #pragma unroll
                for (int nt = 0; nt < 4; nt++)
                    mma16816h(acc[mt][nt], ah[mt], bh[nt]);
        }
    };

    ISSUE(0); CP_COMMIT();
    if (NC > 1) { ISSUE(1); CP_COMMIT(); }

    for (int c = 0; c < NC; c++) {
        const int rem = NC - 1 - c;
        if (rem >= 1) CP_WAIT(1);
        else          CP_WAIT(0);
        __syncthreads();
        if (c + 2 < NC) { ISSUE(c + 2); CP_COMMIT(); }
        MMA(c % 3);
    }
    __syncthreads();

    float* stage = (float*)smp;
    {
        const int r0 = wm * 64 + (lane >> 2);
        const int c0 = wn * 32 + (lane & 3) * 2;
        #pragma unroll
        for (int mt = 0; mt < 4; mt++)
            #pragma unroll
            for (int nt = 0; nt < 4; nt++) {
                int r = r0 + mt * 16, cc = c0 + nt * 8;
                float2 p0; p0.x = acc[mt][nt][0]; p0.y = acc[mt][nt][1];
                float2 p1; p1.x = acc[mt][nt][2]; p1.y = acc[mt][nt][3];
                *(float2*)&stage[r * STAGE_LD + cc]       = p0;
                *(float2*)&stage[(r + 8) * STAGE_LD + cc] = p1;
            }
    }
    __syncthreads();

    #pragma unroll 4
    for (int j = 0; j < 16; j++) {
        int lin = j * 256 + tid;
        int rr = lin >> 5;
        int cg = (lin & 31) * 4;
        #pragma unroll
        for (int q = 0; q < 4; q++) {
            int n = n0 + cg + q;
            if (n < N) {
                float v = stage[rr * STAGE_LD + cg + q];
                if (bias) v += bias[n];
                C[(size_t)(m0 + rr) * N + n] = v;
            }
        }
    }
}

// ---------------- Embedding ----------------
__global__ void embed_kernel(const int* __restrict__ idx,
                             const float* __restrict__ tok,
                             const float* __restrict__ pos,
                             float* __restrict__ x) {
    int row = blockIdx.x;
    int t   = row & (T_ - 1);
    int token = idx[row];
    const float* tp = tok + (size_t)token * E_;
    const float* pp = pos + (size_t)t * E_;
    float* xp = x + (size_t)row * E_;
    for (int e = threadIdx.x; e < E_; e += blockDim.x)
        xp[e] = tp[e] + pp[e];
}

// ---------------- LayerNorm -> bf16 hi/lo ----------------
__global__ void ln_kernel(const float* __restrict__ x,
                          const float* __restrict__ g,
                          const float* __restrict__ b,
                          __nv_bfloat16* __restrict__ yh,
                          __nv_bfloat16* __restrict__ yl) {
    int row = blockIdx.x;
    int tid = threadIdx.x;
    const float* xr = x + (size_t)row * E_;
    float v0 = xr[tid], v1 = xr[tid + 256], v2 = xr[tid + 512];
    float s  = v0 + v1 + v2;
    float ss = v0*v0 + v1*v1 + v2*v2;
    #pragma unroll
    for (int off = 16; off > 0; off >>= 1) {
        s  += __shfl_down_sync(0xffffffffu, s,  off);
        ss += __shfl_down_sync(0xffffffffu, ss, off);
    }
    __shared__ float sh_s[8], sh_ss[8];
    int wid = tid >> 5, lane = tid & 31;
    if (lane == 0) { sh_s[wid] = s; sh_ss[wid] = ss; }
    __syncthreads();
    float tot = 0.f, tots = 0.f;
    #pragma unroll
    for (int i = 0; i < 8; i++) { tot += sh_s[i]; tots += sh_ss[i]; }
    float mean = tot * (1.0f / E_);
    float var  = tots * (1.0f / E_) - mean * mean;
    float rstd = rsqrtf(var + EPS);
    size_t rb = (size_t)row * E_;
    #pragma unroll
    for (int i = 0; i < 3; i++) {
        int c = tid + i * 256;
        float vv = (i == 0 ? v0 : (i == 1 ? v1 : v2));
        float y = (vv - mean) * rstd * g[c] + b[c];
        __nv_bfloat16 h = __float2bfloat16_rn(y);
        yh[rb + c] = h;
        yl[rb + c] = __float2bfloat16_rn(y - __bfloat162float(h));
    }
}

// ---------------- Final LayerNorm -> fp16 ----------------
__global__ void ln16_kernel(const float* __restrict__ x,
                            const float* __restrict__ g,
                            const float* __restrict__ b,
                            __half* __restrict__ y) {
    int row = blockIdx.x;
    int tid = threadIdx.x;
    const float* xr = x + (size_t)row * E_;
    float v0 = xr[tid], v1 = xr[tid + 256], v2 = xr[tid + 512];
    float s  = v0 + v1 + v2;
    float ss = v0*v0 + v1*v1 + v2*v2;
    #pragma unroll
    for (int off = 16; off > 0; off >>= 1) {
        s  += __shfl_down_sync(0xffffffffu, s,  off);
        ss += __shfl_down_sync(0xffffffffu, ss, off);
    }
    __shared__ float sh_s[8], sh_ss[8];
    int wid = tid >> 5, lane = tid & 31;
    if (lane == 0) { sh_s[wid] = s; sh_ss[wid] = ss; }
    __syncthreads();
    float tot = 0.f, tots = 0.f;
    #pragma unroll
    for (int i = 0; i < 8; i++) { tot += sh_s[i]; tots += sh_ss[i]; }
    float mean = tot * (1.0f / E_);
    float var  = tots * (1.0f / E_) - mean * mean;
    float rstd = rsqrtf(var + EPS);
    size_t rb = (size_t)row * E_;
    #pragma unroll
    for (int i = 0; i < 3; i++) {
        int c = tid + i * 256;
        float vv = (i == 0 ? v0 : (i == 1 ? v1 : v2));
        y[rb + c] = __float2half_rn((vv - mean) * rstd * g[c] + b[c]);
    }
}

// ---------------- Tensor-core flash attention ----------------
__global__ void __launch_bounds__(128, 2)
attn_mma(const __half* __restrict__ QKVh, const __half* __restrict__ QKVl,
         __nv_bfloat16* __restrict__ Oh, __nv_bfloat16* __restrict__ Ol) {
    extern __shared__ char smraw[];
    uint32_t raw = smem_u32(smraw);
    uint32_t sb  = (raw + 255u) & ~255u;
    char* smp    = smraw + (sb - raw);
    const uint32_t s_kh = sb, s_kl = sb + 8192, s_vh = sb + 16384, s_vl = sb + 24576;
    char *p_kh = smp, *p_kl = smp + 8192, *p_vh = smp + 16384, *p_vl = smp + 24576;

    const int qb = blockIdx.x, bhid = blockIdx.y;
    const int b = bhid / H_, h = bhid % H_;
    const int tid = threadIdx.x, lane = tid & 31, wq = tid >> 5;
    const float scale = rsqrtf((float)E_);

    const __half* Qh = QKVh;             const __half* Ql = QKVl;
    const __half* Kh = QKVh + BT * E_;   const __half* Kl = QKVl + BT * E_;
    const __half* Vh = QKVh + 2*BT*E_;   const __half* Vl = QKVl + 2*BT*E_;

    const uint32_t koffA = (lane & 16) ? 8u : 0u;
    const uint32_t brow  = (lane & 7) + ((lane & 16) ? 8 : 0);
    const uint32_t koffB = (lane & 8) ? 8u : 0u;

    uint32_t aQh[4][4], aQl[4][4];
    {
        int r = tid >> 1, hf = (tid & 1) * 32;
        const uint4* qph = (const uint4*)(Qh + (size_t)(b*T_ + qb*64 + r)*E_ + h*64 + hf);
        const uint4* qpl = (const uint4*)(Ql + (size_t)(b*T_ + qb*64 + r)*E_ + h*64 + hf);
        #pragma unroll
        for (int j = 0; j < 4; j++) {
            *(uint4*)(p_kh + voff(r, hf + j*8)) = qph[j];
            *(uint4*)(p_kl + voff(r, hf + j*8)) = qpl[j];
        }
        __syncthreads();
        #pragma unroll
        for (int ks = 0; ks < 4; ks++) {
            ldmx4(aQh[ks], s_kh + voff(wq*16 + (lane & 15), ks*16 + koffA));
            ldmx4(aQl[ks], s_kl + voff(wq*16 + (lane & 15), ks*16 + koffA));
        }
        __syncthreads();
    }

    float m0 = -1e30f, m1 = -1e30f, l0 = 0.f, l1 = 0.f;
    float O[8][4];
    #pragma unroll
    for (int nt = 0; nt < 8; nt++)
        #pragma unroll
        for (int q = 0; q < 4; q++) O[nt][q] = 0.f;

    const int q0 = qb*64 + wq*16 + (lane >> 2);
    const int q1 = q0 + 8;

    for (int st0 = 0; st0 <= qb*64; st0 += 64) {
        {
            int s = tid >> 1, hf = (tid & 1) * 32;
            const uint4* kph = (const uint4*)(Kh + (size_t)(b*T_ + st0 + s)*E_ + h*64 + hf);
            const uint4* kpl = (const uint4*)(Kl + (size_t)(b*T_ + st0 + s)*E_ + h*64 + hf);
            #pragma unroll
            for (int j = 0; j < 4; j++) {
                *(uint4*)(p_kh + voff(s, hf + j*8)) = kph[j];
                *(uint4*)(p_kl + voff(s, hf + j*8)) = kpl[j];
            }
            uint4 tvh[4], tvl[4];
            const uint4* vph = (const uint4*)(Vh + (size_t)(b*T_ + st0 + s)*E_ + h*64 + hf);
            const uint4* vpl = (const uint4*)(Vl + (size_t)(b*T_ + st0 + s)*E_ + h*64 + hf);
            #pragma unroll
            for (int j = 0; j < 4; j++) { tvh[j] = vph[j]; tvl[j] = vpl[j]; }
            const __half* hv = (const __half*)tvh;
            const __half* lv = (const __half*)tvl;
            #pragma unroll
            for (int j = 0; j < 32; j++) {
                *(__half*)(p_vh + voff(hf + j, s)) = hv[j];
                *(__half*)(p_vl + voff(hf + j, s)) = lv[j];
            }
        }
        __syncthreads();

        float S[8][4];
        #pragma unroll
        for (int nt = 0; nt < 8; nt++)
            #pragma unroll
            for (int q = 0; q < 4; q++) S[nt][q] = 0.f;
        #pragma unroll
        for (int ks = 0; ks < 4; ks++) {
            uint32_t bKh[8][2], bKl[8][2];
            #pragma unroll
            for (int g = 0; g < 4; g++) {
                uint32_t t[4];
                ldmx4(t, s_kh + voff(g*16 + brow, ks*16 + koffB));
                bKh[2*g][0] = t[0]; bKh[2*g][1] = t[1];
                bKh[2*g+1][0] = t[2]; bKh[2*g+1][1] = t[3];
                ldmx4(t, s_kl + voff(g*16 + brow, ks*16 + koffB));
                bKl[2*g][0] = t[0]; bKl[2*g][1] = t[1];
                bKl[2*g+1][0] = t[2]; bKl[2*g+1][1] = t[3];
            }
            #pragma unroll
            for (int nt = 0; nt < 8; nt++) {
                mma16816h(S[nt], aQh[ks], bKh[nt]);
                mma16816h(S[nt], aQl[ks], bKh[nt]);
                mma16816h(S[nt], aQh[ks], bKl[nt]);
            }
        }

        const bool diag = (st0 == qb*64);
        #pragma unroll
        for (int nt = 0; nt < 8; nt++) {
            S[nt][0] *= scale; S[nt][1] *= scale; S[nt][2] *= scale; S[nt][3] *= scale;
            if (diag) {
                int sg = st0 + nt*8 + (lane & 3)*2;
                if (sg     > q0) S[nt][0] = -1e30f;
                if (sg + 1 > q0) S[nt][1] = -1e30f;
                if (sg     > q1) S[nt][2] = -1e30f;
                if (sg + 1 > q1) S[nt][3] = -1e30f;
            }
        }

        float rx0 = -1e30f, rx1 = -1e30f;
        #pragma unroll
        for (int nt = 0; nt < 8; nt++) {
            rx0 = fmaxf(rx0, fmaxf(S[nt][0], S[nt][1]));
            rx1 = fmaxf(rx1, fmaxf(S[nt][2], S[nt][3]));
        }
        rx0 = fmaxf(rx0, __shfl_xor_sync(0xffffffffu, rx0, 1));
        rx0 = fmaxf(rx0, __shfl_xor_sync(0xffffffffu, rx0, 2));
        rx1 = fmaxf(rx1, __shfl_xor_sync(0xffffffffu, rx1, 1));
        rx1 = fmaxf(rx1, __shfl_xor_sync(0xffffffffu, rx1, 2));
        float mn0 = fmaxf(m0, rx0), mn1 = fmaxf(m1, rx1);
        float c0 = __expf(m0 - mn0), c1 = __expf(m1 - mn1);

        float rs0 = 0.f, rs1 = 0.f;
        uint32_t aPh[4][4], aPl[4][4];
        #pragma unroll
        for (int ks = 0; ks < 4; ks++) {
            #pragma unroll
            for (int hf = 0; hf < 2; hf++) {
                int nt = 2*ks + hf;
                float p0 = __expf(S[nt][0] - mn0);
                float p1 = __expf(S[nt][1] - mn0);
                float p2 = __expf(S[nt][2] - mn1);
                float p3 = __expf(S[nt][3] - mn1);
                rs0 += p0 + p1; rs1 += p2 + p3;
                __half h0 = __float2half_rn(p0), h1 = __float2half_rn(p1);
                __half h2 = __float2half_rn(p2), h3 = __float2half_rn(p3);
                aPh[ks][2*hf]     = pack_h2(h0, h1);
                aPh[ks][2*hf + 1] = pack_h2(h2, h3);
                aPl[ks][2*hf]     = pack_h2(__float2half_rn(p0 - __half2float(h0)),
                                            __float2half_rn(p1 - __half2float(h1)));
                aPl[ks][2*hf + 1] = pack_h2(__float2half_rn(p2 - __half2float(h2)),
                                            __float2half_rn(p3 - __half2float(h3)));
            }
        }
        rs0 += __shfl_xor_sync(0xffffffffu, rs0, 1);
        rs0 += __shfl_xor_sync(0xffffffffu, rs0, 2);
        rs1 += __shfl_xor_sync(0xffffffffu, rs1, 1);
        rs1 += __shfl_xor_sync(0xffffffffu, rs1, 2);
        l0 = l0 * c0 + rs0;
        l1 = l1 * c1 + rs1;

        #pragma unroll
        for (int nt = 0; nt < 8; nt++) {
            O[nt][0] *= c0; O[nt][1] *= c0; O[nt][2] *= c1; O[nt][3] *= c1;
        }

        #pragma unroll
        for (int ks = 0; ks < 4; ks++) {
            uint32_t bVh[8][2], bVl[8][2];
            #pragma unroll
            for (int g = 0; g < 4; g++) {
                uint32_t t[4];
                ldmx4(t, s_vh + voff(g*16 + brow, ks*16 + koffB));
                bVh[2*g][0] = t[0]; bVh[2*g][1] = t[1];
                bVh[2*g+1][0] = t[2]; bVh[2*g+1][1] = t[3];
                ldmx4(t, s_vl + voff(g*16 + brow, ks*16 + koffB));
                bVl[2*g][0] = t[0]; bVl[2*g][1] = t[1];
                bVl[2*g+1][0] = t[2]; bVl[2*g+1][1] = t[3];
            }
            #pragma unroll
            for (int nt = 0; nt < 8; nt++) {
                mma16816h(O[nt], aPh[ks], bVh[nt]);
                mma16816h(O[nt], aPl[ks], bVh[nt]);
                mma16816h(O[nt], aPh[ks], bVl[nt]);
            }
        }
        m0 = mn0; m1 = mn1;
        __syncthreads();
    }

    float i0 = 1.f / l0, i1 = 1.f / l1;
    size_t base0 = (size_t)(b*T_ + q0) * E_ + h*64 + (lane & 3)*2;
    size_t base1 = (size_t)(b*T_ + q1) * E_ + h*64 + (lane & 3)*2;
    #pragma unroll
    for (int nt = 0; nt < 8; nt++) {
        int d = nt * 8;
        float v0 = O[nt][0] * i0, v1 = O[nt][1] * i0;
        float v2 = O[nt][2] * i1, v3 = O[nt][3] * i1;
        __nv_bfloat16 h0 = __float2bfloat16_rn(v0), h1 = __float2bfloat16_rn(v1);
        __nv_bfloat16 h2 = __float2bfloat16_rn(v2), h3 = __float2bfloat16_rn(v3);
        __nv_bfloat162 hp0; hp0.x = h0; hp0.y = h1;
        __nv_bfloat162 hp1; hp1.x = h2; hp1.y = h3;
        *(__nv_bfloat162*)(Oh + base0 + d) = hp0;
        *(__nv_bfloat162*)(Oh + base1 + d) = hp1;
        __nv_bfloat162 lp0, lp1;
        lp0.x = __float2bfloat16_rn(v0 - __bfloat162float(h0));
        lp0.y = __float2bfloat16_rn(v1 - __bfloat162float(h1));
        lp1.x = __float2bfloat16_rn(v2 - __bfloat162float(h2));
        lp1.y = __float2bfloat16_rn(v3 - __bfloat162float(h3));
        *(__nv_bfloat162*)(Ol + base0 + d) = lp0;
        *(__nv_bfloat162*)(Ol + base1 + d) = lp1;
    }
}

// ---------------- Host launch ----------------
extern "C" void kernel_launch(void* const* d_in, const int* in_sizes, int n_in,
                              void* d_out, int out_size) {
    const int*   idx     = (const int*)  d_in[0];
    const float* tok_emb = (const float*)d_in[1];
    const float* pos_emb = (const float*)d_in[2];
    const float* Wq      = (const float*)d_in[3];
    const float* Wk      = (const float*)d_in[4];
    const float* Wv      = (const float*)d_in[5];
    const float* Wo      = (const float*)d_in[6];
    const float* bo      = (const float*)d_in[7];
    const float* ln1_g   = (const float*)d_in[8];
    const float* ln1_b   = (const float*)d_in[9];
    const float* ln2_g   = (const float*)d_in[10];
    const float* ln2_b   = (const float*)d_in[11];
    const float* W1      = (const float*)d_in[12];
    const float* b1      = (const float*)d_in[13];
    const float* W2      = (const float*)d_in[14];
    const float* b2      = (const float*)d_in[15];
    const float* lnf_g   = (const float*)d_in[16];
    const float* lnf_b   = (const float*)d_in[17];
    const float* Wh      = (const float*)d_in[18];
    const float* bh      = (const float*)d_in[19];
    float* out = (float*)d_out;

    float *x;
    __half *qkvh, *qkvl;
    __nv_bfloat16 *xnh, *xnl, *atth, *attl, *ffh, *ffl, *wh, *wl;
    cudaGetSymbolAddress((void**)&x,    g_x);
    cudaGetSymbolAddress((void**)&qkvh, g_qkv_h);
    cudaGetSymbolAddress((void**)&qkvl, g_qkv_l);
    cudaGetSymbolAddress((void**)&xnh,  g_xn_hi);
    cudaGetSymbolAddress((void**)&xnl,  g_xn_lo);
    cudaGetSymbolAddress((void**)&atth, g_att_hi);
    cudaGetSymbolAddress((void**)&attl, g_att_lo);
    cudaGetSymbolAddress((void**)&ffh,  g_ff_hi);
    cudaGetSymbolAddress((void**)&ffl,  g_ff_lo);
    cudaGetSymbolAddress((void**)&wh,   g_w_hi);
    cudaGetSymbolAddress((void**)&wl,   g_w_lo);

    cudaFuncSetAttribute(gemm_bf<3,1>, cudaFuncAttributeMaxDynamicSharedMemorySize, GEMM_SMEM);
    cudaFuncSetAttribute(gemm_bf<1,0>, cudaFuncAttributeMaxDynamicSharedMemorySize, GEMM_SMEM);
    cudaFuncSetAttribute(gemm_bf<2,0>, cudaFuncAttributeMaxDynamicSharedMemorySize, GEMM_SMEM);
    cudaFuncSetAttribute(gemm16,       cudaFuncAttributeMaxDynamicSharedMemorySize, GEMM16_SMEM);
    cudaFuncSetAttribute(attn_mma,     cudaFuncAttributeMaxDynamicSharedMemorySize, ATT_SMEM);

    dim3 gQKVsplit(24, 24, 18);      // all layers' Wq/Wk/Wv
    dim3 gWoAll(24, 24, 6);
    dim3 gW1All(24, 96, 6);
    dim3 gW2All(96, 24, 6);
    dim3 gHd(E_/32, (V_+31)/32);
    dim3 gQKV(32, 12, 3);            // 128x64 tiles
    dim3 gE(32, 12);
    dim3 gFF(32, 48);
    dim3 gV(32, 393);
    dim3 gAttn(T_ / 64, B_ * H_);

    // launch order: QKV GEMM of layer 0 at our 0-based index 4 (ncu window)
    embed_kernel<<<BT, 256>>>(idx, tok_emb, pos_emb, x);                              // 0
    ln_kernel<<<BT, 256>>>(x, ln1_g, ln1_b, xnh, xnl);                                // 1
    wsplit_qkv_all<<<gQKVsplit, 256>>>(Wq, Wk, Wv, wh, wl);                           // 2
    wsplit_all0<<<gWoAll, 256>>>(Wo, (long)E_*E_, wh + WO_OFF, wl + WO_OFF,
                                 (long)LAYER_SZ, E_, E_);                             // 3

    for (int l = 0; l < L_; l++) {
        size_t lo = (size_t)l * LAYER_SZ;

        if (l > 0)
            ln_kernel<<<BT, 256>>>(x, ln1_g + (size_t)l * E_, ln1_b + (size_t)l * E_, xnh, xnl);

        gemm_bf<3,1><<<gQKV, 256, GEMM_SMEM>>>(xnh, xnl, wh + lo, wl + lo,            // 4 for l=0
                                               nullptr, nullptr, nullptr,
                                               (__nv_bfloat16*)qkvh, (__nv_bfloat16*)qkvl, E_, E_);

        attn_mma<<<gAttn, 128, ATT_SMEM>>>(qkvh, qkvl, atth, attl);

        gemm_bf<2,0><<<gE, 256, GEMM_SMEM>>>(atth, attl, wh + lo + WO_OFF, wl + lo + WO_OFF,
                                             bo + (size_t)l * E_, x, x, nullptr, nullptr, E_, E_);

        ln_kernel<<<BT, 256>>>(x, ln2_g + (size_t)l * E_, ln2_b + (size_t)l * E_, xnh, xnl);

        if (l == 0)
            wsplit_all0<<<gW1All, 256>>>(W1, (long)E_*FF, wh + W1_OFF, wl + W1_OFF,
                                         (long)LAYER_SZ, E_, FF);
        gemm_bf<1,0><<<gFF, 256, GEMM_SMEM>>>(xnh, xnl, wh + lo + W1_OFF, wl + lo + W1_OFF,
                                              b1 + (size_t)l * FF, nullptr, nullptr, ffh, ffl, FF, E_);

        if (l == 0)
            wsplit_all0<<<gW2All, 256>>>(W2, (long)FF*E_, wh + W2_OFF, wl + W2_OFF,
                                         (long)LAYER_SZ, FF, E_);
        gemm_bf<2,0><<<gE, 256, GEMM_SMEM>>>(ffh, ffl, wh + lo + W2_OFF, wl + lo + W2_OFF,
                                             b2 + (size_t)l * E_, x, x, nullptr, nullptr, E_, FF);
    }

    // fp16 single-pass head
    __half* xn16 = (__half*)xnh;
    __half* wh16 = (__half*)(wh + HEAD_OFF);
    ln16_kernel<<<BT, 256>>>(x, lnf_g, lnf_b, xn16);
    wsplit16_kernel<<<gHd, 256>>>(Wh, wh16, E_, V_);
    gemm16<<<gV, 256, GEMM16_SMEM>>>(xn16, wh16, bh, out, V_, E_);

    (void)in_sizes; (void)n_in; (void)out_size;
}

// round 12
// speedup vs baseline: 5.5644x; 1.2912x over previous
#include <cuda_runtime.h>
#include <cuda_bf16.h>
#include <cuda_fp16.h>
#include <math.h>
#include <stdint.h>

// ---------------- Problem constants ----------------
#define B_  4
#define T_  1024
#define BT  (B_*T_)        // 4096
#define E_  768
#define E3  2304           // fused QKV width
#define H_  12
#define HD  64
#define L_  6
#define FF  3072
#define V_  50257
#define EPS 1e-5f

#define GEMM_SMEM   73984    // MT=128: 3 x 24KB ring; epilogue reuses
#define GEMM64_SMEM 49408    // MT=64: 3 x 16KB ring
#define GEMM16_SMEM 68096
#define ATT_SMEM    33024
#define STAGE_LD    132

// weight scratch offsets (elements)
#define WQKV_SZ   589824
#define LAYER_SZ  7077888
#define WO_OFF    1769472
#define W1_OFF    2359296
#define W2_OFF    4718592
#define HEAD_OFF  42467328
#define WTOT      81064704

// ---------------- Device scratch (no allocs allowed) ----------------
__device__ float g_x  [BT * E_];
__device__ __half g_xn_h[BT * E_];
__device__ __half g_xn_l[BT * E_];
__device__ __half g_qkv_h[BT * E3];
__device__ __half g_qkv_l[BT * E3];
__device__ __half g_att_h[BT * E_];
__device__ __half g_att_l[BT * E_];
__device__ __half g_ff_h[BT * FF];
__device__ __half g_ff_l[BT * FF];
__device__ __half g_w_h[WTOT];

// ---------------- helpers ----------------
__device__ __forceinline__ uint32_t smem_u32(const void* p) {
    uint32_t a;
    asm("{ .reg .u64 t; cvta.to.shared.u64 t, %1; cvt.u32.u64 %0, t; }" : "=r"(a) : "l"(p));
    return a;
}
// [R][32] 16-bit tile, 64B rows; conflict-free ldmatrix swizzle
__device__ __forceinline__ uint32_t aoff(uint32_t r, uint32_t k) {
    return r * 64u + (((((k) >> 3) & 3u) ^ ((r >> 1) & 3u)) << 4) + (k & 7u) * 2u;
}
// [R][64] 16-bit tile, 128B rows; conflict-free ldmatrix swizzle
__device__ __forceinline__ uint32_t voff(uint32_t r, uint32_t k) {
    return r * 128u + ((((k >> 3) & 7u) ^ (r & 7u)) << 4) + (k & 7u) * 2u;
}
__device__ __forceinline__ void ldmx4(uint32_t r[4], uint32_t addr) {
    asm volatile("ldmatrix.sync.aligned.m8n8.x4.shared.b16 {%0,%1,%2,%3}, [%4];"
                 : "=r"(r[0]), "=r"(r[1]), "=r"(r[2]), "=r"(r[3]) : "r"(addr));
}
__device__ __forceinline__ void mma16816h(float c[4], const uint32_t a[4], const uint32_t b[2]) {
    asm volatile(
        "mma.sync.aligned.m16n8k16.row.col.f32.f16.f16.f32 "
        "{%0,%1,%2,%3}, {%4,%5,%6,%7}, {%8,%9}, {%0,%1,%2,%3};"
        : "+f"(c[0]), "+f"(c[1]), "+f"(c[2]), "+f"(c[3])
        : "r"(a[0]), "r"(a[1]), "r"(a[2]), "r"(a[3]), "r"(b[0]), "r"(b[1]));
}
__device__ __forceinline__ void cp16(uint32_t dst, const void* src, uint32_t sz) {
    asm volatile("cp.async.cg.shared.global [%0], [%1], 16, %2;"
                 :: "r"(dst), "l"(src), "r"(sz) : "memory");
}
#define CP_COMMIT() asm volatile("cp.async.commit_group;" ::: "memory")
#define CP_WAIT(n)  asm volatile("cp.async.wait_group %0;" :: "n"(n) : "memory")
__device__ __forceinline__ uint32_t pack_h2(__half a, __half b) {
    __half2 t = __halves2half2(a, b);
    return *(uint32_t*)&t;
}

// ---------------- Weight transpose -> fp16 single ----------------
// QKV weights (head-blocked): z = l*3 + {q,k,v}
__global__ void wsplit_qkv_all(const float* __restrict__ Wq, const float* __restrict__ Wk,
                               const float* __restrict__ Wv, __half* __restrict__ oh0) {
    __shared__ float t[32][33];
    const int z = blockIdx.z, l = z / 3, w = z - l * 3;
    const float* W = (w == 0 ? Wq : (w == 1 ? Wk : Wv)) + (size_t)l * H_ * E_ * HD;
    __half* oh = oh0 + (size_t)l * LAYER_SZ + (size_t)w * WQKV_SZ;
    const int K = E_;
    const int k0 = blockIdx.x * 32, n0 = blockIdx.y * 32;
    const int tx = threadIdx.x & 31, ty = threadIdx.x >> 5;
    #pragma unroll
    for (int i = 0; i < 32; i += 8) {
        int k = k0 + ty + i, n = n0 + tx;
        t[ty + i][tx] = W[((size_t)(n >> 6) * K + k) * 64 + (n & 63)];
    }
    __syncthreads();
    #pragma unroll
    for (int i = 0; i < 32; i += 8) {
        int n = n0 + ty + i, k = k0 + tx;
        oh[(size_t)n * K + k] = __float2half_rn(t[tx][ty + i]);
    }
}

// Row-major weights, z = layer; stride-batched
__global__ void wsplit_all0(const float* __restrict__ W0, long wstride,
                            __half* __restrict__ oh0, long ostride, int K, int N) {
    __shared__ float t[32][33];
    const float* W = W0 + (size_t)blockIdx.z * wstride;
    __half* oh = oh0 + (size_t)blockIdx.z * ostride;
    const int k0 = blockIdx.x * 32, n0 = blockIdx.y * 32;
    const int tx = threadIdx.x & 31, ty = threadIdx.x >> 5;
    #pragma unroll
    for (int i = 0; i < 32; i += 8) {
        int k = k0 + ty + i, n = n0 + tx;
        t[ty + i][tx] = W[(size_t)k * N + n];
    }
    __syncthreads();
    #pragma unroll
    for (int i = 0; i < 32; i += 8) {
        int n = n0 + ty + i, k = k0 + tx;
        oh[(size_t)n * K + k] = __float2half_rn(t[tx][ty + i]);
    }
}

// Head weight transpose -> fp16 (N-guarded, odd N)
__global__ void wsplit16_kernel(const float* __restrict__ W,
                                __half* __restrict__ oh, int K, int N) {
    __shared__ float t[32][33];
    const int k0 = blockIdx.x * 32, n0 = blockIdx.y * 32;
    const int tx = threadIdx.x & 31, ty = threadIdx.x >> 5;
    #pragma unroll
    for (int i = 0; i < 32; i += 8) {
        int k = k0 + ty + i, n = n0 + tx;
        t[ty + i][tx] = (n < N) ? W[(size_t)k * N + n] : 0.f;
    }
    __syncthreads();
    #pragma unroll
    for (int i = 0; i < 32; i += 8) {
        int n = n0 + ty + i, k = k0 + tx;
        if (n < N)
            oh[(size_t)n * K + k] = __float2half_rn(t[tx][ty + i]);
    }
}

// ---------------- 2-pass fp16 GEMM: C[M,N] = (Ah+Al) @ B^T + epilogue ----------------
// A: [M][K] fp16 hi/lo. B: [N][K] fp16 single. N multiple of 128, M multiple of MT.
// MT: 128 or 64 (M CTA tile). N-tile always 128.
// EPI 1: relu(+bias) -> fp16 hi/lo. EPI 2: res+(+bias) -> fp32 C. EPI 3: (+bias) -> fp16 hi/lo.
template<int MT, int EPI>
__global__ void __launch_bounds__(256, 2)
gemm_h2(const __half* __restrict__ Ah, const __half* __restrict__ Al,
        const __half* __restrict__ B,
        const float* __restrict__ bias, const float* __restrict__ res,
        float* C, __half* __restrict__ Ch, __half* __restrict__ Cl,
        int N, int K) {
    extern __shared__ char smraw[];
    uint32_t raw = smem_u32(smraw);
    uint32_t sb  = (raw + 255u) & ~255u;
    char* smp    = smraw + (sb - raw);

    constexpr int ASZ   = MT * 64;          // bytes per A array per stage
    constexpr int STG   = 2 * ASZ + 8192;   // stage size
    constexpr int MTILES = MT / 32;

    const int tid  = threadIdx.x;
    const int lane = tid & 31;
    const int wid  = tid >> 5;
    const int wm   = wid >> 2;              // 0..1
    const int wn   = wid & 3;               // 0..3
    const int m0   = blockIdx.x * MT;
    const int n0   = blockIdx.y * 128;

    // A loads
    int rA, kA, nA;                          // nA = cp16 per A array
    if (MT == 128) { rA = tid >> 1; kA = (tid & 1) * 16; nA = 2; }
    else           { rA = tid >> 2; kA = (tid & 3) * 8;  nA = 1; }
    const __half* apH = Ah + (size_t)(m0 + rA) * K + kA;
    const __half* apL = Al + (size_t)(m0 + rA) * K + kA;
    // B loads: 128 rows
    const int rB = tid >> 1, kB = (tid & 1) * 16;
    const __half* bp = B + (size_t)(n0 + rB) * K + kB;

    float acc[MTILES][4][4];
    #pragma unroll
    for (int i = 0; i < MTILES; i++)
        #pragma unroll
        for (int j = 0; j < 4; j++)
            #pragma unroll
            for (int q = 0; q < 4; q++) acc[i][j][q] = 0.f;

    const int NC = K >> 5;
    const uint32_t oA0 = aoff(rA, kA), oA1 = aoff(rA, kA + 8);
    const uint32_t oB0 = aoff(rB, kB), oB1 = aoff(rB, kB + 8);

    auto ISSUE = [&](int c) {
        uint32_t b0 = sb + (c % 3) * STG;
        const int ko = c << 5;
        cp16(b0 + oA0,           apH + ko, 16u);
        cp16(b0 + ASZ + oA0,     apL + ko, 16u);
        if (nA == 2) {
            cp16(b0 + oA1,       apH + ko + 8, 16u);
            cp16(b0 + ASZ + oA1, apL + ko + 8, 16u);
        }
        cp16(b0 + 2*ASZ + oB0,   bp + ko,     16u);
        cp16(b0 + 2*ASZ + oB1,   bp + ko + 8, 16u);
    };
    auto MMA = [&](int s) {
        uint32_t base = sb + s * STG;
        const uint32_t arow = wm * (MT/2) + (lane & 15);
        const uint32_t koffA = (lane & 16) ? 8u : 0u;
        const uint32_t nrow = wn * 32 + (lane & 7) + ((lane & 16) ? 8 : 0);
        const uint32_t koffB = (lane & 8) ? 8u : 0u;
        #pragma unroll
        for (int ks = 0; ks < 2; ks++) {
            uint32_t ah[MTILES][4], al[MTILES][4], bh[4][2];
            #pragma unroll
            for (int mt = 0; mt < MTILES; mt++) {
                uint32_t off = aoff(arow + mt * 16, ks * 16 + koffA);
                ldmx4(ah[mt], base + off);
                ldmx4(al[mt], base + ASZ + off);
            }
            #pragma unroll
            for (int g = 0; g < 2; g++) {
                uint32_t off = aoff(nrow + g * 16, ks * 16 + koffB);
                uint32_t t[4];
                ldmx4(t, base + 2*ASZ + off);
                bh[2*g][0] = t[0]; bh[2*g][1] = t[1];
                bh[2*g+1][0] = t[2]; bh[2*g+1][1] = t[3];
            }
            #pragma unroll
            for (int mt = 0; mt < MTILES; mt++)
                #pragma unroll
                for (int nt = 0; nt < 4; nt++) {
                    mma16816h(acc[mt][nt], ah[mt], bh[nt]);
                    mma16816h(acc[mt][nt], al[mt], bh[nt]);
                }
        }
    };

    ISSUE(0); CP_COMMIT();
    if (NC > 1) { ISSUE(1); CP_COMMIT(); }

    for (int c = 0; c < NC; c++) {
        const int rem = NC - 1 - c;
        if (rem >= 1) CP_WAIT(1);
        else          CP_WAIT(0);
        __syncthreads();
        if (c + 2 < NC) { ISSUE(c + 2); CP_COMMIT(); }
        MMA(c % 3);
    }
    __syncthreads();

    // ---- epilogue: regs -> smem stage (MTx128, stride 132) -> gmem ----
    float* stage = (float*)smp;
    {
        const int r0 = wm * (MT/2) + (lane >> 2);
        const int c0 = wn * 32 + (lane & 3) * 2;
        #pragma unroll
        for (int mt = 0; mt < MTILES; mt++)
            #pragma unroll
            for (int nt = 0; nt < 4; nt++) {
                int r = r0 + mt * 16, cc = c0 + nt * 8;
                float2 p0; p0.x = acc[mt][nt][0]; p0.y = acc[mt][nt][1];
                float2 p1; p1.x = acc[mt][nt][2]; p1.y = acc[mt][nt][3];
                *(float2*)&stage[r * STAGE_LD + cc]       = p0;
                *(float2*)&stage[(r + 8) * STAGE_LD + cc] = p1;
            }
    }
    __syncthreads();

    #pragma unroll 4
    for (int j = 0; j < MT/8; j++) {
        int lin = j * 256 + tid;
        int rr = lin >> 5;
        int cg = (lin & 31) * 4;
        int n  = n0 + cg;
        float4 v = *(float4*)&stage[rr * STAGE_LD + cg];
        if (bias) {
            float4 bb = *(const float4*)(bias + n);
            v.x += bb.x; v.y += bb.y; v.z += bb.z; v.w += bb.w;
        }
        size_t base = (size_t)(m0 + rr) * N + n;
        if (EPI == 2) {
            float4 rr4 = *(const float4*)(res + base);
            v.x += rr4.x; v.y += rr4.y; v.z += rr4.z; v.w += rr4.w;
            *(float4*)(C + base) = v;
        } else {
            if (EPI == 1) {
                v.x = fmaxf(v.x, 0.f); v.y = fmaxf(v.y, 0.f);
                v.z = fmaxf(v.z, 0.f); v.w = fmaxf(v.w, 0.f);
            }
            __half h0 = __float2half_rn(v.x), h1 = __float2half_rn(v.y);
            __half h2 = __float2half_rn(v.z), h3 = __float2half_rn(v.w);
            uint2 hp; hp.x = pack_h2(h0, h1); hp.y = pack_h2(h2, h3);
            *(uint2*)(Ch + base) = hp;
            uint2 lp;
            lp.x = pack_h2(__float2half_rn(v.x - __half2float(h0)),
                           __float2half_rn(v.y - __half2float(h1)));
            lp.y = pack_h2(__float2half_rn(v.z - __half2float(h2)),
                           __float2half_rn(v.w - __half2float(h3)));
            *(uint2*)(Cl + base) = lp;
        }
    }
}

// ---------------- fp16 single-pass GEMM (head, 128x128) ----------------
__global__ void __launch_bounds__(256, 2)
gemm16(const __half* __restrict__ Ah, const __half* __restrict__ Bh,
       const float* __restrict__ bias, float* __restrict__ C,
       int N, int K) {
    extern __shared__ char smraw[];
    uint32_t raw = smem_u32(smraw);
    uint32_t sb  = (raw + 255u) & ~255u;
    char* smp    = smraw + (sb - raw);

    const int tid  = threadIdx.x;
    const int lane = tid & 31;
    const int wid  = tid >> 5;
    const int wm   = wid >> 2;
    const int wn   = wid & 3;
    const int m0   = blockIdx.x * 128;
    const int n0   = blockIdx.y * 128;

    const int r_ = tid >> 1;
    const int kh = (tid & 1) * 16;
    const __half* apH = Ah + (size_t)(m0 + r_) * K + kh;
    const int ng = n0 + r_;
    const bool nvB = (ng < N);
    const int ngc = nvB ? ng : (N - 1);
    const uint32_t bsz = nvB ? 16u : 0u;
    const __half* bpH = Bh + (size_t)ngc * K + kh;

    float acc[4][4][4];
    #pragma unroll
    for (int i = 0; i < 4; i++)
        #pragma unroll
        for (int j = 0; j < 4; j++)
            #pragma unroll
            for (int q = 0; q < 4; q++) acc[i][j][q] = 0.f;

    const int NC = K >> 5;
    const uint32_t o0 = aoff(r_, kh), o1 = aoff(r_, kh + 8);

    auto ISSUE = [&](int c) {
        uint32_t b0 = sb + (c % 3) * 16384;
        const int ko = c << 5;
        cp16(b0 + o0,        apH + ko,     16u);
        cp16(b0 + o1,        apH + ko + 8, 16u);
        cp16(b0 + 8192 + o0, bpH + ko,     bsz);
        cp16(b0 + 8192 + o1, bpH + ko + 8, bsz);
    };
    auto MMA = [&](int s) {
        uint32_t base = sb + s * 16384;
        const uint32_t arow = wm * 64 + (lane & 15);
        const uint32_t koffA = (lane & 16) ? 8u : 0u;
        const uint32_t nrow = wn * 32 + (lane & 7) + ((lane & 16) ? 8 : 0);
        const uint32_t koffB = (lane & 8) ? 8u : 0u;
        #pragma unroll
        for (int ks = 0; ks < 2; ks++) {
            uint32_t ah[4][4], bh[4][2];
            #pragma unroll
            for (int mt = 0; mt < 4; mt++) {
                uint32_t off = aoff(arow + mt * 16, ks * 16 + koffA);
                ldmx4(ah[mt], base + off);
            }
            #pragma unroll
            for (int g = 0; g < 2; g++) {
                uint32_t off = aoff(nrow + g * 16, ks * 16 + koffB);
                uint32_t t[4];
                ldmx4(t, base + 8192 + off);
                bh[2*g][0] = t[0]; bh[2*g][1] = t[1];
                bh[2*g+1][0] = t[2]; bh[2*g+1][1] = t[3];
            }
            #pragma unroll
            for (int mt = 0; mt < 4; mt++)
                #pragma unroll
                for (int nt = 0; nt < 4; nt++)
                    mma16816h(acc[mt][nt], ah[mt], bh[nt]);
        }
    };

    ISSUE(0); CP_COMMIT();
    if (NC > 1) { ISSUE(1); CP_COMMIT(); }

    for (int c = 0; c < NC; c++) {
        const int rem = NC - 1 - c;
        if (rem >= 1) CP_WAIT(1);
        else          CP_WAIT(0);
        __syncthreads();
        if (c + 2 < NC) { ISSUE(c + 2); CP_COMMIT(); }
        MMA(c % 3);
    }
    __syncthreads();

    float* stage = (float*)smp;
    {
        const int r0 = wm * 64 + (lane >> 2);
        const int c0 = wn * 32 + (lane & 3) * 2;
        #pragma unroll
        for (int mt = 0; mt < 4; mt++)
            #pragma unroll
            for (int nt = 0; nt < 4; nt++) {
                int r = r0 + mt * 16, cc = c0 + nt * 8;
                float2 p0; p0.x = acc[mt][nt][0]; p0.y = acc[mt][nt][1];
                float2 p1; p1.x = acc[mt][nt][2]; p1.y = acc[mt][nt][3];
                *(float2*)&stage[r * STAGE_LD + cc]       = p0;
                *(float2*)&stage[(r + 8) * STAGE_LD + cc] = p1;
            }
    }
    __syncthreads();

    #pragma unroll 4
    for (int j = 0; j < 16; j++) {
        int lin = j * 256 + tid;
        int rr = lin >> 5;
        int cg = (lin & 31) * 4;
        #pragma unroll
        for (int q = 0; q < 4; q++) {
            int n = n0 + cg + q;
            if (n < N) {
                float v = stage[rr * STAGE_LD + cg + q];
                if (bias) v += bias[n];
                C[(size_t)(m0 + rr) * N + n] = v;
            }
        }
    }
}

// ---------------- Embedding ----------------
__global__ void embed_kernel(const int* __restrict__ idx,
                             const float* __restrict__ tok,
                             const float* __restrict__ pos,
                             float* __restrict__ x) {
    int row = blockIdx.x;
    int t   = row & (T_ - 1);
    int token = idx[row];
    const float* tp = tok + (size_t)token * E_;
    const float* pp = pos + (size_t)t * E_;
    float* xp = x + (size_t)row * E_;
    for (int e = threadIdx.x; e < E_; e += blockDim.x)
        xp[e] = tp[e] + pp[e];
}

// ---------------- LayerNorm -> fp16 hi/lo ----------------
__global__ void ln_kernel(const float* __restrict__ x,
                          const float* __restrict__ g,
                          const float* __restrict__ b,
                          __half* __restrict__ yh,
                          __half* __restrict__ yl) {
    int row = blockIdx.x;
    int tid = threadIdx.x;
    const float* xr = x + (size_t)row * E_;
    float v0 = xr[tid], v1 = xr[tid + 256], v2 = xr[tid + 512];
    float s  = v0 + v1 + v2;
    float ss = v0*v0 + v1*v1 + v2*v2;
    #pragma unroll
    for (int off = 16; off > 0; off >>= 1) {
        s  += __shfl_down_sync(0xffffffffu, s,  off);
        ss += __shfl_down_sync(0xffffffffu, ss, off);
    }
    __shared__ float sh_s[8], sh_ss[8];
    int wid = tid >> 5, lane = tid & 31;
    if (lane == 0) { sh_s[wid] = s; sh_ss[wid] = ss; }
    __syncthreads();
    float tot = 0.f, tots = 0.f;
    #pragma unroll
    for (int i = 0; i < 8; i++) { tot += sh_s[i]; tots += sh_ss[i]; }
    float mean = tot * (1.0f / E_);
    float var  = tots * (1.0f / E_) - mean * mean;
    float rstd = rsqrtf(var + EPS);
    size_t rb = (size_t)row * E_;
    #pragma unroll
    for (int i = 0; i < 3; i++) {
        int c = tid + i * 256;
        float vv = (i == 0 ? v0 : (i == 1 ? v1 : v2));
        float y = (vv - mean) * rstd * g[c] + b[c];
        __half h = __float2half_rn(y);
        yh[rb + c] = h;
        yl[rb + c] = __float2half_rn(y - __half2float(h));
    }
}

// ---------------- Tensor-core flash attention (fused-QKV input, stride E3) ----------------
__global__ void __launch_bounds__(128, 2)
attn_mma(const __half* __restrict__ QKVh, const __half* __restrict__ QKVl,
         __half* __restrict__ Oh, __half* __restrict__ Ol) {
    extern __shared__ char smraw[];
    uint32_t raw = smem_u32(smraw);
    uint32_t sb  = (raw + 255u) & ~255u;
    char* smp    = smraw + (sb - raw);
    const uint32_t s_kh = sb, s_kl = sb + 8192, s_vh = sb + 16384, s_vl = sb + 24576;
    char *p_kh = smp, *p_kl = smp + 8192, *p_vh = smp + 16384, *p_vl = smp + 24576;

    const int qb = blockIdx.x, bhid = blockIdx.y;
    const int b = bhid / H_, h = bhid % H_;
    const int tid = threadIdx.x, lane = tid & 31, wq = tid >> 5;
    const float scale = rsqrtf((float)E_);

    const uint32_t koffA = (lane & 16) ? 8u : 0u;
    const uint32_t brow  = (lane & 7) + ((lane & 16) ? 8 : 0);
    const uint32_t koffB = (lane & 8) ? 8u : 0u;

    uint32_t aQh[4][4], aQl[4][4];
    {
        int r = tid >> 1, hf = (tid & 1) * 32;
        size_t qoff = (size_t)(b*T_ + qb*64 + r) * E3 + h*64 + hf;
        const uint4* qph = (const uint4*)(QKVh + qoff);
        const uint4* qpl = (const uint4*)(QKVl + qoff);
        #pragma unroll
        for (int j = 0; j < 4; j++) {
            *(uint4*)(p_kh + voff(r, hf + j*8)) = qph[j];
            *(uint4*)(p_kl + voff(r, hf + j*8)) = qpl[j];
        }
        __syncthreads();
        #pragma unroll
        for (int ks = 0; ks < 4; ks++) {
            ldmx4(aQh[ks], s_kh + voff(wq*16 + (lane & 15), ks*16 + koffA));
            ldmx4(aQl[ks], s_kl + voff(wq*16 + (lane & 15), ks*16 + koffA));
        }
        __syncthreads();
    }

    float m0 = -1e30f, m1 = -1e30f, l0 = 0.f, l1 = 0.f;
    float O[8][4];
    #pragma unroll
    for (int nt = 0; nt < 8; nt++)
        #pragma unroll
        for (int q = 0; q < 4; q++) O[nt][q] = 0.f;

    const int q0 = qb*64 + wq*16 + (lane >> 2);
    const int q1 = q0 + 8;

    for (int st0 = 0; st0 <= qb*64; st0 += 64) {
        {
            int s = tid >> 1, hf = (tid & 1) * 32;
            size_t koffg = (size_t)(b*T_ + st0 + s) * E3 + 768 + h*64 + hf;
            size_t voffg = (size_t)(b*T_ + st0 + s) * E3 + 1536 + h*64 + hf;
            const uint4* kph = (const uint4*)(QKVh + koffg);
            const uint4* kpl = (const uint4*)(QKVl + koffg);
            #pragma unroll
            for (int j = 0; j < 4; j++) {
                *(uint4*)(p_kh + voff(s, hf + j*8)) = kph[j];
                *(uint4*)(p_kl + voff(s, hf + j*8)) = kpl[j];
            }
            uint4 tvh[4], tvl[4];
            const uint4* vph = (const uint4*)(QKVh + voffg);
            const uint4* vpl = (const uint4*)(QKVl + voffg);
            #pragma unroll
            for (int j = 0; j < 4; j++) { tvh[j] = vph[j]; tvl[j] = vpl[j]; }
            const __half* hv = (const __half*)tvh;
            const __half* lv = (const __half*)tvl;
            #pragma unroll
            for (int j = 0; j < 32; j++) {
                *(__half*)(p_vh + voff(hf + j, s)) = hv[j];
                *(__half*)(p_vl + voff(hf + j, s)) = lv[j];
            }
        }
        __syncthreads();

        float S[8][4];
        #pragma unroll
        for (int nt = 0; nt < 8; nt++)
            #pragma unroll
            for (int q = 0; q < 4; q++) S[nt][q] = 0.f;
        #pragma unroll
        for (int ks = 0; ks < 4; ks++) {
            uint32_t bKh[8][2], bKl[8][2];
            #pragma unroll
            for (int g = 0; g < 4; g++) {
                uint32_t t[4];
                ldmx4(t, s_kh + voff(g*16 + brow, ks*16 + koffB));
                bKh[2*g][0] = t[0]; bKh[2*g][1] = t[1];
                bKh[2*g+1][0] = t[2]; bKh[2*g+1][1] = t[3];
                ldmx4(t, s_kl + voff(g*16 + brow, ks*16 + koffB));
                bKl[2*g][0] = t[0]; bKl[2*g][1] = t[1];
                bKl[2*g+1][0] = t[2]; bKl[2*g+1][1] = t[3];
            }
            #pragma unroll
            for (int nt = 0; nt < 8; nt++) {
                mma16816h(S[nt], aQh[ks], bKh[nt]);
                mma16816h(S[nt], aQl[ks], bKh[nt]);
                mma16816h(S[nt], aQh[ks], bKl[nt]);
            }
        }

        const bool diag = (st0 == qb*64);
        #pragma unroll
        for (int nt = 0; nt < 8; nt++) {
            S[nt][0] *= scale; S[nt][1] *= scale; S[nt][2] *= scale; S[nt][3] *= scale;
            if (diag) {
                int sg = st0 + nt*8 + (lane & 3)*2;
                if (sg     > q0) S[nt][0] = -1e30f;
                if (sg + 1 > q0) S[nt][1] = -1e30f;
                if (sg     > q1) S[nt][2] = -1e30f;
                if (sg + 1 > q1) S[nt][3] = -1e30f;
            }
        }

        float rx0 = -1e30f, rx1 = -1e30f;
        #pragma unroll
        for (int nt = 0; nt < 8; nt++) {
            rx0 = fmaxf(rx0, fmaxf(S[nt][0], S[nt][1]));
            rx1 = fmaxf(rx1, fmaxf(S[nt][2], S[nt][3]));
        }
        rx0 = fmaxf(rx0, __shfl_xor_sync(0xffffffffu, rx0, 1));
        rx0 = fmaxf(rx0, __shfl_xor_sync(0xffffffffu, rx0, 2));
        rx1 = fmaxf(rx1, __shfl_xor_sync(0xffffffffu, rx1, 1));
        rx1 = fmaxf(rx1, __shfl_xor_sync(0xffffffffu, rx1, 2));
        float mn0 = fmaxf(m0, rx0), mn1 = fmaxf(m1, rx1);
        float c0 = __expf(m0 - mn0), c1 = __expf(m1 - mn1);

        float rs0 = 0.f, rs1 = 0.f;
        uint32_t aPh[4][4], aPl[4][4];
        #pragma unroll
        for (int ks = 0; ks < 4; ks++) {
            #pragma unroll
            for (int hf = 0; hf < 2; hf++) {
                int nt = 2*ks + hf;
                float p0 = __expf(S[nt][0] - mn0);
                float p1 = __expf(S[nt][1] - mn0);
                float p2 = __expf(S[nt][2] - mn1);
                float p3 = __expf(S[nt][3] - mn1);
                rs0 += p0 + p1; rs1 += p2 + p3;
                __half h0 = __float2half_rn(p0), h1 = __float2half_rn(p1);
                __half h2 = __float2half_rn(p2), h3 = __float2half_rn(p3);
                aPh[ks][2*hf]     = pack_h2(h0, h1);
                aPh[ks][2*hf + 1] = pack_h2(h2, h3);
                aPl[ks][2*hf]     = pack_h2(__float2half_rn(p0 - __half2float(h0)),
                                            __float2half_rn(p1 - __half2float(h1)));
                aPl[ks][2*hf + 1] = pack_h2(__float2half_rn(p2 - __half2float(h2)),
                                            __float2half_rn(p3 - __half2float(h3)));
            }
        }
        rs0 += __shfl_xor_sync(0xffffffffu, rs0, 1);
        rs0 += __shfl_xor_sync(0xffffffffu, rs0, 2);
        rs1 += __shfl_xor_sync(0xffffffffu, rs1, 1);
        rs1 += __shfl_xor_sync(0xffffffffu, rs1, 2);
        l0 = l0 * c0 + rs0;
        l1 = l1 * c1 + rs1;

        #pragma unroll
        for (int nt = 0; nt < 8; nt++) {
            O[nt][0] *= c0; O[nt][1] *= c0; O[nt][2] *= c1; O[nt][3] *= c1;
        }

        #pragma unroll
        for (int ks = 0; ks < 4; ks++) {
            uint32_t bVh[8][2], bVl[8][2];
            #pragma unroll
            for (int g = 0; g < 4; g++) {
                uint32_t t[4];
                ldmx4(t, s_vh + voff(g*16 + brow, ks*16 + koffB));
                bVh[2*g][0] = t[0]; bVh[2*g][1] = t[1];
                bVh[2*g+1][0] = t[2]; bVh[2*g+1][1] = t[3];
                ldmx4(t, s_vl + voff(g*16 + brow, ks*16 + koffB));
                bVl[2*g][0] = t[0]; bVl[2*g][1] = t[1];
                bVl[2*g+1][0] = t[2]; bVl[2*g+1][1] = t[3];
            }
            #pragma unroll
            for (int nt = 0; nt < 8; nt++) {
                mma16816h(O[nt], aPh[ks], bVh[nt]);
                mma16816h(O[nt], aPl[ks], bVh[nt]);
                mma16816h(O[nt], aPh[ks], bVl[nt]);
            }
        }
        m0 = mn0; m1 = mn1;
        __syncthreads();
    }

    float i0 = 1.f / l0, i1 = 1.f / l1;
    size_t base0 = (size_t)(b*T_ + q0) * E_ + h*64 + (lane & 3)*2;
    size_t base1 = (size_t)(b*T_ + q1) * E_ + h*64 + (lane & 3)*2;
    #pragma unroll
    for (int nt = 0; nt < 8; nt++) {
        int d = nt * 8;
        float v0 = O[nt][0] * i0, v1 = O[nt][1] * i0;
        float v2 = O[nt][2] * i1, v3 = O[nt][3] * i1;
        __half h0 = __float2half_rn(v0), h1 = __float2half_rn(v1);
        __half h2 = __float2half_rn(v2), h3 = __float2half_rn(v3);
        *(uint32_t*)(Oh + base0 + d) = pack_h2(h0, h1);
        *(uint32_t*)(Oh + base1 + d) = pack_h2(h2, h3);
        *(uint32_t*)(Ol + base0 + d) = pack_h2(__float2half_rn(v0 - __half2float(h0)),
                                               __float2half_rn(v1 - __half2float(h1)));
        *(uint32_t*)(Ol + base1 + d) = pack_h2(__float2half_rn(v2 - __half2float(h2)),
                                               __float2half_rn(v3 - __half2float(h3)));
    }
}

// ---------------- Host launch ----------------
extern "C" void kernel_launch(void* const* d_in, const int* in_sizes, int n_in,
                              void* d_out, int out_size) {
    const int*   idx     = (const int*)  d_in[0];
    const float* tok_emb = (const float*)d_in[1];
    const float* pos_emb = (const float*)d_in[2];
    const float* Wq      = (const float*)d_in[3];
    const float* Wk      = (const float*)d_in[4];
    const float* Wv      = (const float*)d_in[5];
    const float* Wo      = (const float*)d_in[6];
    const float* bo      = (const float*)d_in[7];
    const float* ln1_g   = (const float*)d_in[8];
    const float* ln1_b   = (const float*)d_in[9];
    const float* ln2_g   = (const float*)d_in[10];
    const float* ln2_b   = (const float*)d_in[11];
    const float* W1      = (const float*)d_in[12];
    const float* b1      = (const float*)d_in[13];
    const float* W2      = (const float*)d_in[14];
    const float* b2      = (const float*)d_in[15];
    const float* lnf_g   = (const float*)d_in[16];
    const float* lnf_b   = (const float*)d_in[17];
    const float* Wh      = (const float*)d_in[18];
    const float* bh      = (const float*)d_in[19];
    float* out = (float*)d_out;

    float *x;
    __half *xnh, *xnl, *qkvh, *qkvl, *atth, *attl, *ffh, *ffl, *wh;
    cudaGetSymbolAddress((void**)&x,    g_x);
    cudaGetSymbolAddress((void**)&xnh,  g_xn_h);
    cudaGetSymbolAddress((void**)&xnl,  g_xn_l);
    cudaGetSymbolAddress((void**)&qkvh, g_qkv_h);
    cudaGetSymbolAddress((void**)&qkvl, g_qkv_l);
    cudaGetSymbolAddress((void**)&atth, g_att_h);
    cudaGetSymbolAddress((void**)&attl, g_att_l);
    cudaGetSymbolAddress((void**)&ffh,  g_ff_h);
    cudaGetSymbolAddress((void**)&ffl,  g_ff_l);
    cudaGetSymbolAddress((void**)&wh,   g_w_h);

    cudaFuncSetAttribute(gemm_h2<128,3>, cudaFuncAttributeMaxDynamicSharedMemorySize, GEMM_SMEM);
    cudaFuncSetAttribute(gemm_h2<128,1>, cudaFuncAttributeMaxDynamicSharedMemorySize, GEMM_SMEM);
    cudaFuncSetAttribute(gemm_h2<64,2>,  cudaFuncAttributeMaxDynamicSharedMemorySize, GEMM64_SMEM);
    cudaFuncSetAttribute(gemm16,         cudaFuncAttributeMaxDynamicSharedMemorySize, GEMM16_SMEM);
    cudaFuncSetAttribute(attn_mma,       cudaFuncAttributeMaxDynamicSharedMemorySize, ATT_SMEM);

    dim3 gQKVsplit(24, 24, 18);
    dim3 gWoAll(24, 24, 6);
    dim3 gW1All(24, 96, 6);
    dim3 gW2All(96, 24, 6);
    dim3 gHd(24, (V_+31)/32);
    dim3 gQKV(32, 18);       // fused: N=2304, 128x128
    dim3 gWo(64, 6);         // MT=64
    dim3 gFF(32, 24);        // N=3072, 128x128
    dim3 gW2(64, 6);         // MT=64, K=3072
    dim3 gV(32, 393);
    dim3 gAttn(T_ / 64, B_ * H_);

    // launch order: QKV GEMM of layer 0 at index 4 (ncu window)
    embed_kernel<<<BT, 256>>>(idx, tok_emb, pos_emb, x);                              // 0
    ln_kernel<<<BT, 256>>>(x, ln1_g, ln1_b, xnh, xnl);                                // 1
    wsplit_qkv_all<<<gQKVsplit, 256>>>(Wq, Wk, Wv, wh);                               // 2
    wsplit_all0<<<gWoAll, 256>>>(Wo, (long)E_*E_, wh + WO_OFF, (long)LAYER_SZ, E_, E_); // 3

    for (int l = 0; l < L_; l++) {
        size_t lo = (size_t)l * LAYER_SZ;

        if (l > 0)
            ln_kernel<<<BT, 256>>>(x, ln1_g + (size_t)l * E_, ln1_b + (size_t)l * E_, xnh, xnl);

        // fused QKV: weights [2304][768] contiguous at lo
        gemm_h2<128,3><<<gQKV, 256, GEMM_SMEM>>>(xnh, xnl, wh + lo,                  // 4 for l=0
                                                 nullptr, nullptr, nullptr,
                                                 qkvh, qkvl, E3, E_);

        attn_mma<<<gAttn, 128, ATT_SMEM>>>(qkvh, qkvl, atth, attl);

        gemm_h2<64,2><<<gWo, 256, GEMM64_SMEM>>>(atth, attl, wh + lo + WO_OFF,
                                                 bo + (size_t)l * E_, x, x,
                                                 nullptr, nullptr, E_, E_);

        ln_kernel<<<BT, 256>>>(x, ln2_g + (size_t)l * E_, ln2_b + (size_t)l * E_, xnh, xnl);

        if (l == 0)
            wsplit_all0<<<gW1All, 256>>>(W1, (long)E_*FF, wh + W1_OFF, (long)LAYER_SZ, E_, FF);
        gemm_h2<128,1><<<gFF, 256, GEMM_SMEM>>>(xnh, xnl, wh + lo + W1_OFF,
                                                b1 + (size_t)l * FF, nullptr, nullptr,
                                                ffh, ffl, FF, E_);

        if (l == 0)
            wsplit_all0<<<gW2All, 256>>>(W2, (long)FF*E_, wh + W2_OFF, (long)LAYER_SZ, FF, E_);
        gemm_h2<64,2><<<gW2, 256, GEMM64_SMEM>>>(ffh, ffl, wh + lo + W2_OFF,
                                                 b2 + (size_t)l * E_, x, x,
                                                 nullptr, nullptr, E_, FF);
    }

    // fp16 single-pass head (final LN reuses ln_kernel; head uses hi only)
    ln_kernel<<<BT, 256>>>(x, lnf_g, lnf_b, xnh, xnl);
    wsplit16_kernel<<<gHd, 256>>>(Wh, wh + HEAD_OFF, E_, V_);
    gemm16<<<gV, 256, GEMM16_SMEM>>>(xnh, wh + HEAD_OFF, bh, out, V_, E_);

    (void)in_sizes; (void)n_in; (void)out_size;
}